// round 1
// baseline (speedup 1.0000x reference)
#include <cuda_runtime.h>
#include <cstdint>

// Problem constants
#define MTOT   16384      // B*K = 256*64 rows
#define DMODEL 1024
#define NHEAD  16
#define DHEAD  64
#define BATCH  256
#define SEQLEN 64
#define ATT_SCALE 0.125f  // 64^-0.5
#define LN_EPS 1e-5f

// Scratch (static device globals are the allowed workaround for no-alloc rule)
__device__ float g_Q [MTOT * DMODEL];
__device__ float g_K [MTOT * DMODEL];
__device__ float g_V [MTOT * DMODEL];
__device__ float g_AO[MTOT * DMODEL];
__device__ float g_O [MTOT * DMODEL];

// ---------------------------------------------------------------------------
// Packed f32x2 helpers (sm_103a packed fp32 pipe; 2x FFMA throughput)
// ---------------------------------------------------------------------------
__device__ __forceinline__ unsigned long long f32x2_pack(float lo, float hi) {
    unsigned long long r;
    asm("mov.b64 %0, {%1, %2};" : "=l"(r)
        : "r"(__float_as_uint(lo)), "r"(__float_as_uint(hi)));
    return r;
}
__device__ __forceinline__ unsigned long long f32x2_dup(float v) {
    unsigned long long r;
    unsigned u = __float_as_uint(v);
    asm("mov.b64 %0, {%1, %1};" : "=l"(r) : "r"(u));
    return r;
}
#define FMA2(d, a, b) \
    asm("fma.rn.f32x2 %0, %1, %2, %0;" : "+l"(d) : "l"(a), "l"(b))

// ---------------------------------------------------------------------------
// SGEMM (NT): C[m,n] = sum_k A[m*1024+k] * B[n*1024+k]
// M=16384, N=1024, K=1024. Block tile 128x128x16, 256 threads, 8x8/thread,
// f32x2 packed accumulators (acc holds col pairs).
// ---------------------------------------------------------------------------
#define BM 128
#define BN 128
#define BK 16
#define KTILES (DMODEL / BK)

__global__ __launch_bounds__(256) void sgemm_nt(const float* __restrict__ A,
                                                const float* __restrict__ B,
                                                float* __restrict__ C) {
    __shared__ float As[BK][BM];
    __shared__ float Bs[BK][BN];

    const int tid = threadIdx.x;
    const int m0 = blockIdx.y * BM;
    const int n0 = blockIdx.x * BN;

    // Loader mapping: each thread loads 2 float4 per operand per k-tile
    const int lr  = tid >> 2;          // 0..63, second row = lr+64
    const int lk4 = (tid & 3) * 4;     // k sub-offset 0/4/8/12

    const float* Ap0 = A + (size_t)(m0 + lr) * DMODEL + lk4;
    const float* Bp0 = B + (size_t)(n0 + lr) * DMODEL + lk4;

    const int ty = tid >> 4;           // 0..15 -> row group
    const int tx = tid & 15;           // 0..15 -> col group

    unsigned long long acc[8][4];
#pragma unroll
    for (int i = 0; i < 8; i++)
#pragma unroll
        for (int j = 0; j < 4; j++) acc[i][j] = 0ULL;

    float4 ra0 = *(const float4*)(Ap0);
    float4 ra1 = *(const float4*)(Ap0 + 64 * DMODEL);
    float4 rb0 = *(const float4*)(Bp0);
    float4 rb1 = *(const float4*)(Bp0 + 64 * DMODEL);

    for (int kt = 0; kt < KTILES; kt++) {
        // regs -> smem (transposed)
#pragma unroll
        for (int j = 0; j < 4; j++) {
            As[lk4 + j][lr]      = ((const float*)&ra0)[j];
            As[lk4 + j][lr + 64] = ((const float*)&ra1)[j];
            Bs[lk4 + j][lr]      = ((const float*)&rb0)[j];
            Bs[lk4 + j][lr + 64] = ((const float*)&rb1)[j];
        }
        __syncthreads();

        if (kt + 1 < KTILES) {
            const float* Ap = Ap0 + (kt + 1) * BK;
            const float* Bp = Bp0 + (kt + 1) * BK;
            ra0 = *(const float4*)(Ap);
            ra1 = *(const float4*)(Ap + 64 * DMODEL);
            rb0 = *(const float4*)(Bp);
            rb1 = *(const float4*)(Bp + 64 * DMODEL);
        }

#pragma unroll
        for (int kk = 0; kk < BK; kk++) {
            const float4 a0 = *(const float4*)&As[kk][ty * 8];
            const float4 a1 = *(const float4*)&As[kk][ty * 8 + 4];
            const float4 b0 = *(const float4*)&Bs[kk][tx * 8];
            const float4 b1 = *(const float4*)&Bs[kk][tx * 8 + 4];

            unsigned long long B2[4];
            B2[0] = f32x2_pack(b0.x, b0.y);
            B2[1] = f32x2_pack(b0.z, b0.w);
            B2[2] = f32x2_pack(b1.x, b1.y);
            B2[3] = f32x2_pack(b1.z, b1.w);

            const float av[8] = {a0.x, a0.y, a0.z, a0.w, a1.x, a1.y, a1.z, a1.w};
#pragma unroll
            for (int i = 0; i < 8; i++) {
                unsigned long long a2 = f32x2_dup(av[i]);
#pragma unroll
                for (int j = 0; j < 4; j++) FMA2(acc[i][j], a2, B2[j]);
            }
        }
        __syncthreads();
    }

    // Epilogue: store packed pairs (8B aligned)
#pragma unroll
    for (int i = 0; i < 8; i++) {
        float* crow = C + (size_t)(m0 + ty * 8 + i) * DMODEL + n0 + tx * 8;
#pragma unroll
        for (int j = 0; j < 4; j++) {
            *(unsigned long long*)(crow + 2 * j) = acc[i][j];
        }
    }
}

// ---------------------------------------------------------------------------
// Attention: one CTA per (b,h). 64x64x64 QK^T -> softmax -> PV.
// Row masking is intentionally omitted (redundant with the residual gate).
// ---------------------------------------------------------------------------
__global__ __launch_bounds__(256) void attn_kernel(const float* __restrict__ Q,
                                                   const float* __restrict__ Kin,
                                                   const float* __restrict__ V,
                                                   float* __restrict__ AO) {
    const int h = blockIdx.x;
    const int b = blockIdx.y;
    const int t = threadIdx.x;

    __shared__ float bufA[64 * 65];   // Q tile, reused as P
    __shared__ float bufB[64 * 65];   // K tile, reused as V

    const size_t base = (size_t)b * SEQLEN * DMODEL + h * DHEAD;
    const float* Qb = Q   + base;
    const float* Kb = Kin + base;
    const float* Vb = V   + base;

    for (int e = t; e < 4096; e += 256) {
        const int r = e >> 6, d = e & 63;
        bufA[r * 65 + d] = Qb[(size_t)r * DMODEL + d];
        bufB[r * 65 + d] = Kb[(size_t)r * DMODEL + d];
    }
    __syncthreads();

    const int ty = t >> 4;   // q group: rows ty*4..+3
    const int tx = t & 15;   // k group: cols tx*4..+3

    float s[4][4];
#pragma unroll
    for (int i = 0; i < 4; i++)
#pragma unroll
        for (int j = 0; j < 4; j++) s[i][j] = 0.0f;

#pragma unroll 8
    for (int d = 0; d < 64; d++) {
        float a[4], bb[4];
#pragma unroll
        for (int i = 0; i < 4; i++) a[i]  = bufA[(ty * 4 + i) * 65 + d];
#pragma unroll
        for (int j = 0; j < 4; j++) bb[j] = bufB[(tx * 4 + j) * 65 + d];
#pragma unroll
        for (int i = 0; i < 4; i++)
#pragma unroll
            for (int j = 0; j < 4; j++) s[i][j] = fmaf(a[i], bb[j], s[i][j]);
    }
    __syncthreads();   // Q/K reads done; safe to overwrite

    // P (scaled scores) -> bufA ; V tile -> bufB
#pragma unroll
    for (int i = 0; i < 4; i++)
#pragma unroll
        for (int j = 0; j < 4; j++)
            bufA[(ty * 4 + i) * 65 + tx * 4 + j] = s[i][j] * ATT_SCALE;

    for (int e = t; e < 4096; e += 256) {
        const int r = e >> 6, d = e & 63;
        bufB[r * 65 + d] = Vb[(size_t)r * DMODEL + d];
    }
    __syncthreads();

    // Softmax: warp w handles rows w*8 .. w*8+7, 2 elems/lane
    const int warp = t >> 5, lane = t & 31;
    for (int rq = warp * 8; rq < warp * 8 + 8; rq++) {
        float x0 = bufA[rq * 65 + lane];
        float x1 = bufA[rq * 65 + 32 + lane];
        float mx = fmaxf(x0, x1);
#pragma unroll
        for (int d2 = 16; d2; d2 >>= 1)
            mx = fmaxf(mx, __shfl_xor_sync(0xFFFFFFFFu, mx, d2));
        float e0 = __expf(x0 - mx);
        float e1 = __expf(x1 - mx);
        float sm = e0 + e1;
#pragma unroll
        for (int d2 = 16; d2; d2 >>= 1)
            sm += __shfl_xor_sync(0xFFFFFFFFu, sm, d2);
        const float inv = 1.0f / sm;
        bufA[rq * 65 + lane]      = e0 * inv;
        bufA[rq * 65 + 32 + lane] = e1 * inv;
    }
    __syncthreads();

    // O = P @ V
    float o[4][4];
#pragma unroll
    for (int i = 0; i < 4; i++)
#pragma unroll
        for (int j = 0; j < 4; j++) o[i][j] = 0.0f;

#pragma unroll 8
    for (int k = 0; k < 64; k++) {
        float a[4], bb[4];
#pragma unroll
        for (int i = 0; i < 4; i++) a[i]  = bufA[(ty * 4 + i) * 65 + k];
#pragma unroll
        for (int j = 0; j < 4; j++) bb[j] = bufB[k * 65 + tx * 4 + j];
#pragma unroll
        for (int i = 0; i < 4; i++)
#pragma unroll
            for (int j = 0; j < 4; j++) o[i][j] = fmaf(a[i], bb[j], o[i][j]);
    }

    float* AOb = AO + base;
#pragma unroll
    for (int i = 0; i < 4; i++)
#pragma unroll
        for (int j = 0; j < 4; j++)
            AOb[(size_t)(ty * 4 + i) * DMODEL + tx * 4 + j] = o[i][j];
}

// ---------------------------------------------------------------------------
// Gated residual + LayerNorm: one CTA per row (1024 elems, 256 threads x4)
// active_mask read as 4-byte word, nonzero == active (works for int32 {0,1}
// and float32 {0.0,1.0} encodings)
// ---------------------------------------------------------------------------
__global__ __launch_bounds__(256) void resid_ln(const float* __restrict__ hidden,
                                                const float* __restrict__ proj,
                                                const unsigned* __restrict__ mask,
                                                const float* __restrict__ gamma,
                                                const float* __restrict__ beta,
                                                float* __restrict__ out) {
    const int r = blockIdx.x;
    const int t = threadIdx.x;
    const size_t base = (size_t)r * DMODEL + t * 4;

    const float act = (mask[r] != 0u) ? 1.0f : 0.0f;
    const float4 hv = *(const float4*)(hidden + base);
    const float4 ov = *(const float4*)(proj + base);

    float4 f;
    f.x = hv.x + act * ov.x;
    f.y = hv.y + act * ov.y;
    f.z = hv.z + act * ov.z;
    f.w = hv.w + act * ov.w;

    float s  = f.x + f.y + f.z + f.w;
    float s2 = f.x * f.x + f.y * f.y + f.z * f.z + f.w * f.w;

#pragma unroll
    for (int d = 16; d; d >>= 1) {
        s  += __shfl_xor_sync(0xFFFFFFFFu, s,  d);
        s2 += __shfl_xor_sync(0xFFFFFFFFu, s2, d);
    }

    __shared__ float ws[8], ws2[8];
    const int warp = t >> 5, lane = t & 31;
    if (lane == 0) { ws[warp] = s; ws2[warp] = s2; }
    __syncthreads();

    float ts = 0.0f, ts2 = 0.0f;
#pragma unroll
    for (int i = 0; i < 8; i++) { ts += ws[i]; ts2 += ws2[i]; }

    const float mu  = ts * (1.0f / DMODEL);
    const float var = ts2 * (1.0f / DMODEL) - mu * mu;
    const float rs  = rsqrtf(var + LN_EPS);

    const float4 gv = *(const float4*)(gamma + t * 4);
    const float4 bv = *(const float4*)(beta  + t * 4);

    float4 r4;
    r4.x = (f.x - mu) * rs * gv.x + bv.x;
    r4.y = (f.y - mu) * rs * gv.y + bv.y;
    r4.z = (f.z - mu) * rs * gv.z + bv.z;
    r4.w = (f.w - mu) * rs * gv.w + bv.w;
    *(float4*)(out + base) = r4;
}

// ---------------------------------------------------------------------------
// Launch: metadata order is hidden, active_mask, W_q, W_k, W_v, W_o, gamma, beta
// ---------------------------------------------------------------------------
extern "C" void kernel_launch(void* const* d_in, const int* in_sizes, int n_in,
                              void* d_out, int out_size) {
    const float*    hidden = (const float*)d_in[0];
    const unsigned* mask   = (const unsigned*)d_in[1];
    const float*    Wq     = (const float*)d_in[2];
    const float*    Wk     = (const float*)d_in[3];
    const float*    Wv     = (const float*)d_in[4];
    const float*    Wo     = (const float*)d_in[5];
    const float*    gamma  = (const float*)d_in[6];
    const float*    beta   = (const float*)d_in[7];
    float*          out    = (float*)d_out;

    float *Qs, *Ks, *Vs, *AOs, *Os;
    cudaGetSymbolAddress((void**)&Qs,  g_Q);
    cudaGetSymbolAddress((void**)&Ks,  g_K);
    cudaGetSymbolAddress((void**)&Vs,  g_V);
    cudaGetSymbolAddress((void**)&AOs, g_AO);
    cudaGetSymbolAddress((void**)&Os,  g_O);

    const dim3 gg(DMODEL / BN, MTOT / BM);   // (8, 128)
    sgemm_nt<<<gg, 256>>>(hidden, Wq, Qs);
    sgemm_nt<<<gg, 256>>>(hidden, Wk, Ks);
    sgemm_nt<<<gg, 256>>>(hidden, Wv, Vs);

    attn_kernel<<<dim3(NHEAD, BATCH), 256>>>(Qs, Ks, Vs, AOs);

    sgemm_nt<<<gg, 256>>>(AOs, Wo, Os);

    resid_ln<<<MTOT, 256>>>(hidden, Os, mask, gamma, beta, out);
}

// round 4
// speedup vs baseline: 2.1415x; 2.1415x over previous
#include <cuda_runtime.h>
#include <cuda_bf16.h>
#include <cstdint>

// ---------------------------------------------------------------------------
// Problem constants
// ---------------------------------------------------------------------------
#define MTOT   16384      // B*K
#define DMODEL 1024
#define NHEAD  16
#define DHEAD  64
#define BATCH  256
#define SEQLEN 64
#define ATT_SCALE 0.125f
#define LN_EPS 1e-5f

// ---------------------------------------------------------------------------
// Scratch (device globals: the allowed no-alloc workaround)
// ---------------------------------------------------------------------------
__device__ float g_Q [MTOT * DMODEL];
__device__ float g_K [MTOT * DMODEL];
__device__ float g_V [MTOT * DMODEL];
__device__ float g_O [MTOT * DMODEL];
__device__ __nv_bfloat16 g_hh [MTOT * DMODEL];
__device__ __nv_bfloat16 g_hl [MTOT * DMODEL];
__device__ __nv_bfloat16 g_aoh[MTOT * DMODEL];
__device__ __nv_bfloat16 g_aol[MTOT * DMODEL];
__device__ __nv_bfloat16 g_wh [4][DMODEL * DMODEL];
__device__ __nv_bfloat16 g_wl [4][DMODEL * DMODEL];

// ---------------------------------------------------------------------------
// Baseline-PTX helpers (NO sm_103a-only features: harness targets compute_103)
// ---------------------------------------------------------------------------
__device__ __forceinline__ uint32_t smem_u32(const void* p) {
    uint32_t a;
    asm("{ .reg .u64 t; cvta.to.shared.u64 t, %1; cvt.u32.u64 %0, t; }"
        : "=r"(a) : "l"(p));
    return a;
}

#define CP_ASYNC16(dst, src) \
    asm volatile("cp.async.cg.shared.global [%0], [%1], 16;" :: "r"(dst), "l"(src))
#define CP_COMMIT() asm volatile("cp.async.commit_group;" ::: "memory")
#define CP_WAIT(n)  asm volatile("cp.async.wait_group %0;" :: "n"(n) : "memory")

#define LDSM4(r0, r1, r2, r3, addr) \
    asm volatile("ldmatrix.sync.aligned.m8n8.x4.shared.b16 {%0,%1,%2,%3}, [%4];" \
                 : "=r"(r0), "=r"(r1), "=r"(r2), "=r"(r3) : "r"(addr))

#define MMA_BF16(d, a, b) \
    asm volatile("mma.sync.aligned.m16n8k16.row.col.f32.bf16.bf16.f32 " \
                 "{%0,%1,%2,%3},{%4,%5,%6,%7},{%8,%9},{%0,%1,%2,%3};" \
                 : "+f"((d)[0]), "+f"((d)[1]), "+f"((d)[2]), "+f"((d)[3]) \
                 : "r"((a)[0]), "r"((a)[1]), "r"((a)[2]), "r"((a)[3]), \
                   "r"((b)[0]), "r"((b)[1]))

__device__ __forceinline__ uint32_t bf2u(__nv_bfloat16 a, __nv_bfloat16 b) {
    __nv_bfloat162 t; t.x = a; t.y = b;
    return *reinterpret_cast<uint32_t*>(&t);
}

// ---------------------------------------------------------------------------
// fp32 -> bf16 hi/lo conversion
// ---------------------------------------------------------------------------
__global__ __launch_bounds__(256) void cvt_hilo(const float4* __restrict__ in,
                                                uint2* __restrict__ hi,
                                                uint2* __restrict__ lo, int n4) {
    int i = blockIdx.x * 256 + threadIdx.x;
    if (i >= n4) return;
    float4 v = in[i];
    __nv_bfloat16 h0 = __float2bfloat16(v.x);
    __nv_bfloat16 h1 = __float2bfloat16(v.y);
    __nv_bfloat16 h2 = __float2bfloat16(v.z);
    __nv_bfloat16 h3 = __float2bfloat16(v.w);
    __nv_bfloat16 l0 = __float2bfloat16(v.x - __bfloat162float(h0));
    __nv_bfloat16 l1 = __float2bfloat16(v.y - __bfloat162float(h1));
    __nv_bfloat16 l2 = __float2bfloat16(v.z - __bfloat162float(h2));
    __nv_bfloat16 l3 = __float2bfloat16(v.w - __bfloat162float(h3));
    hi[i] = make_uint2(bf2u(h0, h1), bf2u(h2, h3));
    lo[i] = make_uint2(bf2u(l0, l1), bf2u(l2, l3));
}

// ---------------------------------------------------------------------------
// mma.sync split-bf16 GEMM (NT): C[m,n] = sum_k A[m,k] * B[n,k]  (~fp32)
//   C += Ah*Bh + Ah*Bl + Al*Bh
// BM=128, BN=128, BK=32, cp.async double buffer, XOR-swizzled smem,
// 8 warps = 2(M) x 4(N), warp tile 64x32.
// ---------------------------------------------------------------------------
#define BM 128
#define BN 128
#define BKC 32
#define NC (DMODEL / BKC)      // 32 k-chunks
#define MAT_BYTES (128 * 64)   // 128 rows * 32 bf16 = 8192 B per matrix
#define OFF_AH 0
#define OFF_AL (1 * MAT_BYTES)
#define OFF_BH (2 * MAT_BYTES)
#define OFF_BL (3 * MAT_BYTES)
#define STAGE_BYTES (4 * MAT_BYTES)        // 32768
#define GEMM_SMEM (2 * STAGE_BYTES)        // 65536

__global__ __launch_bounds__(256, 1) void gemm_mma(
    const __nv_bfloat16* __restrict__ Ah, const __nv_bfloat16* __restrict__ Al,
    const __nv_bfloat16* __restrict__ Bh, const __nv_bfloat16* __restrict__ Bl,
    float* __restrict__ C)
{
    extern __shared__ char smem[];
    const uint32_t sb = smem_u32(smem);

    const int tid  = threadIdx.x;
    const int wid  = tid >> 5;
    const int lane = tid & 31;
    const int wm   = wid & 1;        // 0..1  -> M offset wm*64
    const int wn   = wid >> 1;       // 0..3  -> N offset wn*32
    const int m0   = blockIdx.y * BM;
    const int n0   = blockIdx.x * BN;

    // per-thread load mapping: 2 chunks per matrix per stage
    // chunk idx = tid + i*256 over 512 chunks: row = idx>>2 (0..127), c = idx&3
    const __nv_bfloat16* gA[2] = {Ah, Al};
    const __nv_bfloat16* gB[2] = {Bh, Bl};

    auto load_stage = [&](int kt, int stg) {
        const uint32_t base = sb + stg * STAGE_BYTES;
#pragma unroll
        for (int i = 0; i < 2; i++) {
            const int idx = tid + i * 256;
            const int r = idx >> 2, c = idx & 3;
            const uint32_t sw = (uint32_t)((c ^ (r & 3)) << 4) + r * 64;
            const size_t goffA = (size_t)(m0 + r) * DMODEL + kt * BKC + c * 8;
            const size_t goffB = (size_t)(n0 + r) * DMODEL + kt * BKC + c * 8;
            CP_ASYNC16(base + OFF_AH + sw, gA[0] + goffA);
            CP_ASYNC16(base + OFF_AL + sw, gA[1] + goffA);
            CP_ASYNC16(base + OFF_BH + sw, gB[0] + goffB);
            CP_ASYNC16(base + OFF_BL + sw, gB[1] + goffB);
        }
        CP_COMMIT();
    };

    float acc[4][4][4];
#pragma unroll
    for (int mi = 0; mi < 4; mi++)
#pragma unroll
        for (int ni = 0; ni < 4; ni++)
#pragma unroll
            for (int q = 0; q < 4; q++) acc[mi][ni][q] = 0.0f;

    // Precompute per-lane ldmatrix address offsets (within a matrix, per kk)
    // A tile mi: rows wm*64 + mi*16 + (lane&15), chunk half = lane>>4
    const int a_row_in16 = lane & 15;
    const int a_half     = lane >> 4;          // 0,1 -> k lo/hi
    // B pair p: rows wn*32 + p*16 + (lane&7) + ((lane>>4)<<3), half = (lane>>3)&1
    const int b_row_in16 = (lane & 7) + ((lane >> 4) << 3);
    const int b_half     = (lane >> 3) & 1;

    load_stage(0, 0);

    for (int kt = 0; kt < NC; kt++) {
        const int cur = kt & 1;
        if (kt + 1 < NC) {
            load_stage(kt + 1, cur ^ 1);
            CP_WAIT(1);
        } else {
            CP_WAIT(0);
        }
        __syncthreads();

        const uint32_t base = sb + cur * STAGE_BYTES;

#pragma unroll
        for (int kk = 0; kk < 2; kk++) {
            uint32_t ah[4][4], al[4][4], bh[4][2], bl[4][2];

#pragma unroll
            for (int mi = 0; mi < 4; mi++) {
                const int row = wm * 64 + mi * 16 + a_row_in16;
                const int ch  = kk * 2 + a_half;
                const uint32_t addr = row * 64 + (uint32_t)((ch ^ (row & 3)) << 4);
                LDSM4(ah[mi][0], ah[mi][1], ah[mi][2], ah[mi][3], base + OFF_AH + addr);
                LDSM4(al[mi][0], al[mi][1], al[mi][2], al[mi][3], base + OFF_AL + addr);
            }
#pragma unroll
            for (int p = 0; p < 2; p++) {
                const int row = wn * 32 + p * 16 + b_row_in16;
                const int ch  = kk * 2 + b_half;
                const uint32_t addr = row * 64 + (uint32_t)((ch ^ (row & 3)) << 4);
                LDSM4(bh[2 * p][0], bh[2 * p][1], bh[2 * p + 1][0], bh[2 * p + 1][1],
                      base + OFF_BH + addr);
                LDSM4(bl[2 * p][0], bl[2 * p][1], bl[2 * p + 1][0], bl[2 * p + 1][1],
                      base + OFF_BL + addr);
            }

#pragma unroll
            for (int mi = 0; mi < 4; mi++)
#pragma unroll
                for (int ni = 0; ni < 4; ni++) {
                    MMA_BF16(acc[mi][ni], ah[mi], bh[ni]);
                    MMA_BF16(acc[mi][ni], ah[mi], bl[ni]);
                    MMA_BF16(acc[mi][ni], al[mi], bh[ni]);
                }
        }
        __syncthreads();
    }

    // Epilogue
    const int g  = lane >> 2;
    const int cc = (lane & 3) * 2;
#pragma unroll
    for (int mi = 0; mi < 4; mi++) {
        const int row = m0 + wm * 64 + mi * 16 + g;
#pragma unroll
        for (int ni = 0; ni < 4; ni++) {
            float* p = C + (size_t)row * DMODEL + n0 + wn * 32 + ni * 8 + cc;
            *(float2*)p = make_float2(acc[mi][ni][0], acc[mi][ni][1]);
            *(float2*)(p + 8 * DMODEL) = make_float2(acc[mi][ni][2], acc[mi][ni][3]);
        }
    }
}

// ---------------------------------------------------------------------------
// Attention: one CTA per (b,h). 64x64x64 QK^T -> softmax -> PV.
// Emits bf16 hi/lo (feeds O-projection GEMM). Row masking omitted
// (redundant with the residual gate).
// ---------------------------------------------------------------------------
__global__ __launch_bounds__(256) void attn_kernel(const float* __restrict__ Q,
                                                   const float* __restrict__ Kin,
                                                   const float* __restrict__ V,
                                                   __nv_bfloat16* __restrict__ AOh,
                                                   __nv_bfloat16* __restrict__ AOl) {
    const int h = blockIdx.x;
    const int b = blockIdx.y;
    const int t = threadIdx.x;

    __shared__ float bufA[64 * 65];
    __shared__ float bufB[64 * 65];

    const size_t base = (size_t)b * SEQLEN * DMODEL + h * DHEAD;
    const float* Qb = Q   + base;
    const float* Kb = Kin + base;
    const float* Vb = V   + base;

    for (int e = t; e < 4096; e += 256) {
        const int r = e >> 6, d = e & 63;
        bufA[r * 65 + d] = Qb[(size_t)r * DMODEL + d];
        bufB[r * 65 + d] = Kb[(size_t)r * DMODEL + d];
    }
    __syncthreads();

    const int ty = t >> 4;
    const int tx = t & 15;

    float s[4][4];
#pragma unroll
    for (int i = 0; i < 4; i++)
#pragma unroll
        for (int j = 0; j < 4; j++) s[i][j] = 0.0f;

#pragma unroll 8
    for (int d = 0; d < 64; d++) {
        float a[4], bb[4];
#pragma unroll
        for (int i = 0; i < 4; i++) a[i]  = bufA[(ty * 4 + i) * 65 + d];
#pragma unroll
        for (int j = 0; j < 4; j++) bb[j] = bufB[(tx * 4 + j) * 65 + d];
#pragma unroll
        for (int i = 0; i < 4; i++)
#pragma unroll
            for (int j = 0; j < 4; j++) s[i][j] = fmaf(a[i], bb[j], s[i][j]);
    }
    __syncthreads();

#pragma unroll
    for (int i = 0; i < 4; i++)
#pragma unroll
        for (int j = 0; j < 4; j++)
            bufA[(ty * 4 + i) * 65 + tx * 4 + j] = s[i][j] * ATT_SCALE;

    for (int e = t; e < 4096; e += 256) {
        const int r = e >> 6, d = e & 63;
        bufB[r * 65 + d] = Vb[(size_t)r * DMODEL + d];
    }
    __syncthreads();

    const int warp = t >> 5, lane = t & 31;
    for (int rq = warp * 8; rq < warp * 8 + 8; rq++) {
        float x0 = bufA[rq * 65 + lane];
        float x1 = bufA[rq * 65 + 32 + lane];
        float mx = fmaxf(x0, x1);
#pragma unroll
        for (int d2 = 16; d2; d2 >>= 1)
            mx = fmaxf(mx, __shfl_xor_sync(0xFFFFFFFFu, mx, d2));
        float e0 = __expf(x0 - mx);
        float e1 = __expf(x1 - mx);
        float sm = e0 + e1;
#pragma unroll
        for (int d2 = 16; d2; d2 >>= 1)
            sm += __shfl_xor_sync(0xFFFFFFFFu, sm, d2);
        const float inv = 1.0f / sm;
        bufA[rq * 65 + lane]      = e0 * inv;
        bufA[rq * 65 + 32 + lane] = e1 * inv;
    }
    __syncthreads();

    float o[4][4];
#pragma unroll
    for (int i = 0; i < 4; i++)
#pragma unroll
        for (int j = 0; j < 4; j++) o[i][j] = 0.0f;

#pragma unroll 8
    for (int k = 0; k < 64; k++) {
        float a[4], bb[4];
#pragma unroll
        for (int i = 0; i < 4; i++) a[i]  = bufA[(ty * 4 + i) * 65 + k];
#pragma unroll
        for (int j = 0; j < 4; j++) bb[j] = bufB[k * 65 + tx * 4 + j];
#pragma unroll
        for (int i = 0; i < 4; i++)
#pragma unroll
            for (int j = 0; j < 4; j++) o[i][j] = fmaf(a[i], bb[j], o[i][j]);
    }

#pragma unroll
    for (int i = 0; i < 4; i++) {
        const size_t eidx = base + (size_t)(ty * 4 + i) * DMODEL + tx * 4;
        __nv_bfloat16 hh[4], ll[4];
#pragma unroll
        for (int j = 0; j < 4; j++) {
            hh[j] = __float2bfloat16(o[i][j]);
            ll[j] = __float2bfloat16(o[i][j] - __bfloat162float(hh[j]));
        }
        *(uint2*)(AOh + eidx) = make_uint2(bf2u(hh[0], hh[1]), bf2u(hh[2], hh[3]));
        *(uint2*)(AOl + eidx) = make_uint2(bf2u(ll[0], ll[1]), bf2u(ll[2], ll[3]));
    }
}

// ---------------------------------------------------------------------------
// Gated residual + LayerNorm
// ---------------------------------------------------------------------------
__global__ __launch_bounds__(256) void resid_ln(const float* __restrict__ hidden,
                                                const float* __restrict__ proj,
                                                const unsigned* __restrict__ mask,
                                                const float* __restrict__ gamma,
                                                const float* __restrict__ beta,
                                                float* __restrict__ out) {
    const int r = blockIdx.x;
    const int t = threadIdx.x;
    const size_t base = (size_t)r * DMODEL + t * 4;

    const float act = (mask[r] != 0u) ? 1.0f : 0.0f;
    const float4 hv = *(const float4*)(hidden + base);
    const float4 ov = *(const float4*)(proj + base);

    float4 f;
    f.x = hv.x + act * ov.x;
    f.y = hv.y + act * ov.y;
    f.z = hv.z + act * ov.z;
    f.w = hv.w + act * ov.w;

    float s  = f.x + f.y + f.z + f.w;
    float s2 = f.x * f.x + f.y * f.y + f.z * f.z + f.w * f.w;

#pragma unroll
    for (int d = 16; d; d >>= 1) {
        s  += __shfl_xor_sync(0xFFFFFFFFu, s,  d);
        s2 += __shfl_xor_sync(0xFFFFFFFFu, s2, d);
    }

    __shared__ float ws[8], ws2[8];
    const int warp = t >> 5, lane = t & 31;
    if (lane == 0) { ws[warp] = s; ws2[warp] = s2; }
    __syncthreads();

    float ts = 0.0f, ts2 = 0.0f;
#pragma unroll
    for (int i = 0; i < 8; i++) { ts += ws[i]; ts2 += ws2[i]; }

    const float mu  = ts * (1.0f / DMODEL);
    const float var = ts2 * (1.0f / DMODEL) - mu * mu;
    const float rs  = rsqrtf(var + LN_EPS);

    const float4 gv = *(const float4*)(gamma + t * 4);
    const float4 bv = *(const float4*)(beta  + t * 4);

    float4 r4;
    r4.x = (f.x - mu) * rs * gv.x + bv.x;
    r4.y = (f.y - mu) * rs * gv.y + bv.y;
    r4.z = (f.z - mu) * rs * gv.z + bv.z;
    r4.w = (f.w - mu) * rs * gv.w + bv.w;
    *(float4*)(out + base) = r4;
}

// ---------------------------------------------------------------------------
// Launch
// ---------------------------------------------------------------------------
extern "C" void kernel_launch(void* const* d_in, const int* in_sizes, int n_in,
                              void* d_out, int out_size) {
    const float*    hidden = (const float*)d_in[0];
    const unsigned* mask   = (const unsigned*)d_in[1];
    const float*    W[4]   = {(const float*)d_in[2], (const float*)d_in[3],
                              (const float*)d_in[4], (const float*)d_in[5]};
    const float*    gamma  = (const float*)d_in[6];
    const float*    beta   = (const float*)d_in[7];
    float*          out    = (float*)d_out;

    float *Qs, *Ks, *Vs, *Os;
    __nv_bfloat16 *hh, *hl, *aoh, *aol, *wh, *wl;
    cudaGetSymbolAddress((void**)&Qs,  g_Q);
    cudaGetSymbolAddress((void**)&Ks,  g_K);
    cudaGetSymbolAddress((void**)&Vs,  g_V);
    cudaGetSymbolAddress((void**)&Os,  g_O);
    cudaGetSymbolAddress((void**)&hh,  g_hh);
    cudaGetSymbolAddress((void**)&hl,  g_hl);
    cudaGetSymbolAddress((void**)&aoh, g_aoh);
    cudaGetSymbolAddress((void**)&aol, g_aol);
    cudaGetSymbolAddress((void**)&wh,  g_wh);
    cudaGetSymbolAddress((void**)&wl,  g_wl);

    cudaFuncSetAttribute(gemm_mma, cudaFuncAttributeMaxDynamicSharedMemorySize, GEMM_SMEM);

    // Conversions
    const int n4h = MTOT * DMODEL / 4;
    cvt_hilo<<<n4h / 256, 256>>>((const float4*)hidden, (uint2*)hh, (uint2*)hl, n4h);
    const int n4w = DMODEL * DMODEL / 4;
    for (int i = 0; i < 4; i++)
        cvt_hilo<<<n4w / 256, 256>>>((const float4*)W[i],
                                     (uint2*)(wh + (size_t)i * DMODEL * DMODEL),
                                     (uint2*)(wl + (size_t)i * DMODEL * DMODEL), n4w);

    const dim3 gg(DMODEL / BN, MTOT / BM);   // (8, 128)
    gemm_mma<<<gg, 256, GEMM_SMEM>>>(hh, hl, wh + 0 * (size_t)DMODEL * DMODEL,
                                     wl + 0 * (size_t)DMODEL * DMODEL, Qs);
    gemm_mma<<<gg, 256, GEMM_SMEM>>>(hh, hl, wh + 1 * (size_t)DMODEL * DMODEL,
                                     wl + 1 * (size_t)DMODEL * DMODEL, Ks);
    gemm_mma<<<gg, 256, GEMM_SMEM>>>(hh, hl, wh + 2 * (size_t)DMODEL * DMODEL,
                                     wl + 2 * (size_t)DMODEL * DMODEL, Vs);

    attn_kernel<<<dim3(NHEAD, BATCH), 256>>>(Qs, Ks, Vs, aoh, aol);

    gemm_mma<<<gg, 256, GEMM_SMEM>>>(aoh, aol, wh + 3 * (size_t)DMODEL * DMODEL,
                                     wl + 3 * (size_t)DMODEL * DMODEL, Os);

    resid_ln<<<MTOT, 256>>>(hidden, Os, mask, gamma, beta, out);
}

// round 5
// speedup vs baseline: 2.3610x; 1.1025x over previous
#include <cuda_runtime.h>
#include <cuda_bf16.h>
#include <cstdint>

// ---------------------------------------------------------------------------
// Problem constants
// ---------------------------------------------------------------------------
#define MTOT   16384      // B*K
#define DMODEL 1024
#define NHEAD  16
#define DHEAD  64
#define BATCH  256
#define SEQLEN 64
#define ATT_SCALE 0.125f
#define LN_EPS 1e-5f

// ---------------------------------------------------------------------------
// Scratch (device globals: the allowed no-alloc workaround)
// ---------------------------------------------------------------------------
__device__ float g_Q [MTOT * DMODEL];
__device__ float g_K [MTOT * DMODEL];
__device__ float g_V [MTOT * DMODEL];
__device__ float g_O [MTOT * DMODEL];
__device__ __nv_bfloat16 g_hh [MTOT * DMODEL];
__device__ __nv_bfloat16 g_hl [MTOT * DMODEL];
__device__ __nv_bfloat16 g_aoh[MTOT * DMODEL];
__device__ __nv_bfloat16 g_aol[MTOT * DMODEL];
__device__ __nv_bfloat16 g_wh [4][DMODEL * DMODEL];
__device__ __nv_bfloat16 g_wl [4][DMODEL * DMODEL];

// ---------------------------------------------------------------------------
// Baseline-PTX helpers (harness compiles via compute_103: no tcgen05)
// ---------------------------------------------------------------------------
__device__ __forceinline__ uint32_t smem_u32(const void* p) {
    uint32_t a;
    asm("{ .reg .u64 t; cvta.to.shared.u64 t, %1; cvt.u32.u64 %0, t; }"
        : "=r"(a) : "l"(p));
    return a;
}

#define CP_ASYNC16(dst, src) \
    asm volatile("cp.async.cg.shared.global [%0], [%1], 16;" :: "r"(dst), "l"(src))
#define CP_COMMIT() asm volatile("cp.async.commit_group;" ::: "memory")
#define CP_WAIT(n)  asm volatile("cp.async.wait_group %0;" :: "n"(n) : "memory")

#define LDSM4(r0, r1, r2, r3, addr) \
    asm volatile("ldmatrix.sync.aligned.m8n8.x4.shared.b16 {%0,%1,%2,%3}, [%4];" \
                 : "=r"(r0), "=r"(r1), "=r"(r2), "=r"(r3) : "r"(addr))

#define MMA_BF16(d, a, b) \
    asm volatile("mma.sync.aligned.m16n8k16.row.col.f32.bf16.bf16.f32 " \
                 "{%0,%1,%2,%3},{%4,%5,%6,%7},{%8,%9},{%0,%1,%2,%3};" \
                 : "+f"((d)[0]), "+f"((d)[1]), "+f"((d)[2]), "+f"((d)[3]) \
                 : "r"((a)[0]), "r"((a)[1]), "r"((a)[2]), "r"((a)[3]), \
                   "r"((b)[0]), "r"((b)[1]))

__device__ __forceinline__ uint32_t bf2u(__nv_bfloat16 a, __nv_bfloat16 b) {
    __nv_bfloat162 t; t.x = a; t.y = b;
    return *reinterpret_cast<uint32_t*>(&t);
}

// ---------------------------------------------------------------------------
// fp32 -> bf16 hi/lo conversion
// ---------------------------------------------------------------------------
__global__ __launch_bounds__(256) void cvt_hilo(const float4* __restrict__ in,
                                                uint2* __restrict__ hi,
                                                uint2* __restrict__ lo, int n4) {
    int i = blockIdx.x * 256 + threadIdx.x;
    if (i >= n4) return;
    float4 v = in[i];
    __nv_bfloat16 h0 = __float2bfloat16(v.x);
    __nv_bfloat16 h1 = __float2bfloat16(v.y);
    __nv_bfloat16 h2 = __float2bfloat16(v.z);
    __nv_bfloat16 h3 = __float2bfloat16(v.w);
    __nv_bfloat16 l0 = __float2bfloat16(v.x - __bfloat162float(h0));
    __nv_bfloat16 l1 = __float2bfloat16(v.y - __bfloat162float(h1));
    __nv_bfloat16 l2 = __float2bfloat16(v.z - __bfloat162float(h2));
    __nv_bfloat16 l3 = __float2bfloat16(v.w - __bfloat162float(h3));
    hi[i] = make_uint2(bf2u(h0, h1), bf2u(h2, h3));
    lo[i] = make_uint2(bf2u(l0, l1), bf2u(l2, l3));
}

// ---------------------------------------------------------------------------
// mma.sync split-bf16 GEMM (NT): C[m,n] = sum_k A[m,k] * B[n,k]  (~fp32)
//   C += Ah*Bh + Ah*Bl + Al*Bh
// BM=128, BN=256, BK=32, cp.async double buffer, XOR-swizzled smem,
// 8 warps = 2(M) x 4(N), warp tile 64x64.
// ---------------------------------------------------------------------------
#define BM 128
#define BN 256
#define BKC 32
#define NC (DMODEL / BKC)        // 32 k-chunks
#define A_BYTES (128 * 64)       // 8192 B per A matrix (128 rows x 32 bf16)
#define B_BYTES (256 * 64)       // 16384 B per B matrix
#define OFF_AH 0
#define OFF_AL (A_BYTES)
#define OFF_BH (2 * A_BYTES)
#define OFF_BL (2 * A_BYTES + B_BYTES)
#define STAGE_BYTES (2 * A_BYTES + 2 * B_BYTES)   // 49152
#define GEMM_SMEM (2 * STAGE_BYTES)               // 98304

__global__ __launch_bounds__(256, 1) void gemm_mma(
    const __nv_bfloat16* __restrict__ Ah, const __nv_bfloat16* __restrict__ Al,
    const __nv_bfloat16* __restrict__ Bh, const __nv_bfloat16* __restrict__ Bl,
    float* __restrict__ C)
{
    extern __shared__ char smem[];
    const uint32_t sb = smem_u32(smem);

    const int tid  = threadIdx.x;
    const int wid  = tid >> 5;
    const int lane = tid & 31;
    const int wm   = wid & 1;        // M offset wm*64
    const int wn   = wid >> 1;       // N offset wn*64
    const int m0   = blockIdx.y * BM;
    const int n0   = blockIdx.x * BN;

    auto load_stage = [&](int kt, int stg) {
        const uint32_t base = sb + stg * STAGE_BYTES;
#pragma unroll
        for (int i = 0; i < 2; i++) {      // A: 512 16B-chunks
            const int idx = tid + i * 256;
            const int r = idx >> 2, c = idx & 3;
            const uint32_t sw = (uint32_t)((c ^ (r & 3)) << 4) + r * 64;
            const size_t goff = (size_t)(m0 + r) * DMODEL + kt * BKC + c * 8;
            CP_ASYNC16(base + OFF_AH + sw, Ah + goff);
            CP_ASYNC16(base + OFF_AL + sw, Al + goff);
        }
#pragma unroll
        for (int i = 0; i < 4; i++) {      // B: 1024 16B-chunks
            const int idx = tid + i * 256;
            const int r = idx >> 2, c = idx & 3;
            const uint32_t sw = (uint32_t)((c ^ (r & 3)) << 4) + r * 64;
            const size_t goff = (size_t)(n0 + r) * DMODEL + kt * BKC + c * 8;
            CP_ASYNC16(base + OFF_BH + sw, Bh + goff);
            CP_ASYNC16(base + OFF_BL + sw, Bl + goff);
        }
        CP_COMMIT();
    };

    float acc[4][8][4];
#pragma unroll
    for (int mi = 0; mi < 4; mi++)
#pragma unroll
        for (int ni = 0; ni < 8; ni++)
#pragma unroll
            for (int q = 0; q < 4; q++) acc[mi][ni][q] = 0.0f;

    const int a_row_in16 = lane & 15;
    const int a_half     = lane >> 4;
    const int b_row_in16 = (lane & 7) + ((lane >> 4) << 3);
    const int b_half     = (lane >> 3) & 1;

    load_stage(0, 0);

    for (int kt = 0; kt < NC; kt++) {
        const int cur = kt & 1;
        if (kt + 1 < NC) {
            load_stage(kt + 1, cur ^ 1);
            CP_WAIT(1);
        } else {
            CP_WAIT(0);
        }
        __syncthreads();

        const uint32_t base = sb + cur * STAGE_BYTES;

#pragma unroll
        for (int kk = 0; kk < 2; kk++) {
            uint32_t ah[4][4], al[4][4];
#pragma unroll
            for (int mi = 0; mi < 4; mi++) {
                const int row = wm * 64 + mi * 16 + a_row_in16;
                const int ch  = kk * 2 + a_half;
                const uint32_t addr = row * 64 + (uint32_t)((ch ^ (row & 3)) << 4);
                LDSM4(ah[mi][0], ah[mi][1], ah[mi][2], ah[mi][3], base + OFF_AH + addr);
                LDSM4(al[mi][0], al[mi][1], al[mi][2], al[mi][3], base + OFF_AL + addr);
            }
#pragma unroll
            for (int p = 0; p < 4; p++) {
                uint32_t bh[2][2], bl[2][2];
                const int row = wn * 64 + p * 16 + b_row_in16;
                const int ch  = kk * 2 + b_half;
                const uint32_t addr = row * 64 + (uint32_t)((ch ^ (row & 3)) << 4);
                LDSM4(bh[0][0], bh[0][1], bh[1][0], bh[1][1], base + OFF_BH + addr);
                LDSM4(bl[0][0], bl[0][1], bl[1][0], bl[1][1], base + OFF_BL + addr);
#pragma unroll
                for (int mi = 0; mi < 4; mi++)
#pragma unroll
                    for (int q = 0; q < 2; q++) {
                        const int ni = 2 * p + q;
                        MMA_BF16(acc[mi][ni], ah[mi], bh[q]);
                        MMA_BF16(acc[mi][ni], ah[mi], bl[q]);
                        MMA_BF16(acc[mi][ni], al[mi], bh[q]);
                    }
            }
        }
        __syncthreads();
    }

    // Epilogue
    const int g  = lane >> 2;
    const int cc = (lane & 3) * 2;
#pragma unroll
    for (int mi = 0; mi < 4; mi++) {
        const int row = m0 + wm * 64 + mi * 16 + g;
#pragma unroll
        for (int ni = 0; ni < 8; ni++) {
            float* p = C + (size_t)row * DMODEL + n0 + wn * 64 + ni * 8 + cc;
            *(float2*)p = make_float2(acc[mi][ni][0], acc[mi][ni][1]);
            *(float2*)(p + 8 * DMODEL) = make_float2(acc[mi][ni][2], acc[mi][ni][3]);
        }
    }
}

// ---------------------------------------------------------------------------
// Attention: one CTA per (b,h). 64x64x64 QK^T -> softmax -> PV.
// K stored transposed in smem; rows padded to 68 floats for aligned float4
// smem access (8 LDS.128 per 64 FMA). Emits bf16 hi/lo for the O GEMM.
// Row masking omitted (redundant with the residual gate).
// ---------------------------------------------------------------------------
#define APAD 68

__global__ __launch_bounds__(256) void attn_kernel(const float* __restrict__ Q,
                                                   const float* __restrict__ Kin,
                                                   const float* __restrict__ V,
                                                   __nv_bfloat16* __restrict__ AOh,
                                                   __nv_bfloat16* __restrict__ AOl) {
    const int h = blockIdx.x;
    const int b = blockIdx.y;
    const int t = threadIdx.x;

    __shared__ __align__(16) float bufA[64 * APAD];   // Q, then P
    __shared__ __align__(16) float bufB[64 * APAD];   // K^T, then V

    const size_t base = (size_t)b * SEQLEN * DMODEL + h * DHEAD;
    const float* Qb = Q   + base;
    const float* Kb = Kin + base;
    const float* Vb = V   + base;

    // Q row-major (float4), K transposed (scalar)
    for (int e = t; e < 1024; e += 256) {
        const int r = e >> 4, d4 = e & 15;
        *(float4*)&bufA[r * APAD + d4 * 4] = *(const float4*)&Qb[(size_t)r * DMODEL + d4 * 4];
    }
    for (int e = t; e < 4096; e += 256) {
        const int r = e >> 6, d = e & 63;
        bufB[d * APAD + r] = Kb[(size_t)r * DMODEL + d];
    }
    __syncthreads();

    const int ty = t >> 4;   // q rows ty*4..+3
    const int tx = t & 15;   // k cols tx*4..+3

    float s[4][4];
#pragma unroll
    for (int i = 0; i < 4; i++)
#pragma unroll
        for (int j = 0; j < 4; j++) s[i][j] = 0.0f;

    for (int d0 = 0; d0 < 64; d0 += 4) {
        float4 a4[4], b4[4];
#pragma unroll
        for (int i = 0; i < 4; i++)
            a4[i] = *(const float4*)&bufA[(ty * 4 + i) * APAD + d0];
#pragma unroll
        for (int dd = 0; dd < 4; dd++)
            b4[dd] = *(const float4*)&bufB[(d0 + dd) * APAD + tx * 4];
#pragma unroll
        for (int i = 0; i < 4; i++) {
            const float* ap = (const float*)&a4[i];
#pragma unroll
            for (int dd = 0; dd < 4; dd++) {
                const float av = ap[dd];
                const float* bp = (const float*)&b4[dd];
                s[i][0] = fmaf(av, bp[0], s[i][0]);
                s[i][1] = fmaf(av, bp[1], s[i][1]);
                s[i][2] = fmaf(av, bp[2], s[i][2]);
                s[i][3] = fmaf(av, bp[3], s[i][3]);
            }
        }
    }
    __syncthreads();   // Q and K^T reads complete

    // P (scaled scores) -> bufA ; V (row-major) -> bufB
#pragma unroll
    for (int i = 0; i < 4; i++) {
        float4 v = make_float4(s[i][0] * ATT_SCALE, s[i][1] * ATT_SCALE,
                               s[i][2] * ATT_SCALE, s[i][3] * ATT_SCALE);
        *(float4*)&bufA[(ty * 4 + i) * APAD + tx * 4] = v;
    }
    for (int e = t; e < 1024; e += 256) {
        const int r = e >> 4, d4 = e & 15;
        *(float4*)&bufB[r * APAD + d4 * 4] = *(const float4*)&Vb[(size_t)r * DMODEL + d4 * 4];
    }
    __syncthreads();

    // Softmax: warp w -> rows w*8..+7, 2 elems/lane
    const int warp = t >> 5, lane = t & 31;
    for (int rq = warp * 8; rq < warp * 8 + 8; rq++) {
        float x0 = bufA[rq * APAD + lane];
        float x1 = bufA[rq * APAD + 32 + lane];
        float mx = fmaxf(x0, x1);
#pragma unroll
        for (int d2 = 16; d2; d2 >>= 1)
            mx = fmaxf(mx, __shfl_xor_sync(0xFFFFFFFFu, mx, d2));
        float e0 = __expf(x0 - mx);
        float e1 = __expf(x1 - mx);
        float sm = e0 + e1;
#pragma unroll
        for (int d2 = 16; d2; d2 >>= 1)
            sm += __shfl_xor_sync(0xFFFFFFFFu, sm, d2);
        const float inv = 1.0f / sm;
        bufA[rq * APAD + lane]      = e0 * inv;
        bufA[rq * APAD + 32 + lane] = e1 * inv;
    }
    __syncthreads();

    // O = P @ V  (same float4 tiling; V rows are k, cols are dh)
    float o[4][4];
#pragma unroll
    for (int i = 0; i < 4; i++)
#pragma unroll
        for (int j = 0; j < 4; j++) o[i][j] = 0.0f;

    for (int k0 = 0; k0 < 64; k0 += 4) {
        float4 a4[4], b4[4];
#pragma unroll
        for (int i = 0; i < 4; i++)
            a4[i] = *(const float4*)&bufA[(ty * 4 + i) * APAD + k0];
#pragma unroll
        for (int kk = 0; kk < 4; kk++)
            b4[kk] = *(const float4*)&bufB[(k0 + kk) * APAD + tx * 4];
#pragma unroll
        for (int i = 0; i < 4; i++) {
            const float* ap = (const float*)&a4[i];
#pragma unroll
            for (int kk = 0; kk < 4; kk++) {
                const float av = ap[kk];
                const float* bp = (const float*)&b4[kk];
                o[i][0] = fmaf(av, bp[0], o[i][0]);
                o[i][1] = fmaf(av, bp[1], o[i][1]);
                o[i][2] = fmaf(av, bp[2], o[i][2]);
                o[i][3] = fmaf(av, bp[3], o[i][3]);
            }
        }
    }

    // hi/lo bf16 epilogue
#pragma unroll
    for (int i = 0; i < 4; i++) {
        const size_t eidx = base + (size_t)(ty * 4 + i) * DMODEL + tx * 4;
        __nv_bfloat16 hh[4], ll[4];
#pragma unroll
        for (int j = 0; j < 4; j++) {
            hh[j] = __float2bfloat16(o[i][j]);
            ll[j] = __float2bfloat16(o[i][j] - __bfloat162float(hh[j]));
        }
        *(uint2*)(AOh + eidx) = make_uint2(bf2u(hh[0], hh[1]), bf2u(hh[2], hh[3]));
        *(uint2*)(AOl + eidx) = make_uint2(bf2u(ll[0], ll[1]), bf2u(ll[2], ll[3]));
    }
}

// ---------------------------------------------------------------------------
// Gated residual + LayerNorm
// ---------------------------------------------------------------------------
__global__ __launch_bounds__(256) void resid_ln(const float* __restrict__ hidden,
                                                const float* __restrict__ proj,
                                                const unsigned* __restrict__ mask,
                                                const float* __restrict__ gamma,
                                                const float* __restrict__ beta,
                                                float* __restrict__ out) {
    const int r = blockIdx.x;
    const int t = threadIdx.x;
    const size_t base = (size_t)r * DMODEL + t * 4;

    const float act = (mask[r] != 0u) ? 1.0f : 0.0f;
    const float4 hv = *(const float4*)(hidden + base);
    const float4 ov = *(const float4*)(proj + base);

    float4 f;
    f.x = hv.x + act * ov.x;
    f.y = hv.y + act * ov.y;
    f.z = hv.z + act * ov.z;
    f.w = hv.w + act * ov.w;

    float s  = f.x + f.y + f.z + f.w;
    float s2 = f.x * f.x + f.y * f.y + f.z * f.z + f.w * f.w;

#pragma unroll
    for (int d = 16; d; d >>= 1) {
        s  += __shfl_xor_sync(0xFFFFFFFFu, s,  d);
        s2 += __shfl_xor_sync(0xFFFFFFFFu, s2, d);
    }

    __shared__ float ws[8], ws2[8];
    const int warp = t >> 5, lane = t & 31;
    if (lane == 0) { ws[warp] = s; ws2[warp] = s2; }
    __syncthreads();

    float ts = 0.0f, ts2 = 0.0f;
#pragma unroll
    for (int i = 0; i < 8; i++) { ts += ws[i]; ts2 += ws2[i]; }

    const float mu  = ts * (1.0f / DMODEL);
    const float var = ts2 * (1.0f / DMODEL) - mu * mu;
    const float rs  = rsqrtf(var + LN_EPS);

    const float4 gv = *(const float4*)(gamma + t * 4);
    const float4 bv = *(const float4*)(beta  + t * 4);

    float4 r4;
    r4.x = (f.x - mu) * rs * gv.x + bv.x;
    r4.y = (f.y - mu) * rs * gv.y + bv.y;
    r4.z = (f.z - mu) * rs * gv.z + bv.z;
    r4.w = (f.w - mu) * rs * gv.w + bv.w;
    *(float4*)(out + base) = r4;
}

// ---------------------------------------------------------------------------
// Launch
// ---------------------------------------------------------------------------
extern "C" void kernel_launch(void* const* d_in, const int* in_sizes, int n_in,
                              void* d_out, int out_size) {
    const float*    hidden = (const float*)d_in[0];
    const unsigned* mask   = (const unsigned*)d_in[1];
    const float*    W[4]   = {(const float*)d_in[2], (const float*)d_in[3],
                              (const float*)d_in[4], (const float*)d_in[5]};
    const float*    gamma  = (const float*)d_in[6];
    const float*    beta   = (const float*)d_in[7];
    float*          out    = (float*)d_out;

    float *Qs, *Ks, *Vs, *Os;
    __nv_bfloat16 *hh, *hl, *aoh, *aol, *wh, *wl;
    cudaGetSymbolAddress((void**)&Qs,  g_Q);
    cudaGetSymbolAddress((void**)&Ks,  g_K);
    cudaGetSymbolAddress((void**)&Vs,  g_V);
    cudaGetSymbolAddress((void**)&Os,  g_O);
    cudaGetSymbolAddress((void**)&hh,  g_hh);
    cudaGetSymbolAddress((void**)&hl,  g_hl);
    cudaGetSymbolAddress((void**)&aoh, g_aoh);
    cudaGetSymbolAddress((void**)&aol, g_aol);
    cudaGetSymbolAddress((void**)&wh,  g_wh);
    cudaGetSymbolAddress((void**)&wl,  g_wl);

    cudaFuncSetAttribute(gemm_mma, cudaFuncAttributeMaxDynamicSharedMemorySize, GEMM_SMEM);

    // Conversions
    const int n4h = MTOT * DMODEL / 4;
    cvt_hilo<<<n4h / 256, 256>>>((const float4*)hidden, (uint2*)hh, (uint2*)hl, n4h);
    const int n4w = DMODEL * DMODEL / 4;
    for (int i = 0; i < 4; i++)
        cvt_hilo<<<n4w / 256, 256>>>((const float4*)W[i],
                                     (uint2*)(wh + (size_t)i * DMODEL * DMODEL),
                                     (uint2*)(wl + (size_t)i * DMODEL * DMODEL), n4w);

    const dim3 gg(DMODEL / BN, MTOT / BM);   // (4, 128)
    gemm_mma<<<gg, 256, GEMM_SMEM>>>(hh, hl, wh + 0 * (size_t)DMODEL * DMODEL,
                                     wl + 0 * (size_t)DMODEL * DMODEL, Qs);
    gemm_mma<<<gg, 256, GEMM_SMEM>>>(hh, hl, wh + 1 * (size_t)DMODEL * DMODEL,
                                     wl + 1 * (size_t)DMODEL * DMODEL, Ks);
    gemm_mma<<<gg, 256, GEMM_SMEM>>>(hh, hl, wh + 2 * (size_t)DMODEL * DMODEL,
                                     wl + 2 * (size_t)DMODEL * DMODEL, Vs);

    attn_kernel<<<dim3(NHEAD, BATCH), 256>>>(Qs, Ks, Vs, aoh, aol);

    gemm_mma<<<gg, 256, GEMM_SMEM>>>(aoh, aol, wh + 3 * (size_t)DMODEL * DMODEL,
                                     wl + 3 * (size_t)DMODEL * DMODEL, Os);

    resid_ln<<<MTOT, 256>>>(hidden, Os, mask, gamma, beta, out);
}

// round 6
// speedup vs baseline: 5.2365x; 2.2179x over previous
#include <cuda_runtime.h>
#include <cuda_fp16.h>
#include <cuda_bf16.h>
#include <cstdint>

// ---------------------------------------------------------------------------
// Problem constants
// ---------------------------------------------------------------------------
#define MTOT   16384      // B*K
#define DMODEL 1024
#define NHEAD  16
#define DHEAD  64
#define BATCH  256
#define SEQLEN 64
#define ATT_SCALE 0.125f
#define LN_EPS 1e-5f

// ---------------------------------------------------------------------------
// Scratch (device globals: the allowed no-alloc workaround)
// ---------------------------------------------------------------------------
__device__ float g_Q [MTOT * DMODEL];
__device__ float g_K [MTOT * DMODEL];
__device__ float g_V [MTOT * DMODEL];
__device__ float g_O [MTOT * DMODEL];
__device__ __half g_hf [MTOT * DMODEL];          // hidden fp16
__device__ __half g_aof[MTOT * DMODEL];          // attn out fp16
__device__ __half g_wf [4][DMODEL * DMODEL];     // Wq,Wk,Wv,Wo fp16

// ---------------------------------------------------------------------------
// Baseline-PTX helpers (harness compiles via compute_103: no tcgen05)
// ---------------------------------------------------------------------------
__device__ __forceinline__ uint32_t smem_u32(const void* p) {
    uint32_t a;
    asm("{ .reg .u64 t; cvta.to.shared.u64 t, %1; cvt.u32.u64 %0, t; }"
        : "=r"(a) : "l"(p));
    return a;
}

#define CP_ASYNC16(dst, src) \
    asm volatile("cp.async.cg.shared.global [%0], [%1], 16;" :: "r"(dst), "l"(src))
#define CP_COMMIT() asm volatile("cp.async.commit_group;" ::: "memory")
#define CP_WAIT(n)  asm volatile("cp.async.wait_group %0;" :: "n"(n) : "memory")

#define LDSM4(r0, r1, r2, r3, addr) \
    asm volatile("ldmatrix.sync.aligned.m8n8.x4.shared.b16 {%0,%1,%2,%3}, [%4];" \
                 : "=r"(r0), "=r"(r1), "=r"(r2), "=r"(r3) : "r"(addr))

#define MMA_F16(d, a, b) \
    asm volatile("mma.sync.aligned.m16n8k16.row.col.f32.f16.f16.f32 " \
                 "{%0,%1,%2,%3},{%4,%5,%6,%7},{%8,%9},{%0,%1,%2,%3};" \
                 : "+f"((d)[0]), "+f"((d)[1]), "+f"((d)[2]), "+f"((d)[3]) \
                 : "r"((a)[0]), "r"((a)[1]), "r"((a)[2]), "r"((a)[3]), \
                   "r"((b)[0]), "r"((b)[1]))

// ---------------------------------------------------------------------------
// fp32 -> fp16 conversion (vectorized, 4 elems/thread)
// ---------------------------------------------------------------------------
__global__ __launch_bounds__(256) void cvt_f16(const float4* __restrict__ in,
                                               uint2* __restrict__ out16, int n4) {
    int i = blockIdx.x * 256 + threadIdx.x;
    if (i >= n4) return;
    float4 v = in[i];
    __half2 p0 = __floats2half2_rn(v.x, v.y);
    __half2 p1 = __floats2half2_rn(v.z, v.w);
    out16[i] = make_uint2(*reinterpret_cast<uint32_t*>(&p0),
                          *reinterpret_cast<uint32_t*>(&p1));
}

// ---------------------------------------------------------------------------
// mma.sync fp16 GEMM (NT): C[m,n] = sum_k A[m,k] * B[n,k], fp32 accum.
// BM=128, BN=256, BK=64, cp.async double buffer, 8-chunk XOR swizzle,
// 8 warps = 2(M) x 4(N), warp tile 64x64.
// ---------------------------------------------------------------------------
#define BM 128
#define BN 256
#define BKC 64
#define NC (DMODEL / BKC)        // 16 k-chunks
#define A_BYTES (128 * 128)      // 16384 B (128 rows x 64 fp16)
#define B_BYTES (256 * 128)      // 32768 B
#define OFF_A 0
#define OFF_B A_BYTES
#define STAGE_BYTES (A_BYTES + B_BYTES)   // 49152
#define GEMM_SMEM (2 * STAGE_BYTES)       // 98304

__global__ __launch_bounds__(256, 1) void gemm_mma(
    const __half* __restrict__ A, const __half* __restrict__ B,
    float* __restrict__ C)
{
    extern __shared__ char smem[];
    const uint32_t sb = smem_u32(smem);

    const int tid  = threadIdx.x;
    const int wid  = tid >> 5;
    const int lane = tid & 31;
    const int wm   = wid & 1;        // M offset wm*64
    const int wn   = wid >> 1;       // N offset wn*64
    const int m0   = blockIdx.y * BM;
    const int n0   = blockIdx.x * BN;

    auto load_stage = [&](int kt, int stg) {
        const uint32_t base = sb + stg * STAGE_BYTES;
#pragma unroll
        for (int i = 0; i < 4; i++) {      // A: 1024 16B-chunks
            const int idx = tid + i * 256;
            const int r = idx >> 3, c = idx & 7;
            const uint32_t sw = (uint32_t)r * 128 + (uint32_t)((c ^ (r & 7)) << 4);
            CP_ASYNC16(base + OFF_A + sw,
                       A + (size_t)(m0 + r) * DMODEL + kt * BKC + c * 8);
        }
#pragma unroll
        for (int i = 0; i < 8; i++) {      // B: 2048 16B-chunks
            const int idx = tid + i * 256;
            const int r = idx >> 3, c = idx & 7;
            const uint32_t sw = (uint32_t)r * 128 + (uint32_t)((c ^ (r & 7)) << 4);
            CP_ASYNC16(base + OFF_B + sw,
                       B + (size_t)(n0 + r) * DMODEL + kt * BKC + c * 8);
        }
        CP_COMMIT();
    };

    float acc[4][8][4];
#pragma unroll
    for (int mi = 0; mi < 4; mi++)
#pragma unroll
        for (int ni = 0; ni < 8; ni++)
#pragma unroll
            for (int q = 0; q < 4; q++) acc[mi][ni][q] = 0.0f;

    const int a_row_in16 = lane & 15;
    const int a_half     = lane >> 4;          // 16B chunk within k16
    const int b_row_in16 = (lane & 7) + ((lane >> 4) << 3);
    const int b_half     = (lane >> 3) & 1;

    load_stage(0, 0);

    for (int kt = 0; kt < NC; kt++) {
        const int cur = kt & 1;
        if (kt + 1 < NC) {
            load_stage(kt + 1, cur ^ 1);
            CP_WAIT(1);
        } else {
            CP_WAIT(0);
        }
        __syncthreads();

        const uint32_t base = sb + cur * STAGE_BYTES;

#pragma unroll
        for (int kk = 0; kk < 4; kk++) {   // 4 k16 groups in BK=64
            uint32_t ah[4][4];
#pragma unroll
            for (int mi = 0; mi < 4; mi++) {
                const int row = wm * 64 + mi * 16 + a_row_in16;
                const int ch  = kk * 2 + a_half;
                const uint32_t addr = (uint32_t)row * 128 + (uint32_t)((ch ^ (row & 7)) << 4);
                LDSM4(ah[mi][0], ah[mi][1], ah[mi][2], ah[mi][3], base + OFF_A + addr);
            }
#pragma unroll
            for (int p = 0; p < 4; p++) {
                uint32_t bf[2][2];
                const int row = wn * 64 + p * 16 + b_row_in16;
                const int ch  = kk * 2 + b_half;
                const uint32_t addr = (uint32_t)row * 128 + (uint32_t)((ch ^ (row & 7)) << 4);
                LDSM4(bf[0][0], bf[0][1], bf[1][0], bf[1][1], base + OFF_B + addr);
#pragma unroll
                for (int mi = 0; mi < 4; mi++)
#pragma unroll
                    for (int q = 0; q < 2; q++)
                        MMA_F16(acc[mi][2 * p + q], ah[mi], bf[q]);
            }
        }
        __syncthreads();
    }

    // Epilogue
    const int g  = lane >> 2;
    const int cc = (lane & 3) * 2;
#pragma unroll
    for (int mi = 0; mi < 4; mi++) {
        const int row = m0 + wm * 64 + mi * 16 + g;
#pragma unroll
        for (int ni = 0; ni < 8; ni++) {
            float* p = C + (size_t)row * DMODEL + n0 + wn * 64 + ni * 8 + cc;
            *(float2*)p = make_float2(acc[mi][ni][0], acc[mi][ni][1]);
            *(float2*)(p + 8 * DMODEL) = make_float2(acc[mi][ni][2], acc[mi][ni][3]);
        }
    }
}

// ---------------------------------------------------------------------------
// Attention: one CTA per (b,h). 64x64x64 QK^T -> softmax -> PV.
// K transposed in smem, rows padded to 68 floats (float4 smem access).
// Emits fp16 for the O GEMM. Row masking omitted (redundant with gate).
// ---------------------------------------------------------------------------
#define APAD 68

__global__ __launch_bounds__(256) void attn_kernel(const float* __restrict__ Q,
                                                   const float* __restrict__ Kin,
                                                   const float* __restrict__ V,
                                                   __half* __restrict__ AOf) {
    const int h = blockIdx.x;
    const int b = blockIdx.y;
    const int t = threadIdx.x;

    __shared__ __align__(16) float bufA[64 * APAD];   // Q, then P
    __shared__ __align__(16) float bufB[64 * APAD];   // K^T, then V

    const size_t base = (size_t)b * SEQLEN * DMODEL + h * DHEAD;
    const float* Qb = Q   + base;
    const float* Kb = Kin + base;
    const float* Vb = V   + base;

    for (int e = t; e < 1024; e += 256) {
        const int r = e >> 4, d4 = e & 15;
        *(float4*)&bufA[r * APAD + d4 * 4] = *(const float4*)&Qb[(size_t)r * DMODEL + d4 * 4];
    }
    for (int e = t; e < 4096; e += 256) {
        const int r = e >> 6, d = e & 63;
        bufB[d * APAD + r] = Kb[(size_t)r * DMODEL + d];
    }
    __syncthreads();

    const int ty = t >> 4;
    const int tx = t & 15;

    float s[4][4];
#pragma unroll
    for (int i = 0; i < 4; i++)
#pragma unroll
        for (int j = 0; j < 4; j++) s[i][j] = 0.0f;

    for (int d0 = 0; d0 < 64; d0 += 4) {
        float4 a4[4], b4[4];
#pragma unroll
        for (int i = 0; i < 4; i++)
            a4[i] = *(const float4*)&bufA[(ty * 4 + i) * APAD + d0];
#pragma unroll
        for (int dd = 0; dd < 4; dd++)
            b4[dd] = *(const float4*)&bufB[(d0 + dd) * APAD + tx * 4];
#pragma unroll
        for (int i = 0; i < 4; i++) {
            const float* ap = (const float*)&a4[i];
#pragma unroll
            for (int dd = 0; dd < 4; dd++) {
                const float av = ap[dd];
                const float* bp = (const float*)&b4[dd];
                s[i][0] = fmaf(av, bp[0], s[i][0]);
                s[i][1] = fmaf(av, bp[1], s[i][1]);
                s[i][2] = fmaf(av, bp[2], s[i][2]);
                s[i][3] = fmaf(av, bp[3], s[i][3]);
            }
        }
    }
    __syncthreads();

#pragma unroll
    for (int i = 0; i < 4; i++) {
        float4 v = make_float4(s[i][0] * ATT_SCALE, s[i][1] * ATT_SCALE,
                               s[i][2] * ATT_SCALE, s[i][3] * ATT_SCALE);
        *(float4*)&bufA[(ty * 4 + i) * APAD + tx * 4] = v;
    }
    for (int e = t; e < 1024; e += 256) {
        const int r = e >> 4, d4 = e & 15;
        *(float4*)&bufB[r * APAD + d4 * 4] = *(const float4*)&Vb[(size_t)r * DMODEL + d4 * 4];
    }
    __syncthreads();

    const int warp = t >> 5, lane = t & 31;
    for (int rq = warp * 8; rq < warp * 8 + 8; rq++) {
        float x0 = bufA[rq * APAD + lane];
        float x1 = bufA[rq * APAD + 32 + lane];
        float mx = fmaxf(x0, x1);
#pragma unroll
        for (int d2 = 16; d2; d2 >>= 1)
            mx = fmaxf(mx, __shfl_xor_sync(0xFFFFFFFFu, mx, d2));
        float e0 = __expf(x0 - mx);
        float e1 = __expf(x1 - mx);
        float sm = e0 + e1;
#pragma unroll
        for (int d2 = 16; d2; d2 >>= 1)
            sm += __shfl_xor_sync(0xFFFFFFFFu, sm, d2);
        const float inv = 1.0f / sm;
        bufA[rq * APAD + lane]      = e0 * inv;
        bufA[rq * APAD + 32 + lane] = e1 * inv;
    }
    __syncthreads();

    float o[4][4];
#pragma unroll
    for (int i = 0; i < 4; i++)
#pragma unroll
        for (int j = 0; j < 4; j++) o[i][j] = 0.0f;

    for (int k0 = 0; k0 < 64; k0 += 4) {
        float4 a4[4], b4[4];
#pragma unroll
        for (int i = 0; i < 4; i++)
            a4[i] = *(const float4*)&bufA[(ty * 4 + i) * APAD + k0];
#pragma unroll
        for (int kk = 0; kk < 4; kk++)
            b4[kk] = *(const float4*)&bufB[(k0 + kk) * APAD + tx * 4];
#pragma unroll
        for (int i = 0; i < 4; i++) {
            const float* ap = (const float*)&a4[i];
#pragma unroll
            for (int kk = 0; kk < 4; kk++) {
                const float av = ap[kk];
                const float* bp = (const float*)&b4[kk];
                o[i][0] = fmaf(av, bp[0], o[i][0]);
                o[i][1] = fmaf(av, bp[1], o[i][1]);
                o[i][2] = fmaf(av, bp[2], o[i][2]);
                o[i][3] = fmaf(av, bp[3], o[i][3]);
            }
        }
    }

#pragma unroll
    for (int i = 0; i < 4; i++) {
        const size_t eidx = base + (size_t)(ty * 4 + i) * DMODEL + tx * 4;
        __half2 p0 = __floats2half2_rn(o[i][0], o[i][1]);
        __half2 p1 = __floats2half2_rn(o[i][2], o[i][3]);
        *(uint2*)(AOf + eidx) = make_uint2(*reinterpret_cast<uint32_t*>(&p0),
                                           *reinterpret_cast<uint32_t*>(&p1));
    }
}

// ---------------------------------------------------------------------------
// Gated residual + LayerNorm
// ---------------------------------------------------------------------------
__global__ __launch_bounds__(256) void resid_ln(const float* __restrict__ hidden,
                                                const float* __restrict__ proj,
                                                const unsigned* __restrict__ mask,
                                                const float* __restrict__ gamma,
                                                const float* __restrict__ beta,
                                                float* __restrict__ out) {
    const int r = blockIdx.x;
    const int t = threadIdx.x;
    const size_t base = (size_t)r * DMODEL + t * 4;

    const float act = (mask[r] != 0u) ? 1.0f : 0.0f;
    const float4 hv = *(const float4*)(hidden + base);
    const float4 ov = *(const float4*)(proj + base);

    float4 f;
    f.x = hv.x + act * ov.x;
    f.y = hv.y + act * ov.y;
    f.z = hv.z + act * ov.z;
    f.w = hv.w + act * ov.w;

    float s  = f.x + f.y + f.z + f.w;
    float s2 = f.x * f.x + f.y * f.y + f.z * f.z + f.w * f.w;

#pragma unroll
    for (int d = 16; d; d >>= 1) {
        s  += __shfl_xor_sync(0xFFFFFFFFu, s,  d);
        s2 += __shfl_xor_sync(0xFFFFFFFFu, s2, d);
    }

    __shared__ float ws[8], ws2[8];
    const int warp = t >> 5, lane = t & 31;
    if (lane == 0) { ws[warp] = s; ws2[warp] = s2; }
    __syncthreads();

    float ts = 0.0f, ts2 = 0.0f;
#pragma unroll
    for (int i = 0; i < 8; i++) { ts += ws[i]; ts2 += ws2[i]; }

    const float mu  = ts * (1.0f / DMODEL);
    const float var = ts2 * (1.0f / DMODEL) - mu * mu;
    const float rs  = rsqrtf(var + LN_EPS);

    const float4 gv = *(const float4*)(gamma + t * 4);
    const float4 bv = *(const float4*)(beta  + t * 4);

    float4 r4;
    r4.x = (f.x - mu) * rs * gv.x + bv.x;
    r4.y = (f.y - mu) * rs * gv.y + bv.y;
    r4.z = (f.z - mu) * rs * gv.z + bv.z;
    r4.w = (f.w - mu) * rs * gv.w + bv.w;
    *(float4*)(out + base) = r4;
}

// ---------------------------------------------------------------------------
// Launch
// ---------------------------------------------------------------------------
extern "C" void kernel_launch(void* const* d_in, const int* in_sizes, int n_in,
                              void* d_out, int out_size) {
    const float*    hidden = (const float*)d_in[0];
    const unsigned* mask   = (const unsigned*)d_in[1];
    const float*    W[4]   = {(const float*)d_in[2], (const float*)d_in[3],
                              (const float*)d_in[4], (const float*)d_in[5]};
    const float*    gamma  = (const float*)d_in[6];
    const float*    beta   = (const float*)d_in[7];
    float*          out    = (float*)d_out;

    float *Qs, *Ks, *Vs, *Os;
    __half *hf, *aof, *wf;
    cudaGetSymbolAddress((void**)&Qs,  g_Q);
    cudaGetSymbolAddress((void**)&Ks,  g_K);
    cudaGetSymbolAddress((void**)&Vs,  g_V);
    cudaGetSymbolAddress((void**)&Os,  g_O);
    cudaGetSymbolAddress((void**)&hf,  g_hf);
    cudaGetSymbolAddress((void**)&aof, g_aof);
    cudaGetSymbolAddress((void**)&wf,  g_wf);

    cudaFuncSetAttribute(gemm_mma, cudaFuncAttributeMaxDynamicSharedMemorySize, GEMM_SMEM);

    // Conversions
    const int n4h = MTOT * DMODEL / 4;
    cvt_f16<<<n4h / 256, 256>>>((const float4*)hidden, (uint2*)hf, n4h);
    const int n4w = DMODEL * DMODEL / 4;
    for (int i = 0; i < 4; i++)
        cvt_f16<<<n4w / 256, 256>>>((const float4*)W[i],
                                    (uint2*)(wf + (size_t)i * DMODEL * DMODEL), n4w);

    const dim3 gg(DMODEL / BN, MTOT / BM);   // (4, 128)
    gemm_mma<<<gg, 256, GEMM_SMEM>>>(hf, wf + 0 * (size_t)DMODEL * DMODEL, Qs);
    gemm_mma<<<gg, 256, GEMM_SMEM>>>(hf, wf + 1 * (size_t)DMODEL * DMODEL, Ks);
    gemm_mma<<<gg, 256, GEMM_SMEM>>>(hf, wf + 2 * (size_t)DMODEL * DMODEL, Vs);

    attn_kernel<<<dim3(NHEAD, BATCH), 256>>>(Qs, Ks, Vs, aof);

    gemm_mma<<<gg, 256, GEMM_SMEM>>>(aof, wf + 3 * (size_t)DMODEL * DMODEL, Os);

    resid_ln<<<MTOT, 256>>>(hidden, Os, mask, gamma, beta, out);
}

// round 7
// speedup vs baseline: 6.6362x; 1.2673x over previous
#include <cuda_runtime.h>
#include <cuda_fp16.h>
#include <cstdint>

// ---------------------------------------------------------------------------
// Problem constants
// ---------------------------------------------------------------------------
#define MTOT   16384      // B*K
#define DMODEL 1024
#define NHEAD  16
#define DHEAD  64
#define BATCH  256
#define SEQLEN 64
#define ATT_SCALE 0.125f
#define LN_EPS 1e-5f

// ---------------------------------------------------------------------------
// Scratch (device globals: the allowed no-alloc workaround)
// ---------------------------------------------------------------------------
__device__ __half g_Qf [MTOT * DMODEL];          // Q (pre-scaled) fp16
__device__ __half g_Kf [MTOT * DMODEL];          // K fp16
__device__ __half g_Vf [MTOT * DMODEL];          // V fp16
__device__ float  g_O  [MTOT * DMODEL];          // O projection fp32
__device__ __half g_hf [MTOT * DMODEL];          // hidden fp16
__device__ __half g_aof[MTOT * DMODEL];          // attn out fp16
__device__ __half g_wf [4][DMODEL * DMODEL];     // Wq,Wk,Wv,Wo fp16

// ---------------------------------------------------------------------------
// Baseline-PTX helpers (harness compiles via compute_103: no tcgen05)
// ---------------------------------------------------------------------------
__device__ __forceinline__ uint32_t smem_u32(const void* p) {
    uint32_t a;
    asm("{ .reg .u64 t; cvta.to.shared.u64 t, %1; cvt.u32.u64 %0, t; }"
        : "=r"(a) : "l"(p));
    return a;
}

#define CP_ASYNC16(dst, src) \
    asm volatile("cp.async.cg.shared.global [%0], [%1], 16;" :: "r"(dst), "l"(src))
#define CP_COMMIT() asm volatile("cp.async.commit_group;" ::: "memory")
#define CP_WAIT(n)  asm volatile("cp.async.wait_group %0;" :: "n"(n) : "memory")

#define LDSM4(r0, r1, r2, r3, addr) \
    asm volatile("ldmatrix.sync.aligned.m8n8.x4.shared.b16 {%0,%1,%2,%3}, [%4];" \
                 : "=r"(r0), "=r"(r1), "=r"(r2), "=r"(r3) : "r"(addr))

#define LDSM4T(r0, r1, r2, r3, addr) \
    asm volatile("ldmatrix.sync.aligned.m8n8.x4.trans.shared.b16 {%0,%1,%2,%3}, [%4];" \
                 : "=r"(r0), "=r"(r1), "=r"(r2), "=r"(r3) : "r"(addr))

#define MMA_F16(d, a, b) \
    asm volatile("mma.sync.aligned.m16n8k16.row.col.f32.f16.f16.f32 " \
                 "{%0,%1,%2,%3},{%4,%5,%6,%7},{%8,%9},{%0,%1,%2,%3};" \
                 : "+f"((d)[0]), "+f"((d)[1]), "+f"((d)[2]), "+f"((d)[3]) \
                 : "r"((a)[0]), "r"((a)[1]), "r"((a)[2]), "r"((a)[3]), \
                   "r"((b)[0]), "r"((b)[1]))

__device__ __forceinline__ uint32_t h2u(__half2 h) {
    return *reinterpret_cast<uint32_t*>(&h);
}

// ---------------------------------------------------------------------------
// fp32 -> fp16 conversion
// ---------------------------------------------------------------------------
__global__ __launch_bounds__(256) void cvt_f16(const float4* __restrict__ in,
                                               uint2* __restrict__ out16, int n4) {
    int i = blockIdx.x * 256 + threadIdx.x;
    if (i >= n4) return;
    float4 v = in[i];
    __half2 p0 = __floats2half2_rn(v.x, v.y);
    __half2 p1 = __floats2half2_rn(v.z, v.w);
    out16[i] = make_uint2(h2u(p0), h2u(p1));
}

// ---------------------------------------------------------------------------
// mma.sync fp16 GEMM (NT): C[m,n] = sum_k A[m,k] * B[n,k], fp32 accum.
// BM=128, BN=256, BK=64, cp.async double buffer, 8-chunk XOR swizzle,
// 8 warps = 2(M) x 4(N), warp tile 64x64.
// Epilogue: Ch != nullptr -> fp16 output (acc*scale), else fp32 to Cf.
// ---------------------------------------------------------------------------
#define BM 128
#define BN 256
#define BKC 64
#define NC (DMODEL / BKC)        // 16 k-chunks
#define A_BYTES (128 * 128)
#define B_BYTES (256 * 128)
#define OFF_A 0
#define OFF_B A_BYTES
#define STAGE_BYTES (A_BYTES + B_BYTES)   // 49152
#define GEMM_SMEM (2 * STAGE_BYTES)       // 98304

__global__ __launch_bounds__(256, 1) void gemm_mma(
    const __half* __restrict__ A, const __half* __restrict__ B,
    float* __restrict__ Cf, __half* __restrict__ Ch, float scale)
{
    extern __shared__ char smem[];
    const uint32_t sb = smem_u32(smem);

    const int tid  = threadIdx.x;
    const int wid  = tid >> 5;
    const int lane = tid & 31;
    const int wm   = wid & 1;
    const int wn   = wid >> 1;
    const int m0   = blockIdx.y * BM;
    const int n0   = blockIdx.x * BN;

    auto load_stage = [&](int kt, int stg) {
        const uint32_t base = sb + stg * STAGE_BYTES;
#pragma unroll
        for (int i = 0; i < 4; i++) {
            const int idx = tid + i * 256;
            const int r = idx >> 3, c = idx & 7;
            const uint32_t sw = (uint32_t)r * 128 + (uint32_t)((c ^ (r & 7)) << 4);
            CP_ASYNC16(base + OFF_A + sw,
                       A + (size_t)(m0 + r) * DMODEL + kt * BKC + c * 8);
        }
#pragma unroll
        for (int i = 0; i < 8; i++) {
            const int idx = tid + i * 256;
            const int r = idx >> 3, c = idx & 7;
            const uint32_t sw = (uint32_t)r * 128 + (uint32_t)((c ^ (r & 7)) << 4);
            CP_ASYNC16(base + OFF_B + sw,
                       B + (size_t)(n0 + r) * DMODEL + kt * BKC + c * 8);
        }
        CP_COMMIT();
    };

    float acc[4][8][4];
#pragma unroll
    for (int mi = 0; mi < 4; mi++)
#pragma unroll
        for (int ni = 0; ni < 8; ni++)
#pragma unroll
            for (int q = 0; q < 4; q++) acc[mi][ni][q] = 0.0f;

    const int a_row_in16 = lane & 15;
    const int a_half     = lane >> 4;
    const int b_row_in16 = (lane & 7) + ((lane >> 4) << 3);
    const int b_half     = (lane >> 3) & 1;

    load_stage(0, 0);

    for (int kt = 0; kt < NC; kt++) {
        const int cur = kt & 1;
        if (kt + 1 < NC) {
            load_stage(kt + 1, cur ^ 1);
            CP_WAIT(1);
        } else {
            CP_WAIT(0);
        }
        __syncthreads();

        const uint32_t base = sb + cur * STAGE_BYTES;

#pragma unroll
        for (int kk = 0; kk < 4; kk++) {
            uint32_t ah[4][4];
#pragma unroll
            for (int mi = 0; mi < 4; mi++) {
                const int row = wm * 64 + mi * 16 + a_row_in16;
                const int ch  = kk * 2 + a_half;
                const uint32_t addr = (uint32_t)row * 128 + (uint32_t)((ch ^ (row & 7)) << 4);
                LDSM4(ah[mi][0], ah[mi][1], ah[mi][2], ah[mi][3], base + OFF_A + addr);
            }
#pragma unroll
            for (int p = 0; p < 4; p++) {
                uint32_t bf[2][2];
                const int row = wn * 64 + p * 16 + b_row_in16;
                const int ch  = kk * 2 + b_half;
                const uint32_t addr = (uint32_t)row * 128 + (uint32_t)((ch ^ (row & 7)) << 4);
                LDSM4(bf[0][0], bf[0][1], bf[1][0], bf[1][1], base + OFF_B + addr);
#pragma unroll
                for (int mi = 0; mi < 4; mi++)
#pragma unroll
                    for (int q = 0; q < 2; q++)
                        MMA_F16(acc[mi][2 * p + q], ah[mi], bf[q]);
            }
        }
        __syncthreads();
    }

    const int g  = lane >> 2;
    const int cc = (lane & 3) * 2;
    if (Ch) {
#pragma unroll
        for (int mi = 0; mi < 4; mi++) {
            const int row = m0 + wm * 64 + mi * 16 + g;
#pragma unroll
            for (int ni = 0; ni < 8; ni++) {
                __half* p = Ch + (size_t)row * DMODEL + n0 + wn * 64 + ni * 8 + cc;
                *(__half2*)p = __floats2half2_rn(acc[mi][ni][0] * scale, acc[mi][ni][1] * scale);
                *(__half2*)(p + 8 * DMODEL) =
                    __floats2half2_rn(acc[mi][ni][2] * scale, acc[mi][ni][3] * scale);
            }
        }
    } else {
#pragma unroll
        for (int mi = 0; mi < 4; mi++) {
            const int row = m0 + wm * 64 + mi * 16 + g;
#pragma unroll
            for (int ni = 0; ni < 8; ni++) {
                float* p = Cf + (size_t)row * DMODEL + n0 + wn * 64 + ni * 8 + cc;
                *(float2*)p = make_float2(acc[mi][ni][0], acc[mi][ni][1]);
                *(float2*)(p + 8 * DMODEL) = make_float2(acc[mi][ni][2], acc[mi][ni][3]);
            }
        }
    }
}

// ---------------------------------------------------------------------------
// Attention on mma.sync: one CTA per (b,h), 128 threads (4 warps).
// Q pre-scaled by ATT_SCALE. S = Q@K^T (HMMA) -> in-register softmax ->
// S-accum fragments reused directly as P A-operands -> P@V with V via
// ldmatrix.trans. Row masking omitted (redundant with the residual gate).
// ---------------------------------------------------------------------------
#define ATT_SMEM (3 * 8192)

__global__ __launch_bounds__(128) void attn_mma(const __half* __restrict__ Qf,
                                                const __half* __restrict__ Kf,
                                                const __half* __restrict__ Vf,
                                                __half* __restrict__ AOf) {
    const int h = blockIdx.x;
    const int b = blockIdx.y;
    const int t = threadIdx.x;
    const int w = t >> 5;
    const int lane = t & 31;

    __shared__ __align__(128) char sm[ATT_SMEM];
    const uint32_t sQ = smem_u32(sm);
    const uint32_t sK = sQ + 8192;
    const uint32_t sV = sQ + 16384;

    const size_t gbase = (size_t)b * SEQLEN * DMODEL + h * DHEAD;

    // Load Q,K,V tiles (64 rows x 64 fp16 = 8KB each), swizzled
    for (int idx = t; idx < 512; idx += 128) {
        const int r = idx >> 3, c = idx & 7;
        const uint32_t sw = (uint32_t)r * 128 + (uint32_t)((c ^ (r & 7)) << 4);
        const size_t go = gbase + (size_t)r * DMODEL + c * 8;
        CP_ASYNC16(sQ + sw, Qf + go);
        CP_ASYNC16(sK + sw, Kf + go);
        CP_ASYNC16(sV + sw, Vf + go);
    }
    CP_COMMIT();
    CP_WAIT(0);
    __syncthreads();

    // ---- S = Q @ K^T : warp w covers rows 16w..16w+15, all 64 cols ----
    float s[8][4];
#pragma unroll
    for (int j = 0; j < 8; j++)
#pragma unroll
        for (int q = 0; q < 4; q++) s[j][q] = 0.0f;

    const int a_row = w * 16 + (lane & 15);
    const int a_half = lane >> 4;
    const int b_row_in16 = (lane & 7) + ((lane >> 4) << 3);
    const int b_half = (lane >> 3) & 1;

#pragma unroll
    for (int g = 0; g < 4; g++) {
        uint32_t aq[4];
        {
            const int ch = 2 * g + a_half;
            const uint32_t addr = (uint32_t)a_row * 128 + (uint32_t)((ch ^ (a_row & 7)) << 4);
            LDSM4(aq[0], aq[1], aq[2], aq[3], sQ + addr);
        }
#pragma unroll
        for (int p = 0; p < 4; p++) {
            uint32_t bk[2][2];
            const int row = p * 16 + b_row_in16;
            const int ch  = 2 * g + b_half;
            const uint32_t addr = (uint32_t)row * 128 + (uint32_t)((ch ^ (row & 7)) << 4);
            LDSM4(bk[0][0], bk[0][1], bk[1][0], bk[1][1], sK + addr);
            MMA_F16(s[2 * p],     aq, bk[0]);
            MMA_F16(s[2 * p + 1], aq, bk[1]);
        }
    }

    // ---- softmax over the 64 columns, rows r0 = lane>>2 and r0+8 ----
    float mx0 = -1e30f, mx1 = -1e30f;
#pragma unroll
    for (int j = 0; j < 8; j++) {
        mx0 = fmaxf(mx0, fmaxf(s[j][0], s[j][1]));
        mx1 = fmaxf(mx1, fmaxf(s[j][2], s[j][3]));
    }
#pragma unroll
    for (int d = 1; d <= 2; d <<= 1) {
        mx0 = fmaxf(mx0, __shfl_xor_sync(0xFFFFFFFFu, mx0, d));
        mx1 = fmaxf(mx1, __shfl_xor_sync(0xFFFFFFFFu, mx1, d));
    }
    float sm0 = 0.0f, sm1 = 0.0f;
#pragma unroll
    for (int j = 0; j < 8; j++) {
        s[j][0] = __expf(s[j][0] - mx0); sm0 += s[j][0];
        s[j][1] = __expf(s[j][1] - mx0); sm0 += s[j][1];
        s[j][2] = __expf(s[j][2] - mx1); sm1 += s[j][2];
        s[j][3] = __expf(s[j][3] - mx1); sm1 += s[j][3];
    }
#pragma unroll
    for (int d = 1; d <= 2; d <<= 1) {
        sm0 += __shfl_xor_sync(0xFFFFFFFFu, sm0, d);
        sm1 += __shfl_xor_sync(0xFFFFFFFFu, sm1, d);
    }
    const float inv0 = 1.0f / sm0;
    const float inv1 = 1.0f / sm1;

    // P fragments (fp16): tile j -> ph[j] (row r0), pl[j] (row r0+8)
    uint32_t ph[8], pl[8];
#pragma unroll
    for (int j = 0; j < 8; j++) {
        ph[j] = h2u(__floats2half2_rn(s[j][0] * inv0, s[j][1] * inv0));
        pl[j] = h2u(__floats2half2_rn(s[j][2] * inv1, s[j][3] * inv1));
    }

    // ---- O = P @ V ----
    float o[8][4];
#pragma unroll
    for (int j = 0; j < 8; j++)
#pragma unroll
        for (int q = 0; q < 4; q++) o[j][q] = 0.0f;

    const int v_row_in16 = (lane & 7) + 8 * ((lane >> 3) & 1);  // k within group
    const int v_col8     = 8 * (lane >> 4);                     // n offset 0/8

#pragma unroll
    for (int g = 0; g < 4; g++) {
        // A operand for k-group g: S-accum tiles 2g, 2g+1
        uint32_t ap[4] = { ph[2 * g], pl[2 * g], ph[2 * g + 1], pl[2 * g + 1] };
#pragma unroll
        for (int q = 0; q < 4; q++) {        // n-pair q: n-tiles 2q, 2q+1
            uint32_t bv[2][2];
            const int row = 16 * g + v_row_in16;
            const int col = 16 * q + v_col8;
            const uint32_t addr = (uint32_t)row * 128 +
                                  (uint32_t)(((col >> 3) ^ (row & 7)) << 4);
            LDSM4T(bv[0][0], bv[0][1], bv[1][0], bv[1][1], sV + addr);
            MMA_F16(o[2 * q],     ap, bv[0]);
            MMA_F16(o[2 * q + 1], ap, bv[1]);
        }
    }

    // ---- store fp16 attn out ----
    const int r0 = lane >> 2;
    const int cc = (lane & 3) * 2;
#pragma unroll
    for (int j = 0; j < 8; j++) {
        __half* p = AOf + gbase + (size_t)(w * 16 + r0) * DMODEL + j * 8 + cc;
        *(__half2*)p = __floats2half2_rn(o[j][0], o[j][1]);
        *(__half2*)(p + 8 * DMODEL) = __floats2half2_rn(o[j][2], o[j][3]);
    }
}

// ---------------------------------------------------------------------------
// Gated residual + LayerNorm
// ---------------------------------------------------------------------------
__global__ __launch_bounds__(256) void resid_ln(const float* __restrict__ hidden,
                                                const float* __restrict__ proj,
                                                const unsigned* __restrict__ mask,
                                                const float* __restrict__ gamma,
                                                const float* __restrict__ beta,
                                                float* __restrict__ out) {
    const int r = blockIdx.x;
    const int t = threadIdx.x;
    const size_t base = (size_t)r * DMODEL + t * 4;

    const float act = (mask[r] != 0u) ? 1.0f : 0.0f;
    const float4 hv = *(const float4*)(hidden + base);
    const float4 ov = *(const float4*)(proj + base);

    float4 f;
    f.x = hv.x + act * ov.x;
    f.y = hv.y + act * ov.y;
    f.z = hv.z + act * ov.z;
    f.w = hv.w + act * ov.w;

    float s  = f.x + f.y + f.z + f.w;
    float s2 = f.x * f.x + f.y * f.y + f.z * f.z + f.w * f.w;

#pragma unroll
    for (int d = 16; d; d >>= 1) {
        s  += __shfl_xor_sync(0xFFFFFFFFu, s,  d);
        s2 += __shfl_xor_sync(0xFFFFFFFFu, s2, d);
    }

    __shared__ float ws[8], ws2[8];
    const int warp = t >> 5, lane = t & 31;
    if (lane == 0) { ws[warp] = s; ws2[warp] = s2; }
    __syncthreads();

    float ts = 0.0f, ts2 = 0.0f;
#pragma unroll
    for (int i = 0; i < 8; i++) { ts += ws[i]; ts2 += ws2[i]; }

    const float mu  = ts * (1.0f / DMODEL);
    const float var = ts2 * (1.0f / DMODEL) - mu * mu;
    const float rs  = rsqrtf(var + LN_EPS);

    const float4 gv = *(const float4*)(gamma + t * 4);
    const float4 bv = *(const float4*)(beta  + t * 4);

    float4 r4;
    r4.x = (f.x - mu) * rs * gv.x + bv.x;
    r4.y = (f.y - mu) * rs * gv.y + bv.y;
    r4.z = (f.z - mu) * rs * gv.z + bv.z;
    r4.w = (f.w - mu) * rs * gv.w + bv.w;
    *(float4*)(out + base) = r4;
}

// ---------------------------------------------------------------------------
// Launch
// ---------------------------------------------------------------------------
extern "C" void kernel_launch(void* const* d_in, const int* in_sizes, int n_in,
                              void* d_out, int out_size) {
    const float*    hidden = (const float*)d_in[0];
    const unsigned* mask   = (const unsigned*)d_in[1];
    const float*    W[4]   = {(const float*)d_in[2], (const float*)d_in[3],
                              (const float*)d_in[4], (const float*)d_in[5]};
    const float*    gamma  = (const float*)d_in[6];
    const float*    beta   = (const float*)d_in[7];
    float*          out    = (float*)d_out;

    float *Os;
    __half *Qf, *Kf, *Vf, *hf, *aof, *wf;
    cudaGetSymbolAddress((void**)&Qf,  g_Qf);
    cudaGetSymbolAddress((void**)&Kf,  g_Kf);
    cudaGetSymbolAddress((void**)&Vf,  g_Vf);
    cudaGetSymbolAddress((void**)&Os,  g_O);
    cudaGetSymbolAddress((void**)&hf,  g_hf);
    cudaGetSymbolAddress((void**)&aof, g_aof);
    cudaGetSymbolAddress((void**)&wf,  g_wf);

    cudaFuncSetAttribute(gemm_mma, cudaFuncAttributeMaxDynamicSharedMemorySize, GEMM_SMEM);

    // Conversions
    const int n4h = MTOT * DMODEL / 4;
    cvt_f16<<<n4h / 256, 256>>>((const float4*)hidden, (uint2*)hf, n4h);
    const int n4w = DMODEL * DMODEL / 4;
    for (int i = 0; i < 4; i++)
        cvt_f16<<<n4w / 256, 256>>>((const float4*)W[i],
                                    (uint2*)(wf + (size_t)i * DMODEL * DMODEL), n4w);

    const dim3 gg(DMODEL / BN, MTOT / BM);   // (4, 128)
    // QKV projections -> fp16 (Q pre-scaled by ATT_SCALE)
    gemm_mma<<<gg, 256, GEMM_SMEM>>>(hf, wf + 0 * (size_t)DMODEL * DMODEL,
                                     nullptr, Qf, ATT_SCALE);
    gemm_mma<<<gg, 256, GEMM_SMEM>>>(hf, wf + 1 * (size_t)DMODEL * DMODEL,
                                     nullptr, Kf, 1.0f);
    gemm_mma<<<gg, 256, GEMM_SMEM>>>(hf, wf + 2 * (size_t)DMODEL * DMODEL,
                                     nullptr, Vf, 1.0f);

    attn_mma<<<dim3(NHEAD, BATCH), 128>>>(Qf, Kf, Vf, aof);

    // O projection -> fp32
    gemm_mma<<<gg, 256, GEMM_SMEM>>>(aof, wf + 3 * (size_t)DMODEL * DMODEL,
                                     Os, nullptr, 1.0f);

    resid_ln<<<MTOT, 256>>>(hidden, Os, mask, gamma, beta, out);
}

// round 8
// speedup vs baseline: 6.9988x; 1.0546x over previous
#include <cuda_runtime.h>
#include <cuda_fp16.h>
#include <cstdint>

// ---------------------------------------------------------------------------
// Problem constants
// ---------------------------------------------------------------------------
#define MTOT   16384      // B*K
#define DMODEL 1024
#define NHEAD  16
#define DHEAD  64
#define BATCH  256
#define SEQLEN 64
#define ATT_SCALE 0.125f
#define LN_EPS 1e-5f

// ---------------------------------------------------------------------------
// Scratch (device globals: the allowed no-alloc workaround)
// ---------------------------------------------------------------------------
__device__ __half g_Qf [MTOT * DMODEL];          // Q (pre-scaled) fp16
__device__ __half g_Kf [MTOT * DMODEL];          // K fp16
__device__ __half g_Vf [MTOT * DMODEL];          // V fp16
__device__ float  g_O  [MTOT * DMODEL];          // O projection fp32
__device__ __half g_hf [MTOT * DMODEL];          // hidden fp16
__device__ __half g_aof[MTOT * DMODEL];          // attn out fp16
__device__ __half g_wf [4][DMODEL * DMODEL];     // Wq,Wk,Wv,Wo fp16 (contiguous)

// ---------------------------------------------------------------------------
// Baseline-PTX helpers (harness compiles via compute_103: no tcgen05)
// ---------------------------------------------------------------------------
__device__ __forceinline__ uint32_t smem_u32(const void* p) {
    uint32_t a;
    asm("{ .reg .u64 t; cvta.to.shared.u64 t, %1; cvt.u32.u64 %0, t; }"
        : "=r"(a) : "l"(p));
    return a;
}

#define CP_ASYNC16(dst, src) \
    asm volatile("cp.async.cg.shared.global [%0], [%1], 16;" :: "r"(dst), "l"(src))
#define CP_COMMIT() asm volatile("cp.async.commit_group;" ::: "memory")
#define CP_WAIT(n)  asm volatile("cp.async.wait_group %0;" :: "n"(n) : "memory")

#define LDSM4(r0, r1, r2, r3, addr) \
    asm volatile("ldmatrix.sync.aligned.m8n8.x4.shared.b16 {%0,%1,%2,%3}, [%4];" \
                 : "=r"(r0), "=r"(r1), "=r"(r2), "=r"(r3) : "r"(addr))

#define LDSM4T(r0, r1, r2, r3, addr) \
    asm volatile("ldmatrix.sync.aligned.m8n8.x4.trans.shared.b16 {%0,%1,%2,%3}, [%4];" \
                 : "=r"(r0), "=r"(r1), "=r"(r2), "=r"(r3) : "r"(addr))

#define MMA_F16(d, a, b) \
    asm volatile("mma.sync.aligned.m16n8k16.row.col.f32.f16.f16.f32 " \
                 "{%0,%1,%2,%3},{%4,%5,%6,%7},{%8,%9},{%0,%1,%2,%3};" \
                 : "+f"((d)[0]), "+f"((d)[1]), "+f"((d)[2]), "+f"((d)[3]) \
                 : "r"((a)[0]), "r"((a)[1]), "r"((a)[2]), "r"((a)[3]), \
                   "r"((b)[0]), "r"((b)[1]))

__device__ __forceinline__ uint32_t h2u(__half2 h) {
    return *reinterpret_cast<uint32_t*>(&h);
}

// ---------------------------------------------------------------------------
// fp32 -> fp16 conversions
// ---------------------------------------------------------------------------
__global__ __launch_bounds__(256) void cvt_f16(const float4* __restrict__ in,
                                               uint2* __restrict__ out16, int n4) {
    int i = blockIdx.x * 256 + threadIdx.x;
    if (i >= n4) return;
    float4 v = in[i];
    __half2 p0 = __floats2half2_rn(v.x, v.y);
    __half2 p1 = __floats2half2_rn(v.z, v.w);
    out16[i] = make_uint2(h2u(p0), h2u(p1));
}

// all four weights in one launch (each 1024x1024 = 262144 float4)
__global__ __launch_bounds__(256) void cvt_w4(const float4* __restrict__ w0,
                                              const float4* __restrict__ w1,
                                              const float4* __restrict__ w2,
                                              const float4* __restrict__ w3,
                                              uint2* __restrict__ out16) {
    const int i = blockIdx.x * 256 + threadIdx.x;   // 0 .. 4*262144-1
    const int w = i >> 18;
    const int j = i & 262143;
    const float4* src = (w == 0) ? w0 : (w == 1) ? w1 : (w == 2) ? w2 : w3;
    float4 v = src[j];
    __half2 p0 = __floats2half2_rn(v.x, v.y);
    __half2 p1 = __floats2half2_rn(v.z, v.w);
    out16[i] = make_uint2(h2u(p0), h2u(p1));
}

// ---------------------------------------------------------------------------
// mma.sync fp16 GEMM (NT): C[m,n] = sum_k A[m,k] * B[n,k], fp32 accum.
// BM=128, BN=256, BK=64, cp.async 3-stage pipeline, 8-chunk XOR swizzle,
// 8 warps = 2(M) x 4(N), warp tile 64x64.
// MODE 0: fp32 out to Cf (N=1024 grid).
// MODE 1: fused QKV, N=3072; out fp16 to Qf/Kf/Vf by n-range, Q scaled.
// ---------------------------------------------------------------------------
#define BM 128
#define BN 256
#define BKC 64
#define NC (DMODEL / BKC)        // 16 k-chunks
#define A_BYTES (128 * 128)
#define B_BYTES (256 * 128)
#define OFF_A 0
#define OFF_B A_BYTES
#define STAGE_BYTES (A_BYTES + B_BYTES)   // 49152
#define NSTAGE 3
#define GEMM_SMEM (NSTAGE * STAGE_BYTES)  // 147456

template <int MODE>
__global__ __launch_bounds__(256, 1) void gemm_mma(
    const __half* __restrict__ A, const __half* __restrict__ B,
    float* __restrict__ Cf,
    __half* __restrict__ Q, __half* __restrict__ Kk, __half* __restrict__ V)
{
    extern __shared__ char smem[];
    const uint32_t sb = smem_u32(smem);

    const int tid  = threadIdx.x;
    const int wid  = tid >> 5;
    const int lane = tid & 31;
    const int wm   = wid & 1;
    const int wn   = wid >> 1;
    const int m0   = blockIdx.y * BM;
    const int n0   = blockIdx.x * BN;

    auto load_stage = [&](int kt, int stg) {
        const uint32_t base = sb + stg * STAGE_BYTES;
#pragma unroll
        for (int i = 0; i < 4; i++) {
            const int idx = tid + i * 256;
            const int r = idx >> 3, c = idx & 7;
            const uint32_t sw = (uint32_t)r * 128 + (uint32_t)((c ^ (r & 7)) << 4);
            CP_ASYNC16(base + OFF_A + sw,
                       A + (size_t)(m0 + r) * DMODEL + kt * BKC + c * 8);
        }
#pragma unroll
        for (int i = 0; i < 8; i++) {
            const int idx = tid + i * 256;
            const int r = idx >> 3, c = idx & 7;
            const uint32_t sw = (uint32_t)r * 128 + (uint32_t)((c ^ (r & 7)) << 4);
            CP_ASYNC16(base + OFF_B + sw,
                       B + (size_t)(n0 + r) * DMODEL + kt * BKC + c * 8);
        }
        CP_COMMIT();
    };

    float acc[4][8][4];
#pragma unroll
    for (int mi = 0; mi < 4; mi++)
#pragma unroll
        for (int ni = 0; ni < 8; ni++)
#pragma unroll
            for (int q = 0; q < 4; q++) acc[mi][ni][q] = 0.0f;

    const int a_row_in16 = lane & 15;
    const int a_half     = lane >> 4;
    const int b_row_in16 = (lane & 7) + ((lane >> 4) << 3);
    const int b_half     = (lane >> 3) & 1;

    load_stage(0, 0);
    load_stage(1, 1);

    for (int kt = 0; kt < NC; kt++) {
        if (kt < NC - 1) { CP_WAIT(1); } else { CP_WAIT(0); }
        __syncthreads();

        if (kt + 2 < NC) load_stage(kt + 2, (kt + 2) % NSTAGE);

        const uint32_t base = sb + (kt % NSTAGE) * STAGE_BYTES;

#pragma unroll
        for (int kk = 0; kk < 4; kk++) {
            uint32_t ah[4][4];
#pragma unroll
            for (int mi = 0; mi < 4; mi++) {
                const int row = wm * 64 + mi * 16 + a_row_in16;
                const int ch  = kk * 2 + a_half;
                const uint32_t addr = (uint32_t)row * 128 + (uint32_t)((ch ^ (row & 7)) << 4);
                LDSM4(ah[mi][0], ah[mi][1], ah[mi][2], ah[mi][3], base + OFF_A + addr);
            }
#pragma unroll
            for (int p = 0; p < 4; p++) {
                uint32_t bf[2][2];
                const int row = wn * 64 + p * 16 + b_row_in16;
                const int ch  = kk * 2 + b_half;
                const uint32_t addr = (uint32_t)row * 128 + (uint32_t)((ch ^ (row & 7)) << 4);
                LDSM4(bf[0][0], bf[0][1], bf[1][0], bf[1][1], base + OFF_B + addr);
#pragma unroll
                for (int mi = 0; mi < 4; mi++)
#pragma unroll
                    for (int q = 0; q < 2; q++)
                        MMA_F16(acc[mi][2 * p + q], ah[mi], bf[q]);
            }
        }
    }

    const int g  = lane >> 2;
    const int cc = (lane & 3) * 2;
    if (MODE == 1) {
        const int widx = n0 >> 10;          // 0=Q, 1=K, 2=V
        const int col0 = n0 & 1023;
        __half* Ch = (widx == 0) ? Q : (widx == 1) ? Kk : V;
        const float scale = (widx == 0) ? ATT_SCALE : 1.0f;
#pragma unroll
        for (int mi = 0; mi < 4; mi++) {
            const int row = m0 + wm * 64 + mi * 16 + g;
#pragma unroll
            for (int ni = 0; ni < 8; ni++) {
                __half* p = Ch + (size_t)row * DMODEL + col0 + wn * 64 + ni * 8 + cc;
                *(__half2*)p = __floats2half2_rn(acc[mi][ni][0] * scale,
                                                 acc[mi][ni][1] * scale);
                *(__half2*)(p + 8 * DMODEL) =
                    __floats2half2_rn(acc[mi][ni][2] * scale, acc[mi][ni][3] * scale);
            }
        }
    } else {
#pragma unroll
        for (int mi = 0; mi < 4; mi++) {
            const int row = m0 + wm * 64 + mi * 16 + g;
#pragma unroll
            for (int ni = 0; ni < 8; ni++) {
                float* p = Cf + (size_t)row * DMODEL + n0 + wn * 64 + ni * 8 + cc;
                *(float2*)p = make_float2(acc[mi][ni][0], acc[mi][ni][1]);
                *(float2*)(p + 8 * DMODEL) = make_float2(acc[mi][ni][2], acc[mi][ni][3]);
            }
        }
    }
}

// ---------------------------------------------------------------------------
// Attention on mma.sync: one CTA per (b,h), 128 threads (4 warps).
// Q pre-scaled by ATT_SCALE. S = Q@K^T -> in-register softmax -> P@V with
// V via ldmatrix.trans. Row masking omitted (redundant with the gate).
// ---------------------------------------------------------------------------
#define ATT_SMEM (3 * 8192)

__global__ __launch_bounds__(128) void attn_mma(const __half* __restrict__ Qf,
                                                const __half* __restrict__ Kf,
                                                const __half* __restrict__ Vf,
                                                __half* __restrict__ AOf) {
    const int h = blockIdx.x;
    const int b = blockIdx.y;
    const int t = threadIdx.x;
    const int w = t >> 5;
    const int lane = t & 31;

    __shared__ __align__(128) char sm[ATT_SMEM];
    const uint32_t sQ = smem_u32(sm);
    const uint32_t sK = sQ + 8192;
    const uint32_t sV = sQ + 16384;

    const size_t gbase = (size_t)b * SEQLEN * DMODEL + h * DHEAD;

    for (int idx = t; idx < 512; idx += 128) {
        const int r = idx >> 3, c = idx & 7;
        const uint32_t sw = (uint32_t)r * 128 + (uint32_t)((c ^ (r & 7)) << 4);
        const size_t go = gbase + (size_t)r * DMODEL + c * 8;
        CP_ASYNC16(sQ + sw, Qf + go);
        CP_ASYNC16(sK + sw, Kf + go);
        CP_ASYNC16(sV + sw, Vf + go);
    }
    CP_COMMIT();
    CP_WAIT(0);
    __syncthreads();

    float s[8][4];
#pragma unroll
    for (int j = 0; j < 8; j++)
#pragma unroll
        for (int q = 0; q < 4; q++) s[j][q] = 0.0f;

    const int a_row = w * 16 + (lane & 15);
    const int a_half = lane >> 4;
    const int b_row_in16 = (lane & 7) + ((lane >> 4) << 3);
    const int b_half = (lane >> 3) & 1;

#pragma unroll
    for (int g = 0; g < 4; g++) {
        uint32_t aq[4];
        {
            const int ch = 2 * g + a_half;
            const uint32_t addr = (uint32_t)a_row * 128 + (uint32_t)((ch ^ (a_row & 7)) << 4);
            LDSM4(aq[0], aq[1], aq[2], aq[3], sQ + addr);
        }
#pragma unroll
        for (int p = 0; p < 4; p++) {
            uint32_t bk[2][2];
            const int row = p * 16 + b_row_in16;
            const int ch  = 2 * g + b_half;
            const uint32_t addr = (uint32_t)row * 128 + (uint32_t)((ch ^ (row & 7)) << 4);
            LDSM4(bk[0][0], bk[0][1], bk[1][0], bk[1][1], sK + addr);
            MMA_F16(s[2 * p],     aq, bk[0]);
            MMA_F16(s[2 * p + 1], aq, bk[1]);
        }
    }

    float mx0 = -1e30f, mx1 = -1e30f;
#pragma unroll
    for (int j = 0; j < 8; j++) {
        mx0 = fmaxf(mx0, fmaxf(s[j][0], s[j][1]));
        mx1 = fmaxf(mx1, fmaxf(s[j][2], s[j][3]));
    }
#pragma unroll
    for (int d = 1; d <= 2; d <<= 1) {
        mx0 = fmaxf(mx0, __shfl_xor_sync(0xFFFFFFFFu, mx0, d));
        mx1 = fmaxf(mx1, __shfl_xor_sync(0xFFFFFFFFu, mx1, d));
    }
    float sm0 = 0.0f, sm1 = 0.0f;
#pragma unroll
    for (int j = 0; j < 8; j++) {
        s[j][0] = __expf(s[j][0] - mx0); sm0 += s[j][0];
        s[j][1] = __expf(s[j][1] - mx0); sm0 += s[j][1];
        s[j][2] = __expf(s[j][2] - mx1); sm1 += s[j][2];
        s[j][3] = __expf(s[j][3] - mx1); sm1 += s[j][3];
    }
#pragma unroll
    for (int d = 1; d <= 2; d <<= 1) {
        sm0 += __shfl_xor_sync(0xFFFFFFFFu, sm0, d);
        sm1 += __shfl_xor_sync(0xFFFFFFFFu, sm1, d);
    }
    const float inv0 = 1.0f / sm0;
    const float inv1 = 1.0f / sm1;

    uint32_t ph[8], pl[8];
#pragma unroll
    for (int j = 0; j < 8; j++) {
        ph[j] = h2u(__floats2half2_rn(s[j][0] * inv0, s[j][1] * inv0));
        pl[j] = h2u(__floats2half2_rn(s[j][2] * inv1, s[j][3] * inv1));
    }

    float o[8][4];
#pragma unroll
    for (int j = 0; j < 8; j++)
#pragma unroll
        for (int q = 0; q < 4; q++) o[j][q] = 0.0f;

    const int v_row_in16 = (lane & 7) + 8 * ((lane >> 3) & 1);
    const int v_col8     = 8 * (lane >> 4);

#pragma unroll
    for (int g = 0; g < 4; g++) {
        uint32_t ap[4] = { ph[2 * g], pl[2 * g], ph[2 * g + 1], pl[2 * g + 1] };
#pragma unroll
        for (int q = 0; q < 4; q++) {
            uint32_t bv[2][2];
            const int row = 16 * g + v_row_in16;
            const int col = 16 * q + v_col8;
            const uint32_t addr = (uint32_t)row * 128 +
                                  (uint32_t)(((col >> 3) ^ (row & 7)) << 4);
            LDSM4T(bv[0][0], bv[0][1], bv[1][0], bv[1][1], sV + addr);
            MMA_F16(o[2 * q],     ap, bv[0]);
            MMA_F16(o[2 * q + 1], ap, bv[1]);
        }
    }

    const int r0 = lane >> 2;
    const int cc = (lane & 3) * 2;
#pragma unroll
    for (int j = 0; j < 8; j++) {
        __half* p = AOf + gbase + (size_t)(w * 16 + r0) * DMODEL + j * 8 + cc;
        *(__half2*)p = __floats2half2_rn(o[j][0], o[j][1]);
        *(__half2*)(p + 8 * DMODEL) = __floats2half2_rn(o[j][2], o[j][3]);
    }
}

// ---------------------------------------------------------------------------
// Gated residual + LayerNorm
// ---------------------------------------------------------------------------
__global__ __launch_bounds__(256) void resid_ln(const float* __restrict__ hidden,
                                                const float* __restrict__ proj,
                                                const unsigned* __restrict__ mask,
                                                const float* __restrict__ gamma,
                                                const float* __restrict__ beta,
                                                float* __restrict__ out) {
    const int r = blockIdx.x;
    const int t = threadIdx.x;
    const size_t base = (size_t)r * DMODEL + t * 4;

    const float act = (mask[r] != 0u) ? 1.0f : 0.0f;
    const float4 hv = *(const float4*)(hidden + base);
    const float4 ov = *(const float4*)(proj + base);

    float4 f;
    f.x = hv.x + act * ov.x;
    f.y = hv.y + act * ov.y;
    f.z = hv.z + act * ov.z;
    f.w = hv.w + act * ov.w;

    float s  = f.x + f.y + f.z + f.w;
    float s2 = f.x * f.x + f.y * f.y + f.z * f.z + f.w * f.w;

#pragma unroll
    for (int d = 16; d; d >>= 1) {
        s  += __shfl_xor_sync(0xFFFFFFFFu, s,  d);
        s2 += __shfl_xor_sync(0xFFFFFFFFu, s2, d);
    }

    __shared__ float ws[8], ws2[8];
    const int warp = t >> 5, lane = t & 31;
    if (lane == 0) { ws[warp] = s; ws2[warp] = s2; }
    __syncthreads();

    float ts = 0.0f, ts2 = 0.0f;
#pragma unroll
    for (int i = 0; i < 8; i++) { ts += ws[i]; ts2 += ws2[i]; }

    const float mu  = ts * (1.0f / DMODEL);
    const float var = ts2 * (1.0f / DMODEL) - mu * mu;
    const float rs  = rsqrtf(var + LN_EPS);

    const float4 gv = *(const float4*)(gamma + t * 4);
    const float4 bv = *(const float4*)(beta  + t * 4);

    float4 r4;
    r4.x = (f.x - mu) * rs * gv.x + bv.x;
    r4.y = (f.y - mu) * rs * gv.y + bv.y;
    r4.z = (f.z - mu) * rs * gv.z + bv.z;
    r4.w = (f.w - mu) * rs * gv.w + bv.w;
    *(float4*)(out + base) = r4;
}

// ---------------------------------------------------------------------------
// Launch
// ---------------------------------------------------------------------------
extern "C" void kernel_launch(void* const* d_in, const int* in_sizes, int n_in,
                              void* d_out, int out_size) {
    const float*    hidden = (const float*)d_in[0];
    const unsigned* mask   = (const unsigned*)d_in[1];
    const float*    W[4]   = {(const float*)d_in[2], (const float*)d_in[3],
                              (const float*)d_in[4], (const float*)d_in[5]};
    const float*    gamma  = (const float*)d_in[6];
    const float*    beta   = (const float*)d_in[7];
    float*          out    = (float*)d_out;

    float *Os;
    __half *Qf, *Kf, *Vf, *hf, *aof, *wf;
    cudaGetSymbolAddress((void**)&Qf,  g_Qf);
    cudaGetSymbolAddress((void**)&Kf,  g_Kf);
    cudaGetSymbolAddress((void**)&Vf,  g_Vf);
    cudaGetSymbolAddress((void**)&Os,  g_O);
    cudaGetSymbolAddress((void**)&hf,  g_hf);
    cudaGetSymbolAddress((void**)&aof, g_aof);
    cudaGetSymbolAddress((void**)&wf,  g_wf);

    cudaFuncSetAttribute(gemm_mma<0>, cudaFuncAttributeMaxDynamicSharedMemorySize, GEMM_SMEM);
    cudaFuncSetAttribute(gemm_mma<1>, cudaFuncAttributeMaxDynamicSharedMemorySize, GEMM_SMEM);

    // Conversions (hidden + all 4 weights in 2 launches)
    const int n4h = MTOT * DMODEL / 4;
    cvt_f16<<<n4h / 256, 256>>>((const float4*)hidden, (uint2*)hf, n4h);
    cvt_w4<<<4 * (DMODEL * DMODEL / 4) / 256, 256>>>(
        (const float4*)W[0], (const float4*)W[1],
        (const float4*)W[2], (const float4*)W[3], (uint2*)wf);

    // Fused QKV projection (N = 3072)
    gemm_mma<1><<<dim3(3 * DMODEL / BN, MTOT / BM), 256, GEMM_SMEM>>>(
        hf, wf, nullptr, Qf, Kf, Vf);

    attn_mma<<<dim3(NHEAD, BATCH), 128>>>(Qf, Kf, Vf, aof);

    // O projection -> fp32
    gemm_mma<0><<<dim3(DMODEL / BN, MTOT / BM), 256, GEMM_SMEM>>>(
        aof, wf + 3 * (size_t)DMODEL * DMODEL, Os, nullptr, nullptr, nullptr);

    resid_ln<<<MTOT, 256>>>(hidden, Os, mask, gamma, beta, out);
}

// round 9
// speedup vs baseline: 7.0775x; 1.0112x over previous
#include <cuda_runtime.h>
#include <cuda_fp16.h>
#include <cstdint>

// ---------------------------------------------------------------------------
// Problem constants
// ---------------------------------------------------------------------------
#define MTOT   16384      // B*K
#define DMODEL 1024
#define NHEAD  16
#define DHEAD  64
#define BATCH  256
#define SEQLEN 64
#define ATT_SCALE 0.125f
#define LN_EPS 1e-5f

// ---------------------------------------------------------------------------
// Scratch (device globals: the allowed no-alloc workaround)
// ---------------------------------------------------------------------------
__device__ __half g_Qf [MTOT * DMODEL];          // Q (pre-scaled) fp16
__device__ __half g_Kf [MTOT * DMODEL];          // K fp16
__device__ __half g_Vf [MTOT * DMODEL];          // V fp16
__device__ __half g_Of [MTOT * DMODEL];          // O projection fp16
__device__ __half g_hf [MTOT * DMODEL];          // hidden fp16
__device__ __half g_aof[MTOT * DMODEL];          // attn out fp16
__device__ __half g_wf [4][DMODEL * DMODEL];     // Wq,Wk,Wv,Wo fp16 (contiguous)

// ---------------------------------------------------------------------------
// Baseline-PTX helpers (harness compiles via compute_103: no tcgen05)
// ---------------------------------------------------------------------------
__device__ __forceinline__ uint32_t smem_u32(const void* p) {
    uint32_t a;
    asm("{ .reg .u64 t; cvta.to.shared.u64 t, %1; cvt.u32.u64 %0, t; }"
        : "=r"(a) : "l"(p));
    return a;
}

#define CP_ASYNC16(dst, src) \
    asm volatile("cp.async.cg.shared.global [%0], [%1], 16;" :: "r"(dst), "l"(src))
#define CP_COMMIT() asm volatile("cp.async.commit_group;" ::: "memory")
#define CP_WAIT(n)  asm volatile("cp.async.wait_group %0;" :: "n"(n) : "memory")

#define LDSM4(r0, r1, r2, r3, addr) \
    asm volatile("ldmatrix.sync.aligned.m8n8.x4.shared.b16 {%0,%1,%2,%3}, [%4];" \
                 : "=r"(r0), "=r"(r1), "=r"(r2), "=r"(r3) : "r"(addr))

#define LDSM4T(r0, r1, r2, r3, addr) \
    asm volatile("ldmatrix.sync.aligned.m8n8.x4.trans.shared.b16 {%0,%1,%2,%3}, [%4];" \
                 : "=r"(r0), "=r"(r1), "=r"(r2), "=r"(r3) : "r"(addr))

#define MMA_F16(d, a, b) \
    asm volatile("mma.sync.aligned.m16n8k16.row.col.f32.f16.f16.f32 " \
                 "{%0,%1,%2,%3},{%4,%5,%6,%7},{%8,%9},{%0,%1,%2,%3};" \
                 : "+f"((d)[0]), "+f"((d)[1]), "+f"((d)[2]), "+f"((d)[3]) \
                 : "r"((a)[0]), "r"((a)[1]), "r"((a)[2]), "r"((a)[3]), \
                   "r"((b)[0]), "r"((b)[1]))

__device__ __forceinline__ uint32_t h2u(__half2 h) {
    return *reinterpret_cast<uint32_t*>(&h);
}

// ---------------------------------------------------------------------------
// fp32 -> fp16 conversions
// ---------------------------------------------------------------------------
__global__ __launch_bounds__(256) void cvt_f16(const float4* __restrict__ in,
                                               uint2* __restrict__ out16, int n4) {
    int i = blockIdx.x * 256 + threadIdx.x;
    if (i >= n4) return;
    float4 v = in[i];
    __half2 p0 = __floats2half2_rn(v.x, v.y);
    __half2 p1 = __floats2half2_rn(v.z, v.w);
    out16[i] = make_uint2(h2u(p0), h2u(p1));
}

__global__ __launch_bounds__(256) void cvt_w4(const float4* __restrict__ w0,
                                              const float4* __restrict__ w1,
                                              const float4* __restrict__ w2,
                                              const float4* __restrict__ w3,
                                              uint2* __restrict__ out16) {
    const int i = blockIdx.x * 256 + threadIdx.x;   // 0 .. 4*262144-1
    const int w = i >> 18;
    const int j = i & 262143;
    const float4* src = (w == 0) ? w0 : (w == 1) ? w1 : (w == 2) ? w2 : w3;
    float4 v = src[j];
    __half2 p0 = __floats2half2_rn(v.x, v.y);
    __half2 p1 = __floats2half2_rn(v.z, v.w);
    out16[i] = make_uint2(h2u(p0), h2u(p1));
}

// ---------------------------------------------------------------------------
// mma.sync fp16 GEMM (NT): C[m,n] = sum_k A[m,k] * B[n,k], fp32 accum.
// BM=128, BN=256, BK=64, cp.async 3-stage pipeline, 8-chunk XOR swizzle.
// 512 threads = 16 warps = 4(M) x 4(N), warp tile 32x64 (4 warps/SMSP for
// latency hiding on the legacy HMMA pipe).
// MODE 0: fp16 out (O projection). MODE 1: fused QKV (N=3072), Q scaled.
// ---------------------------------------------------------------------------
#define BM 128
#define BN 256
#define BKC 64
#define NC (DMODEL / BKC)        // 16 k-chunks
#define A_BYTES (128 * 128)
#define B_BYTES (256 * 128)
#define OFF_A 0
#define OFF_B A_BYTES
#define STAGE_BYTES (A_BYTES + B_BYTES)   // 49152
#define NSTAGE 3
#define GEMM_SMEM (NSTAGE * STAGE_BYTES)  // 147456
#define GTHREADS 512

template <int MODE>
__global__ __launch_bounds__(GTHREADS, 1) void gemm_mma(
    const __half* __restrict__ A, const __half* __restrict__ B,
    __half* __restrict__ O,
    __half* __restrict__ Q, __half* __restrict__ Kk, __half* __restrict__ V)
{
    extern __shared__ char smem[];
    const uint32_t sb = smem_u32(smem);

    const int tid  = threadIdx.x;
    const int wid  = tid >> 5;
    const int lane = tid & 31;
    const int wm   = wid & 3;        // M offset wm*32
    const int wn   = wid >> 2;       // N offset wn*64
    const int m0   = blockIdx.y * BM;
    const int n0   = blockIdx.x * BN;

    auto load_stage = [&](int kt, int stg) {
        const uint32_t base = sb + stg * STAGE_BYTES;
#pragma unroll
        for (int i = 0; i < 2; i++) {          // A: 1024 16B-chunks
            const int idx = tid + i * GTHREADS;
            const int r = idx >> 3, c = idx & 7;
            const uint32_t sw = (uint32_t)r * 128 + (uint32_t)((c ^ (r & 7)) << 4);
            CP_ASYNC16(base + OFF_A + sw,
                       A + (size_t)(m0 + r) * DMODEL + kt * BKC + c * 8);
        }
#pragma unroll
        for (int i = 0; i < 4; i++) {          // B: 2048 16B-chunks
            const int idx = tid + i * GTHREADS;
            const int r = idx >> 3, c = idx & 7;
            const uint32_t sw = (uint32_t)r * 128 + (uint32_t)((c ^ (r & 7)) << 4);
            CP_ASYNC16(base + OFF_B + sw,
                       B + (size_t)(n0 + r) * DMODEL + kt * BKC + c * 8);
        }
        CP_COMMIT();
    };

    float acc[2][8][4];
#pragma unroll
    for (int mi = 0; mi < 2; mi++)
#pragma unroll
        for (int ni = 0; ni < 8; ni++)
#pragma unroll
            for (int q = 0; q < 4; q++) acc[mi][ni][q] = 0.0f;

    const int a_row_in16 = lane & 15;
    const int a_half     = lane >> 4;
    const int b_row_in16 = (lane & 7) + ((lane >> 4) << 3);
    const int b_half     = (lane >> 3) & 1;

    load_stage(0, 0);
    load_stage(1, 1);

    for (int kt = 0; kt < NC; kt++) {
        if (kt < NC - 1) { CP_WAIT(1); } else { CP_WAIT(0); }
        __syncthreads();

        if (kt + 2 < NC) load_stage(kt + 2, (kt + 2) % NSTAGE);

        const uint32_t base = sb + (kt % NSTAGE) * STAGE_BYTES;

#pragma unroll
        for (int kk = 0; kk < 4; kk++) {
            uint32_t ah[2][4];
#pragma unroll
            for (int mi = 0; mi < 2; mi++) {
                const int row = wm * 32 + mi * 16 + a_row_in16;
                const int ch  = kk * 2 + a_half;
                const uint32_t addr = (uint32_t)row * 128 + (uint32_t)((ch ^ (row & 7)) << 4);
                LDSM4(ah[mi][0], ah[mi][1], ah[mi][2], ah[mi][3], base + OFF_A + addr);
            }
#pragma unroll
            for (int p = 0; p < 4; p++) {
                uint32_t bf[2][2];
                const int row = wn * 64 + p * 16 + b_row_in16;
                const int ch  = kk * 2 + b_half;
                const uint32_t addr = (uint32_t)row * 128 + (uint32_t)((ch ^ (row & 7)) << 4);
                LDSM4(bf[0][0], bf[0][1], bf[1][0], bf[1][1], base + OFF_B + addr);
#pragma unroll
                for (int mi = 0; mi < 2; mi++)
#pragma unroll
                    for (int q = 0; q < 2; q++)
                        MMA_F16(acc[mi][2 * p + q], ah[mi], bf[q]);
            }
        }
    }

    const int g  = lane >> 2;
    const int cc = (lane & 3) * 2;
    if (MODE == 1) {
        const int widx = n0 >> 10;          // 0=Q, 1=K, 2=V
        const int col0 = n0 & 1023;
        __half* Ch = (widx == 0) ? Q : (widx == 1) ? Kk : V;
        const float scale = (widx == 0) ? ATT_SCALE : 1.0f;
#pragma unroll
        for (int mi = 0; mi < 2; mi++) {
            const int row = m0 + wm * 32 + mi * 16 + g;
#pragma unroll
            for (int ni = 0; ni < 8; ni++) {
                __half* p = Ch + (size_t)row * DMODEL + col0 + wn * 64 + ni * 8 + cc;
                *(__half2*)p = __floats2half2_rn(acc[mi][ni][0] * scale,
                                                 acc[mi][ni][1] * scale);
                *(__half2*)(p + 8 * DMODEL) =
                    __floats2half2_rn(acc[mi][ni][2] * scale, acc[mi][ni][3] * scale);
            }
        }
    } else {
#pragma unroll
        for (int mi = 0; mi < 2; mi++) {
            const int row = m0 + wm * 32 + mi * 16 + g;
#pragma unroll
            for (int ni = 0; ni < 8; ni++) {
                __half* p = O + (size_t)row * DMODEL + n0 + wn * 64 + ni * 8 + cc;
                *(__half2*)p = __floats2half2_rn(acc[mi][ni][0], acc[mi][ni][1]);
                *(__half2*)(p + 8 * DMODEL) =
                    __floats2half2_rn(acc[mi][ni][2], acc[mi][ni][3]);
            }
        }
    }
}

// ---------------------------------------------------------------------------
// Attention on mma.sync: one CTA per (b,h), 128 threads (4 warps).
// Q pre-scaled by ATT_SCALE. S = Q@K^T -> in-register softmax -> P@V with
// V via ldmatrix.trans. Row masking omitted (redundant with the gate).
// ---------------------------------------------------------------------------
#define ATT_SMEM (3 * 8192)

__global__ __launch_bounds__(128) void attn_mma(const __half* __restrict__ Qf,
                                                const __half* __restrict__ Kf,
                                                const __half* __restrict__ Vf,
                                                __half* __restrict__ AOf) {
    const int h = blockIdx.x;
    const int b = blockIdx.y;
    const int t = threadIdx.x;
    const int w = t >> 5;
    const int lane = t & 31;

    __shared__ __align__(128) char sm[ATT_SMEM];
    const uint32_t sQ = smem_u32(sm);
    const uint32_t sK = sQ + 8192;
    const uint32_t sV = sQ + 16384;

    const size_t gbase = (size_t)b * SEQLEN * DMODEL + h * DHEAD;

    for (int idx = t; idx < 512; idx += 128) {
        const int r = idx >> 3, c = idx & 7;
        const uint32_t sw = (uint32_t)r * 128 + (uint32_t)((c ^ (r & 7)) << 4);
        const size_t go = gbase + (size_t)r * DMODEL + c * 8;
        CP_ASYNC16(sQ + sw, Qf + go);
        CP_ASYNC16(sK + sw, Kf + go);
        CP_ASYNC16(sV + sw, Vf + go);
    }
    CP_COMMIT();
    CP_WAIT(0);
    __syncthreads();

    float s[8][4];
#pragma unroll
    for (int j = 0; j < 8; j++)
#pragma unroll
        for (int q = 0; q < 4; q++) s[j][q] = 0.0f;

    const int a_row = w * 16 + (lane & 15);
    const int a_half = lane >> 4;
    const int b_row_in16 = (lane & 7) + ((lane >> 4) << 3);
    const int b_half = (lane >> 3) & 1;

#pragma unroll
    for (int g = 0; g < 4; g++) {
        uint32_t aq[4];
        {
            const int ch = 2 * g + a_half;
            const uint32_t addr = (uint32_t)a_row * 128 + (uint32_t)((ch ^ (a_row & 7)) << 4);
            LDSM4(aq[0], aq[1], aq[2], aq[3], sQ + addr);
        }
#pragma unroll
        for (int p = 0; p < 4; p++) {
            uint32_t bk[2][2];
            const int row = p * 16 + b_row_in16;
            const int ch  = 2 * g + b_half;
            const uint32_t addr = (uint32_t)row * 128 + (uint32_t)((ch ^ (row & 7)) << 4);
            LDSM4(bk[0][0], bk[0][1], bk[1][0], bk[1][1], sK + addr);
            MMA_F16(s[2 * p],     aq, bk[0]);
            MMA_F16(s[2 * p + 1], aq, bk[1]);
        }
    }

    float mx0 = -1e30f, mx1 = -1e30f;
#pragma unroll
    for (int j = 0; j < 8; j++) {
        mx0 = fmaxf(mx0, fmaxf(s[j][0], s[j][1]));
        mx1 = fmaxf(mx1, fmaxf(s[j][2], s[j][3]));
    }
#pragma unroll
    for (int d = 1; d <= 2; d <<= 1) {
        mx0 = fmaxf(mx0, __shfl_xor_sync(0xFFFFFFFFu, mx0, d));
        mx1 = fmaxf(mx1, __shfl_xor_sync(0xFFFFFFFFu, mx1, d));
    }
    float sm0 = 0.0f, sm1 = 0.0f;
#pragma unroll
    for (int j = 0; j < 8; j++) {
        s[j][0] = __expf(s[j][0] - mx0); sm0 += s[j][0];
        s[j][1] = __expf(s[j][1] - mx0); sm0 += s[j][1];
        s[j][2] = __expf(s[j][2] - mx1); sm1 += s[j][2];
        s[j][3] = __expf(s[j][3] - mx1); sm1 += s[j][3];
    }
#pragma unroll
    for (int d = 1; d <= 2; d <<= 1) {
        sm0 += __shfl_xor_sync(0xFFFFFFFFu, sm0, d);
        sm1 += __shfl_xor_sync(0xFFFFFFFFu, sm1, d);
    }
    const float inv0 = 1.0f / sm0;
    const float inv1 = 1.0f / sm1;

    uint32_t ph[8], pl[8];
#pragma unroll
    for (int j = 0; j < 8; j++) {
        ph[j] = h2u(__floats2half2_rn(s[j][0] * inv0, s[j][1] * inv0));
        pl[j] = h2u(__floats2half2_rn(s[j][2] * inv1, s[j][3] * inv1));
    }

    float o[8][4];
#pragma unroll
    for (int j = 0; j < 8; j++)
#pragma unroll
        for (int q = 0; q < 4; q++) o[j][q] = 0.0f;

    const int v_row_in16 = (lane & 7) + 8 * ((lane >> 3) & 1);
    const int v_col8     = 8 * (lane >> 4);

#pragma unroll
    for (int g = 0; g < 4; g++) {
        uint32_t ap[4] = { ph[2 * g], pl[2 * g], ph[2 * g + 1], pl[2 * g + 1] };
#pragma unroll
        for (int q = 0; q < 4; q++) {
            uint32_t bv[2][2];
            const int row = 16 * g + v_row_in16;
            const int col = 16 * q + v_col8;
            const uint32_t addr = (uint32_t)row * 128 +
                                  (uint32_t)(((col >> 3) ^ (row & 7)) << 4);
            LDSM4T(bv[0][0], bv[0][1], bv[1][0], bv[1][1], sV + addr);
            MMA_F16(o[2 * q],     ap, bv[0]);
            MMA_F16(o[2 * q + 1], ap, bv[1]);
        }
    }

    const int r0 = lane >> 2;
    const int cc = (lane & 3) * 2;
#pragma unroll
    for (int j = 0; j < 8; j++) {
        __half* p = AOf + gbase + (size_t)(w * 16 + r0) * DMODEL + j * 8 + cc;
        *(__half2*)p = __floats2half2_rn(o[j][0], o[j][1]);
        *(__half2*)(p + 8 * DMODEL) = __floats2half2_rn(o[j][2], o[j][3]);
    }
}

// ---------------------------------------------------------------------------
// Gated residual + LayerNorm (proj now fp16)
// ---------------------------------------------------------------------------
__global__ __launch_bounds__(256) void resid_ln(const float* __restrict__ hidden,
                                                const __half* __restrict__ proj,
                                                const unsigned* __restrict__ mask,
                                                const float* __restrict__ gamma,
                                                const float* __restrict__ beta,
                                                float* __restrict__ out) {
    const int r = blockIdx.x;
    const int t = threadIdx.x;
    const size_t base = (size_t)r * DMODEL + t * 4;

    const float act = (mask[r] != 0u) ? 1.0f : 0.0f;
    const float4 hv = *(const float4*)(hidden + base);
    const uint2 o2 = *(const uint2*)(proj + base);
    const __half2 oh0 = *reinterpret_cast<const __half2*>(&o2.x);
    const __half2 oh1 = *reinterpret_cast<const __half2*>(&o2.y);
    const float2 of0 = __half22float2(oh0);
    const float2 of1 = __half22float2(oh1);

    float4 f;
    f.x = hv.x + act * of0.x;
    f.y = hv.y + act * of0.y;
    f.z = hv.z + act * of1.x;
    f.w = hv.w + act * of1.y;

    float s  = f.x + f.y + f.z + f.w;
    float s2 = f.x * f.x + f.y * f.y + f.z * f.z + f.w * f.w;

#pragma unroll
    for (int d = 16; d; d >>= 1) {
        s  += __shfl_xor_sync(0xFFFFFFFFu, s,  d);
        s2 += __shfl_xor_sync(0xFFFFFFFFu, s2, d);
    }

    __shared__ float ws[8], ws2[8];
    const int warp = t >> 5, lane = t & 31;
    if (lane == 0) { ws[warp] = s; ws2[warp] = s2; }
    __syncthreads();

    float ts = 0.0f, ts2 = 0.0f;
#pragma unroll
    for (int i = 0; i < 8; i++) { ts += ws[i]; ts2 += ws2[i]; }

    const float mu  = ts * (1.0f / DMODEL);
    const float var = ts2 * (1.0f / DMODEL) - mu * mu;
    const float rs  = rsqrtf(var + LN_EPS);

    const float4 gv = *(const float4*)(gamma + t * 4);
    const float4 bv = *(const float4*)(beta  + t * 4);

    float4 r4;
    r4.x = (f.x - mu) * rs * gv.x + bv.x;
    r4.y = (f.y - mu) * rs * gv.y + bv.y;
    r4.z = (f.z - mu) * rs * gv.z + bv.z;
    r4.w = (f.w - mu) * rs * gv.w + bv.w;
    *(float4*)(out + base) = r4;
}

// ---------------------------------------------------------------------------
// Launch
// ---------------------------------------------------------------------------
extern "C" void kernel_launch(void* const* d_in, const int* in_sizes, int n_in,
                              void* d_out, int out_size) {
    const float*    hidden = (const float*)d_in[0];
    const unsigned* mask   = (const unsigned*)d_in[1];
    const float*    W[4]   = {(const float*)d_in[2], (const float*)d_in[3],
                              (const float*)d_in[4], (const float*)d_in[5]};
    const float*    gamma  = (const float*)d_in[6];
    const float*    beta   = (const float*)d_in[7];
    float*          out    = (float*)d_out;

    __half *Qf, *Kf, *Vf, *Of, *hf, *aof, *wf;
    cudaGetSymbolAddress((void**)&Qf,  g_Qf);
    cudaGetSymbolAddress((void**)&Kf,  g_Kf);
    cudaGetSymbolAddress((void**)&Vf,  g_Vf);
    cudaGetSymbolAddress((void**)&Of,  g_Of);
    cudaGetSymbolAddress((void**)&hf,  g_hf);
    cudaGetSymbolAddress((void**)&aof, g_aof);
    cudaGetSymbolAddress((void**)&wf,  g_wf);

    cudaFuncSetAttribute(gemm_mma<0>, cudaFuncAttributeMaxDynamicSharedMemorySize, GEMM_SMEM);
    cudaFuncSetAttribute(gemm_mma<1>, cudaFuncAttributeMaxDynamicSharedMemorySize, GEMM_SMEM);

    // Conversions (hidden + all 4 weights in 2 launches)
    const int n4h = MTOT * DMODEL / 4;
    cvt_f16<<<n4h / 256, 256>>>((const float4*)hidden, (uint2*)hf, n4h);
    cvt_w4<<<4 * (DMODEL * DMODEL / 4) / 256, 256>>>(
        (const float4*)W[0], (const float4*)W[1],
        (const float4*)W[2], (const float4*)W[3], (uint2*)wf);

    // Fused QKV projection (N = 3072)
    gemm_mma<1><<<dim3(3 * DMODEL / BN, MTOT / BM), GTHREADS, GEMM_SMEM>>>(
        hf, wf, nullptr, Qf, Kf, Vf);

    attn_mma<<<dim3(NHEAD, BATCH), 128>>>(Qf, Kf, Vf, aof);

    // O projection -> fp16
    gemm_mma<0><<<dim3(DMODEL / BN, MTOT / BM), GTHREADS, GEMM_SMEM>>>(
        aof, wf + 3 * (size_t)DMODEL * DMODEL, Of, nullptr, nullptr, nullptr);

    resid_ln<<<MTOT, 256>>>(hidden, Of, mask, gamma, beta, out);
}

// round 12
// speedup vs baseline: 8.7338x; 1.2340x over previous
#include <cuda_runtime.h>
#include <cuda_fp16.h>
#include <cstdint>

// ---------------------------------------------------------------------------
// Problem constants
// ---------------------------------------------------------------------------
#define MTOT   16384      // B*K
#define DMODEL 1024
#define NHEAD  16
#define DHEAD  64
#define BATCH  256
#define SEQLEN 64
#define ATT_SCALE 0.125f
#define LN_EPS 1e-5f

// ---------------------------------------------------------------------------
// Scratch (device globals: the allowed no-alloc workaround)
// ---------------------------------------------------------------------------
__device__ __half g_Qf [MTOT * DMODEL];          // Q (pre-scaled) fp16
__device__ __half g_Kf [MTOT * DMODEL];          // K fp16
__device__ __half g_Vf [MTOT * DMODEL];          // V fp16
__device__ __half g_Of [MTOT * DMODEL];          // O projection fp16
__device__ __half g_hf [MTOT * DMODEL];          // hidden fp16
__device__ __half g_aof[MTOT * DMODEL];          // attn out fp16
__device__ __half g_wf [4][DMODEL * DMODEL];     // Wq,Wk,Wv,Wo fp16 (contiguous)
__device__ int    g_cnt;                         // # active rows
__device__ int    g_idx[MTOT];                   // sorted active-row indices

// ---------------------------------------------------------------------------
// Baseline-PTX helpers (harness compiles via compute_103: no tcgen05)
// ---------------------------------------------------------------------------
__device__ __forceinline__ uint32_t smem_u32(const void* p) {
    uint32_t a;
    asm("{ .reg .u64 t; cvta.to.shared.u64 t, %1; cvt.u32.u64 %0, t; }"
        : "=r"(a) : "l"(p));
    return a;
}

#define CP_ASYNC16(dst, src) \
    asm volatile("cp.async.cg.shared.global [%0], [%1], 16;" :: "r"(dst), "l"(src))
#define CP_COMMIT() asm volatile("cp.async.commit_group;" ::: "memory")
#define CP_WAIT(n)  asm volatile("cp.async.wait_group %0;" :: "n"(n) : "memory")

#define LDSM4(r0, r1, r2, r3, addr) \
    asm volatile("ldmatrix.sync.aligned.m8n8.x4.shared.b16 {%0,%1,%2,%3}, [%4];" \
                 : "=r"(r0), "=r"(r1), "=r"(r2), "=r"(r3) : "r"(addr))

#define LDSM4T(r0, r1, r2, r3, addr) \
    asm volatile("ldmatrix.sync.aligned.m8n8.x4.trans.shared.b16 {%0,%1,%2,%3}, [%4];" \
                 : "=r"(r0), "=r"(r1), "=r"(r2), "=r"(r3) : "r"(addr))

#define MMA_F16(d, a, b) \
    asm volatile("mma.sync.aligned.m16n8k16.row.col.f32.f16.f16.f32 " \
                 "{%0,%1,%2,%3},{%4,%5,%6,%7},{%8,%9},{%0,%1,%2,%3};" \
                 : "+f"((d)[0]), "+f"((d)[1]), "+f"((d)[2]), "+f"((d)[3]) \
                 : "r"((a)[0]), "r"((a)[1]), "r"((a)[2]), "r"((a)[3]), \
                   "r"((b)[0]), "r"((b)[1]))

__device__ __forceinline__ uint32_t h2u(__half2 h) {
    return *reinterpret_cast<uint32_t*>(&h);
}

// ---------------------------------------------------------------------------
// fp32 -> fp16 conversions
// ---------------------------------------------------------------------------
__global__ __launch_bounds__(256) void cvt_f16(const float4* __restrict__ in,
                                               uint2* __restrict__ out16, int n4) {
    int i = blockIdx.x * 256 + threadIdx.x;
    if (i >= n4) return;
    float4 v = in[i];
    __half2 p0 = __floats2half2_rn(v.x, v.y);
    __half2 p1 = __floats2half2_rn(v.z, v.w);
    out16[i] = make_uint2(h2u(p0), h2u(p1));
}

__global__ __launch_bounds__(256) void cvt_w4(const float4* __restrict__ w0,
                                              const float4* __restrict__ w1,
                                              const float4* __restrict__ w2,
                                              const float4* __restrict__ w3,
                                              uint2* __restrict__ out16) {
    const int i = blockIdx.x * 256 + threadIdx.x;   // 0 .. 4*262144-1
    const int w = i >> 18;
    const int j = i & 262143;
    const float4* src = (w == 0) ? w0 : (w == 1) ? w1 : (w == 2) ? w2 : w3;
    float4 v = src[j];
    __half2 p0 = __floats2half2_rn(v.x, v.y);
    __half2 p1 = __floats2half2_rn(v.z, v.w);
    out16[i] = make_uint2(h2u(p0), h2u(p1));
}

// ---------------------------------------------------------------------------
// Deterministic sorted compaction of active rows (single CTA, 1024 threads,
// 16 rows/thread, warp + block exclusive scan).
// ---------------------------------------------------------------------------
__global__ __launch_bounds__(1024) void build_idx(const unsigned* __restrict__ mask) {
    const int t = threadIdx.x;
    const int lane = t & 31, warp = t >> 5;

    int loc = 0;
    int c = 0;
#pragma unroll
    for (int i = 0; i < 16; i++) {
        const int r = t * 16 + i;
        const int a = (mask[r] != 0u) ? 1 : 0;
        loc |= a << i;
        c += a;
    }
    int pre = c;
#pragma unroll
    for (int d = 1; d < 32; d <<= 1) {
        int v = __shfl_up_sync(0xFFFFFFFFu, pre, d);
        if (lane >= d) pre += v;
    }
    __shared__ int wsum[32];
    if (lane == 31) wsum[warp] = pre;
    __syncthreads();
    if (warp == 0) {
        int v = wsum[lane];
        int p = v;
#pragma unroll
        for (int d = 1; d < 32; d <<= 1) {
            int x = __shfl_up_sync(0xFFFFFFFFu, p, d);
            if (lane >= d) p += x;
        }
        wsum[lane] = p - v;      // exclusive warp offsets
    }
    __syncthreads();

    int base = wsum[warp] + (pre - c);
#pragma unroll
    for (int i = 0; i < 16; i++) {
        if ((loc >> i) & 1) g_idx[base++] = t * 16 + i;
    }
    if (t == 1023) g_cnt = base;
}

// ---------------------------------------------------------------------------
// mma.sync fp16 GEMM (NT): C[m,n] = sum_k A[m,k] * B[n,k], fp32 accum.
// BM=128, BN=256, BK=64, cp.async 3-stage pipeline, 8-chunk XOR swizzle.
// 512 threads = 16 warps = 4(M) x 4(N), warp tile 32x64.
// MODE 1: fused QKV (N=3072). Q n-region compacted via g_idx; K/V full.
// MODE 0: O projection, fully compacted, fp16 out.
// Epilogue indirection maps BOTH fragment rows independently:
//   c0c1 -> g_idx[rowc], c2c3 -> g_idx[rowc+8].
// ---------------------------------------------------------------------------
#define BM 128
#define BN 256
#define BKC 64
#define NC (DMODEL / BKC)        // 16 k-chunks
#define A_BYTES (128 * 128)
#define B_BYTES (256 * 128)
#define OFF_A 0
#define OFF_B A_BYTES
#define STAGE_BYTES (A_BYTES + B_BYTES)   // 49152
#define NSTAGE 3
#define GEMM_SMEM (NSTAGE * STAGE_BYTES)  // 147456
#define GTHREADS 512

template <int MODE>
__global__ __launch_bounds__(GTHREADS, 1) void gemm_mma(
    const __half* __restrict__ A, const __half* __restrict__ B,
    __half* __restrict__ O,
    __half* __restrict__ Q, __half* __restrict__ Kk, __half* __restrict__ V)
{
    const int m0   = blockIdx.y * BM;
    const int n0   = blockIdx.x * BN;
    const int widx = (MODE == 1) ? (n0 >> 10) : 0;   // 0=Q,1=K,2=V
    const bool compact = (MODE == 0) || (widx == 0);
    const int cnt = compact ? g_cnt : MTOT;
    if (compact && m0 >= cnt) return;
    const int cmax = cnt - 1;

    extern __shared__ char smem[];
    const uint32_t sb = smem_u32(smem);

    const int tid  = threadIdx.x;
    const int wid  = tid >> 5;
    const int lane = tid & 31;
    const int wm   = wid & 3;        // M offset wm*32
    const int wn   = wid >> 2;       // N offset wn*64

    // Per-thread A source rows (indirected per tile row when compacted)
    int arow[2];
#pragma unroll
    for (int i = 0; i < 2; i++) {
        const int r = (tid + i * GTHREADS) >> 3;
        const int gm = m0 + r;
        const int gc = gm <= cmax ? gm : cmax;
        arow[i] = compact ? g_idx[gc] : gm;
    }

    auto load_stage = [&](int kt, int stg) {
        const uint32_t base = sb + stg * STAGE_BYTES;
#pragma unroll
        for (int i = 0; i < 2; i++) {          // A: 1024 16B-chunks
            const int idx = tid + i * GTHREADS;
            const int r = idx >> 3, c = idx & 7;
            const uint32_t sw = (uint32_t)r * 128 + (uint32_t)((c ^ (r & 7)) << 4);
            CP_ASYNC16(base + OFF_A + sw,
                       A + (size_t)arow[i] * DMODEL + kt * BKC + c * 8);
        }
#pragma unroll
        for (int i = 0; i < 4; i++) {          // B: 2048 16B-chunks
            const int idx = tid + i * GTHREADS;
            const int r = idx >> 3, c = idx & 7;
            const uint32_t sw = (uint32_t)r * 128 + (uint32_t)((c ^ (r & 7)) << 4);
            CP_ASYNC16(base + OFF_B + sw,
                       B + (size_t)(n0 + r) * DMODEL + kt * BKC + c * 8);
        }
        CP_COMMIT();
    };

    float acc[2][8][4];
#pragma unroll
    for (int mi = 0; mi < 2; mi++)
#pragma unroll
        for (int ni = 0; ni < 8; ni++)
#pragma unroll
            for (int q = 0; q < 4; q++) acc[mi][ni][q] = 0.0f;

    const int a_row_in16 = lane & 15;
    const int a_half     = lane >> 4;
    const int b_row_in16 = (lane & 7) + ((lane >> 4) << 3);
    const int b_half     = (lane >> 3) & 1;

    load_stage(0, 0);
    load_stage(1, 1);

    for (int kt = 0; kt < NC; kt++) {
        if (kt < NC - 1) { CP_WAIT(1); } else { CP_WAIT(0); }
        __syncthreads();

        if (kt + 2 < NC) load_stage(kt + 2, (kt + 2) % NSTAGE);

        const uint32_t base = sb + (kt % NSTAGE) * STAGE_BYTES;

#pragma unroll
        for (int kk = 0; kk < 4; kk++) {
            uint32_t ah[2][4];
#pragma unroll
            for (int mi = 0; mi < 2; mi++) {
                const int row = wm * 32 + mi * 16 + a_row_in16;
                const int ch  = kk * 2 + a_half;
                const uint32_t addr = (uint32_t)row * 128 + (uint32_t)((ch ^ (row & 7)) << 4);
                LDSM4(ah[mi][0], ah[mi][1], ah[mi][2], ah[mi][3], base + OFF_A + addr);
            }
#pragma unroll
            for (int p = 0; p < 4; p++) {
                uint32_t bf[2][2];
                const int row = wn * 64 + p * 16 + b_row_in16;
                const int ch  = kk * 2 + b_half;
                const uint32_t addr = (uint32_t)row * 128 + (uint32_t)((ch ^ (row & 7)) << 4);
                LDSM4(bf[0][0], bf[0][1], bf[1][0], bf[1][1], base + OFF_B + addr);
#pragma unroll
                for (int mi = 0; mi < 2; mi++)
#pragma unroll
                    for (int q = 0; q < 2; q++)
                        MMA_F16(acc[mi][2 * p + q], ah[mi], bf[q]);
            }
        }
    }

    const int g  = lane >> 2;
    const int cc = (lane & 3) * 2;
    if (MODE == 1) {
        const int col0 = n0 & 1023;
        __half* Ch = (widx == 0) ? Q : (widx == 1) ? Kk : V;
        const float scale = (widx == 0) ? ATT_SCALE : 1.0f;
#pragma unroll
        for (int mi = 0; mi < 2; mi++) {
            const int rc0 = m0 + wm * 32 + mi * 16 + g;
            const int rc1 = rc0 + 8;
            const int i0 = rc0 <= cmax ? rc0 : cmax;
            const int i1 = rc1 <= cmax ? rc1 : cmax;
            const int rlo = compact ? g_idx[i0] : rc0;
            const int rhi = compact ? g_idx[i1] : rc1;
#pragma unroll
            for (int ni = 0; ni < 8; ni++) {
                const size_t coff = (size_t)col0 + wn * 64 + ni * 8 + cc;
                *(__half2*)(Ch + (size_t)rlo * DMODEL + coff) =
                    __floats2half2_rn(acc[mi][ni][0] * scale, acc[mi][ni][1] * scale);
                *(__half2*)(Ch + (size_t)rhi * DMODEL + coff) =
                    __floats2half2_rn(acc[mi][ni][2] * scale, acc[mi][ni][3] * scale);
            }
        }
    } else {
#pragma unroll
        for (int mi = 0; mi < 2; mi++) {
            const int rc0 = m0 + wm * 32 + mi * 16 + g;
            const int rc1 = rc0 + 8;
            const int i0 = rc0 <= cmax ? rc0 : cmax;
            const int i1 = rc1 <= cmax ? rc1 : cmax;
            const int rlo = g_idx[i0];
            const int rhi = g_idx[i1];
#pragma unroll
            for (int ni = 0; ni < 8; ni++) {
                const size_t coff = (size_t)n0 + wn * 64 + ni * 8 + cc;
                *(__half2*)(O + (size_t)rlo * DMODEL + coff) =
                    __floats2half2_rn(acc[mi][ni][0], acc[mi][ni][1]);
                *(__half2*)(O + (size_t)rhi * DMODEL + coff) =
                    __floats2half2_rn(acc[mi][ni][2], acc[mi][ni][3]);
            }
        }
    }
}

// ---------------------------------------------------------------------------
// Attention on mma.sync: one CTA per (b,h), 128 threads (4 warps).
// Q pre-scaled by ATT_SCALE. Inactive Q rows are zero -> uniform softmax ->
// finite output, discarded by the residual gate.
// ---------------------------------------------------------------------------
#define ATT_SMEM (3 * 8192)

__global__ __launch_bounds__(128) void attn_mma(const __half* __restrict__ Qf,
                                                const __half* __restrict__ Kf,
                                                const __half* __restrict__ Vf,
                                                __half* __restrict__ AOf) {
    const int h = blockIdx.x;
    const int b = blockIdx.y;
    const int t = threadIdx.x;
    const int w = t >> 5;
    const int lane = t & 31;

    __shared__ __align__(128) char sm[ATT_SMEM];
    const uint32_t sQ = smem_u32(sm);
    const uint32_t sK = sQ + 8192;
    const uint32_t sV = sQ + 16384;

    const size_t gbase = (size_t)b * SEQLEN * DMODEL + h * DHEAD;

    for (int idx = t; idx < 512; idx += 128) {
        const int r = idx >> 3, c = idx & 7;
        const uint32_t sw = (uint32_t)r * 128 + (uint32_t)((c ^ (r & 7)) << 4);
        const size_t go = gbase + (size_t)r * DMODEL + c * 8;
        CP_ASYNC16(sQ + sw, Qf + go);
        CP_ASYNC16(sK + sw, Kf + go);
        CP_ASYNC16(sV + sw, Vf + go);
    }
    CP_COMMIT();
    CP_WAIT(0);
    __syncthreads();

    float s[8][4];
#pragma unroll
    for (int j = 0; j < 8; j++)
#pragma unroll
        for (int q = 0; q < 4; q++) s[j][q] = 0.0f;

    const int a_row = w * 16 + (lane & 15);
    const int a_half = lane >> 4;
    const int b_row_in16 = (lane & 7) + ((lane >> 4) << 3);
    const int b_half = (lane >> 3) & 1;

#pragma unroll
    for (int g = 0; g < 4; g++) {
        uint32_t aq[4];
        {
            const int ch = 2 * g + a_half;
            const uint32_t addr = (uint32_t)a_row * 128 + (uint32_t)((ch ^ (a_row & 7)) << 4);
            LDSM4(aq[0], aq[1], aq[2], aq[3], sQ + addr);
        }
#pragma unroll
        for (int p = 0; p < 4; p++) {
            uint32_t bk[2][2];
            const int row = p * 16 + b_row_in16;
            const int ch  = 2 * g + b_half;
            const uint32_t addr = (uint32_t)row * 128 + (uint32_t)((ch ^ (row & 7)) << 4);
            LDSM4(bk[0][0], bk[0][1], bk[1][0], bk[1][1], sK + addr);
            MMA_F16(s[2 * p],     aq, bk[0]);
            MMA_F16(s[2 * p + 1], aq, bk[1]);
        }
    }

    float mx0 = -1e30f, mx1 = -1e30f;
#pragma unroll
    for (int j = 0; j < 8; j++) {
        mx0 = fmaxf(mx0, fmaxf(s[j][0], s[j][1]));
        mx1 = fmaxf(mx1, fmaxf(s[j][2], s[j][3]));
    }
#pragma unroll
    for (int d = 1; d <= 2; d <<= 1) {
        mx0 = fmaxf(mx0, __shfl_xor_sync(0xFFFFFFFFu, mx0, d));
        mx1 = fmaxf(mx1, __shfl_xor_sync(0xFFFFFFFFu, mx1, d));
    }
    float sm0 = 0.0f, sm1 = 0.0f;
#pragma unroll
    for (int j = 0; j < 8; j++) {
        s[j][0] = __expf(s[j][0] - mx0); sm0 += s[j][0];
        s[j][1] = __expf(s[j][1] - mx0); sm0 += s[j][1];
        s[j][2] = __expf(s[j][2] - mx1); sm1 += s[j][2];
        s[j][3] = __expf(s[j][3] - mx1); sm1 += s[j][3];
    }
#pragma unroll
    for (int d = 1; d <= 2; d <<= 1) {
        sm0 += __shfl_xor_sync(0xFFFFFFFFu, sm0, d);
        sm1 += __shfl_xor_sync(0xFFFFFFFFu, sm1, d);
    }
    const float inv0 = 1.0f / sm0;
    const float inv1 = 1.0f / sm1;

    uint32_t ph[8], pl[8];
#pragma unroll
    for (int j = 0; j < 8; j++) {
        ph[j] = h2u(__floats2half2_rn(s[j][0] * inv0, s[j][1] * inv0));
        pl[j] = h2u(__floats2half2_rn(s[j][2] * inv1, s[j][3] * inv1));
    }

    float o[8][4];
#pragma unroll
    for (int j = 0; j < 8; j++)
#pragma unroll
        for (int q = 0; q < 4; q++) o[j][q] = 0.0f;

    const int v_row_in16 = (lane & 7) + 8 * ((lane >> 3) & 1);
    const int v_col8     = 8 * (lane >> 4);

#pragma unroll
    for (int g = 0; g < 4; g++) {
        uint32_t ap[4] = { ph[2 * g], pl[2 * g], ph[2 * g + 1], pl[2 * g + 1] };
#pragma unroll
        for (int q = 0; q < 4; q++) {
            uint32_t bv[2][2];
            const int row = 16 * g + v_row_in16;
            const int col = 16 * q + v_col8;
            const uint32_t addr = (uint32_t)row * 128 +
                                  (uint32_t)(((col >> 3) ^ (row & 7)) << 4);
            LDSM4T(bv[0][0], bv[0][1], bv[1][0], bv[1][1], sV + addr);
            MMA_F16(o[2 * q],     ap, bv[0]);
            MMA_F16(o[2 * q + 1], ap, bv[1]);
        }
    }

    const int r0 = lane >> 2;
    const int cc = (lane & 3) * 2;
#pragma unroll
    for (int j = 0; j < 8; j++) {
        __half* p = AOf + gbase + (size_t)(w * 16 + r0) * DMODEL + j * 8 + cc;
        *(__half2*)p = __floats2half2_rn(o[j][0], o[j][1]);
        *(__half2*)(p + 8 * DMODEL) = __floats2half2_rn(o[j][2], o[j][3]);
    }
}

// ---------------------------------------------------------------------------
// Gated residual + LayerNorm (proj fp16; inactive proj rows stay zero)
// ---------------------------------------------------------------------------
__global__ __launch_bounds__(256) void resid_ln(const float* __restrict__ hidden,
                                                const __half* __restrict__ proj,
                                                const unsigned* __restrict__ mask,
                                                const float* __restrict__ gamma,
                                                const float* __restrict__ beta,
                                                float* __restrict__ out) {
    const int r = blockIdx.x;
    const int t = threadIdx.x;
    const size_t base = (size_t)r * DMODEL + t * 4;

    const float act = (mask[r] != 0u) ? 1.0f : 0.0f;
    const float4 hv = *(const float4*)(hidden + base);
    const uint2 o2 = *(const uint2*)(proj + base);
    const __half2 oh0 = *reinterpret_cast<const __half2*>(&o2.x);
    const __half2 oh1 = *reinterpret_cast<const __half2*>(&o2.y);
    const float2 of0 = __half22float2(oh0);
    const float2 of1 = __half22float2(oh1);

    float4 f;
    f.x = hv.x + act * of0.x;
    f.y = hv.y + act * of0.y;
    f.z = hv.z + act * of1.x;
    f.w = hv.w + act * of1.y;

    float s  = f.x + f.y + f.z + f.w;
    float s2 = f.x * f.x + f.y * f.y + f.z * f.z + f.w * f.w;

#pragma unroll
    for (int d = 16; d; d >>= 1) {
        s  += __shfl_xor_sync(0xFFFFFFFFu, s,  d);
        s2 += __shfl_xor_sync(0xFFFFFFFFu, s2, d);
    }

    __shared__ float ws[8], ws2[8];
    const int warp = t >> 5, lane = t & 31;
    if (lane == 0) { ws[warp] = s; ws2[warp] = s2; }
    __syncthreads();

    float ts = 0.0f, ts2 = 0.0f;
#pragma unroll
    for (int i = 0; i < 8; i++) { ts += ws[i]; ts2 += ws2[i]; }

    const float mu  = ts * (1.0f / DMODEL);
    const float var = ts2 * (1.0f / DMODEL) - mu * mu;
    const float rs  = rsqrtf(var + LN_EPS);

    const float4 gv = *(const float4*)(gamma + t * 4);
    const float4 bv = *(const float4*)(beta  + t * 4);

    float4 r4;
    r4.x = (f.x - mu) * rs * gv.x + bv.x;
    r4.y = (f.y - mu) * rs * gv.y + bv.y;
    r4.z = (f.z - mu) * rs * gv.z + bv.z;
    r4.w = (f.w - mu) * rs * gv.w + bv.w;
    *(float4*)(out + base) = r4;
}

// ---------------------------------------------------------------------------
// Launch
// ---------------------------------------------------------------------------
extern "C" void kernel_launch(void* const* d_in, const int* in_sizes, int n_in,
                              void* d_out, int out_size) {
    const float*    hidden = (const float*)d_in[0];
    const unsigned* mask   = (const unsigned*)d_in[1];
    const float*    W[4]   = {(const float*)d_in[2], (const float*)d_in[3],
                              (const float*)d_in[4], (const float*)d_in[5]};
    const float*    gamma  = (const float*)d_in[6];
    const float*    beta   = (const float*)d_in[7];
    float*          out    = (float*)d_out;

    __half *Qf, *Kf, *Vf, *Of, *hf, *aof, *wf;
    cudaGetSymbolAddress((void**)&Qf,  g_Qf);
    cudaGetSymbolAddress((void**)&Kf,  g_Kf);
    cudaGetSymbolAddress((void**)&Vf,  g_Vf);
    cudaGetSymbolAddress((void**)&Of,  g_Of);
    cudaGetSymbolAddress((void**)&hf,  g_hf);
    cudaGetSymbolAddress((void**)&aof, g_aof);
    cudaGetSymbolAddress((void**)&wf,  g_wf);

    cudaFuncSetAttribute(gemm_mma<0>, cudaFuncAttributeMaxDynamicSharedMemorySize, GEMM_SMEM);
    cudaFuncSetAttribute(gemm_mma<1>, cudaFuncAttributeMaxDynamicSharedMemorySize, GEMM_SMEM);

    // Conversions + active-row compaction
    const int n4h = MTOT * DMODEL / 4;
    cvt_f16<<<n4h / 256, 256>>>((const float4*)hidden, (uint2*)hf, n4h);
    cvt_w4<<<4 * (DMODEL * DMODEL / 4) / 256, 256>>>(
        (const float4*)W[0], (const float4*)W[1],
        (const float4*)W[2], (const float4*)W[3], (uint2*)wf);
    build_idx<<<1, 1024>>>(mask);

    // Fused QKV projection (N = 3072; Q region compacted)
    gemm_mma<1><<<dim3(3 * DMODEL / BN, MTOT / BM), GTHREADS, GEMM_SMEM>>>(
        hf, wf, nullptr, Qf, Kf, Vf);

    attn_mma<<<dim3(NHEAD, BATCH), 128>>>(Qf, Kf, Vf, aof);

    // O projection (compacted) -> fp16
    gemm_mma<0><<<dim3(DMODEL / BN, MTOT / BM), GTHREADS, GEMM_SMEM>>>(
        aof, wf + 3 * (size_t)DMODEL * DMODEL, Of, nullptr, nullptr, nullptr);

    resid_ln<<<MTOT, 256>>>(hidden, Of, mask, gamma, beta, out);
}

// round 13
// speedup vs baseline: 9.4122x; 1.0777x over previous
#include <cuda_runtime.h>
#include <cuda_fp16.h>
#include <cstdint>

// ---------------------------------------------------------------------------
// Problem constants
// ---------------------------------------------------------------------------
#define MTOT   16384      // B*K
#define DMODEL 1024
#define NHEAD  16
#define DHEAD  64
#define BATCH  256
#define SEQLEN 64
#define ATT_SCALE 0.125f
#define LN_EPS 1e-5f

// ---------------------------------------------------------------------------
// Scratch (device globals: the allowed no-alloc workaround)
// ---------------------------------------------------------------------------
__device__ __half g_Qf [MTOT * DMODEL];          // Q (pre-scaled) fp16
__device__ __half g_Kf [MTOT * DMODEL];          // K fp16
__device__ __half g_Vf [MTOT * DMODEL];          // V fp16
__device__ __half g_Of [MTOT * DMODEL];          // O projection fp16
__device__ __half g_hf [MTOT * DMODEL];          // hidden fp16
__device__ __half g_aof[MTOT * DMODEL];          // attn out fp16
__device__ __half g_wf [4][DMODEL * DMODEL];     // Wq,Wk,Wv,Wo fp16 (contiguous)
__device__ int    g_cnt;                         // # active rows
__device__ int    g_idx[MTOT];                   // sorted active-row indices

// ---------------------------------------------------------------------------
// Baseline-PTX helpers (harness compiles via compute_103: no tcgen05)
// ---------------------------------------------------------------------------
__device__ __forceinline__ uint32_t smem_u32(const void* p) {
    uint32_t a;
    asm("{ .reg .u64 t; cvta.to.shared.u64 t, %1; cvt.u32.u64 %0, t; }"
        : "=r"(a) : "l"(p));
    return a;
}

#define CP_ASYNC16(dst, src) \
    asm volatile("cp.async.cg.shared.global [%0], [%1], 16;" :: "r"(dst), "l"(src))
#define CP_COMMIT() asm volatile("cp.async.commit_group;" ::: "memory")
#define CP_WAIT(n)  asm volatile("cp.async.wait_group %0;" :: "n"(n) : "memory")

#define LDSM4(r0, r1, r2, r3, addr) \
    asm volatile("ldmatrix.sync.aligned.m8n8.x4.shared.b16 {%0,%1,%2,%3}, [%4];" \
                 : "=r"(r0), "=r"(r1), "=r"(r2), "=r"(r3) : "r"(addr))

#define LDSM4T(r0, r1, r2, r3, addr) \
    asm volatile("ldmatrix.sync.aligned.m8n8.x4.trans.shared.b16 {%0,%1,%2,%3}, [%4];" \
                 : "=r"(r0), "=r"(r1), "=r"(r2), "=r"(r3) : "r"(addr))

#define MMA_F16(d, a, b) \
    asm volatile("mma.sync.aligned.m16n8k16.row.col.f32.f16.f16.f32 " \
                 "{%0,%1,%2,%3},{%4,%5,%6,%7},{%8,%9},{%0,%1,%2,%3};" \
                 : "+f"((d)[0]), "+f"((d)[1]), "+f"((d)[2]), "+f"((d)[3]) \
                 : "r"((a)[0]), "r"((a)[1]), "r"((a)[2]), "r"((a)[3]), \
                   "r"((b)[0]), "r"((b)[1]))

__device__ __forceinline__ uint32_t h2u(__half2 h) {
    return *reinterpret_cast<uint32_t*>(&h);
}

// ---------------------------------------------------------------------------
// fp32 -> fp16 conversions
// ---------------------------------------------------------------------------
__global__ __launch_bounds__(256) void cvt_f16(const float4* __restrict__ in,
                                               uint2* __restrict__ out16, int n4) {
    int i = blockIdx.x * 256 + threadIdx.x;
    if (i >= n4) return;
    float4 v = in[i];
    __half2 p0 = __floats2half2_rn(v.x, v.y);
    __half2 p1 = __floats2half2_rn(v.z, v.w);
    out16[i] = make_uint2(h2u(p0), h2u(p1));
}

__global__ __launch_bounds__(256) void cvt_w4(const float4* __restrict__ w0,
                                              const float4* __restrict__ w1,
                                              const float4* __restrict__ w2,
                                              const float4* __restrict__ w3,
                                              uint2* __restrict__ out16) {
    const int i = blockIdx.x * 256 + threadIdx.x;   // 0 .. 4*262144-1
    const int w = i >> 18;
    const int j = i & 262143;
    const float4* src = (w == 0) ? w0 : (w == 1) ? w1 : (w == 2) ? w2 : w3;
    float4 v = src[j];
    __half2 p0 = __floats2half2_rn(v.x, v.y);
    __half2 p1 = __floats2half2_rn(v.z, v.w);
    out16[i] = make_uint2(h2u(p0), h2u(p1));
}

// ---------------------------------------------------------------------------
// Deterministic sorted compaction of active rows (single CTA, 1024 threads).
// ---------------------------------------------------------------------------
__global__ __launch_bounds__(1024) void build_idx(const unsigned* __restrict__ mask) {
    const int t = threadIdx.x;
    const int lane = t & 31, warp = t >> 5;

    int loc = 0;
    int c = 0;
#pragma unroll
    for (int i = 0; i < 16; i++) {
        const int r = t * 16 + i;
        const int a = (mask[r] != 0u) ? 1 : 0;
        loc |= a << i;
        c += a;
    }
    int pre = c;
#pragma unroll
    for (int d = 1; d < 32; d <<= 1) {
        int v = __shfl_up_sync(0xFFFFFFFFu, pre, d);
        if (lane >= d) pre += v;
    }
    __shared__ int wsum[32];
    if (lane == 31) wsum[warp] = pre;
    __syncthreads();
    if (warp == 0) {
        int v = wsum[lane];
        int p = v;
#pragma unroll
        for (int d = 1; d < 32; d <<= 1) {
            int x = __shfl_up_sync(0xFFFFFFFFu, p, d);
            if (lane >= d) p += x;
        }
        wsum[lane] = p - v;
    }
    __syncthreads();

    int base = wsum[warp] + (pre - c);
#pragma unroll
    for (int i = 0; i < 16; i++) {
        if ((loc >> i) & 1) g_idx[base++] = t * 16 + i;
    }
    if (t == 1023) g_cnt = base;
}

// ---------------------------------------------------------------------------
// mma.sync fp16 GEMM (NT): C[m,n] = sum_k A[m,k] * B[n,k], fp32 accum.
// BM=128, BN=128, BK=64, cp.async 3-stage pipeline (96KB), 8-chunk XOR
// swizzle. 256 threads = 8 warps = 2(M) x 4(N), warp tile 64x32.
// __launch_bounds__(256,2): TWO CTAs per SM so one CTA's barrier/epilogue
// bubbles are covered by the other CTA's MMAs.
// MODE 1: fused QKV (N=3072). Q n-region compacted via g_idx; K/V full.
// MODE 0: O projection, fully compacted, fp16 out.
// ---------------------------------------------------------------------------
#define BM 128
#define BN 128
#define BKC 64
#define NC (DMODEL / BKC)        // 16 k-chunks
#define A_BYTES (128 * 128)      // 16384
#define B_BYTES (128 * 128)      // 16384
#define OFF_A 0
#define OFF_B A_BYTES
#define STAGE_BYTES (A_BYTES + B_BYTES)   // 32768
#define NSTAGE 3
#define GEMM_SMEM (NSTAGE * STAGE_BYTES)  // 98304
#define GTHREADS 256

template <int MODE>
__global__ __launch_bounds__(GTHREADS, 2) void gemm_mma(
    const __half* __restrict__ A, const __half* __restrict__ B,
    __half* __restrict__ O,
    __half* __restrict__ Q, __half* __restrict__ Kk, __half* __restrict__ V)
{
    const int m0   = blockIdx.y * BM;
    const int n0   = blockIdx.x * BN;
    const int widx = (MODE == 1) ? (n0 >> 10) : 0;   // 0=Q,1=K,2=V
    const bool compact = (MODE == 0) || (widx == 0);
    const int cnt = compact ? g_cnt : MTOT;
    if (compact && m0 >= cnt) return;
    const int cmax = cnt - 1;

    extern __shared__ char smem[];
    const uint32_t sb = smem_u32(smem);

    const int tid  = threadIdx.x;
    const int wid  = tid >> 5;
    const int lane = tid & 31;
    const int wm   = wid & 1;        // M offset wm*64
    const int wn   = wid >> 1;       // N offset wn*32

    // Per-thread A source rows (indirected per tile row when compacted)
    int arow[4];
#pragma unroll
    for (int i = 0; i < 4; i++) {
        const int r = (tid + i * GTHREADS) >> 3;
        const int gm = m0 + r;
        const int gc = gm <= cmax ? gm : cmax;
        arow[i] = compact ? g_idx[gc] : gm;
    }

    auto load_stage = [&](int kt, int stg) {
        const uint32_t base = sb + stg * STAGE_BYTES;
#pragma unroll
        for (int i = 0; i < 4; i++) {          // A: 1024 16B-chunks
            const int idx = tid + i * GTHREADS;
            const int r = idx >> 3, c = idx & 7;
            const uint32_t sw = (uint32_t)r * 128 + (uint32_t)((c ^ (r & 7)) << 4);
            CP_ASYNC16(base + OFF_A + sw,
                       A + (size_t)arow[i] * DMODEL + kt * BKC + c * 8);
        }
#pragma unroll
        for (int i = 0; i < 4; i++) {          // B: 1024 16B-chunks
            const int idx = tid + i * GTHREADS;
            const int r = idx >> 3, c = idx & 7;
            const uint32_t sw = (uint32_t)r * 128 + (uint32_t)((c ^ (r & 7)) << 4);
            CP_ASYNC16(base + OFF_B + sw,
                       B + (size_t)(n0 + r) * DMODEL + kt * BKC + c * 8);
        }
        CP_COMMIT();
    };

    float acc[4][4][4];
#pragma unroll
    for (int mi = 0; mi < 4; mi++)
#pragma unroll
        for (int ni = 0; ni < 4; ni++)
#pragma unroll
            for (int q = 0; q < 4; q++) acc[mi][ni][q] = 0.0f;

    const int a_row_in16 = lane & 15;
    const int a_half     = lane >> 4;
    const int b_row_in16 = (lane & 7) + ((lane >> 4) << 3);
    const int b_half     = (lane >> 3) & 1;

    load_stage(0, 0);
    load_stage(1, 1);

    for (int kt = 0; kt < NC; kt++) {
        if (kt < NC - 1) { CP_WAIT(1); } else { CP_WAIT(0); }
        __syncthreads();

        if (kt + 2 < NC) load_stage(kt + 2, (kt + 2) % NSTAGE);

        const uint32_t base = sb + (kt % NSTAGE) * STAGE_BYTES;

#pragma unroll
        for (int kk = 0; kk < 4; kk++) {
            uint32_t ah[4][4];
#pragma unroll
            for (int mi = 0; mi < 4; mi++) {
                const int row = wm * 64 + mi * 16 + a_row_in16;
                const int ch  = kk * 2 + a_half;
                const uint32_t addr = (uint32_t)row * 128 + (uint32_t)((ch ^ (row & 7)) << 4);
                LDSM4(ah[mi][0], ah[mi][1], ah[mi][2], ah[mi][3], base + OFF_A + addr);
            }
#pragma unroll
            for (int p = 0; p < 2; p++) {
                uint32_t bf[2][2];
                const int row = wn * 32 + p * 16 + b_row_in16;
                const int ch  = kk * 2 + b_half;
                const uint32_t addr = (uint32_t)row * 128 + (uint32_t)((ch ^ (row & 7)) << 4);
                LDSM4(bf[0][0], bf[0][1], bf[1][0], bf[1][1], base + OFF_B + addr);
#pragma unroll
                for (int mi = 0; mi < 4; mi++)
#pragma unroll
                    for (int q = 0; q < 2; q++)
                        MMA_F16(acc[mi][2 * p + q], ah[mi], bf[q]);
            }
        }
    }

    const int g  = lane >> 2;
    const int cc = (lane & 3) * 2;
    if (MODE == 1) {
        const int col0 = n0 & 1023;
        __half* Ch = (widx == 0) ? Q : (widx == 1) ? Kk : V;
        const float scale = (widx == 0) ? ATT_SCALE : 1.0f;
#pragma unroll
        for (int mi = 0; mi < 4; mi++) {
            const int rc0 = m0 + wm * 64 + mi * 16 + g;
            const int rc1 = rc0 + 8;
            const int i0 = rc0 <= cmax ? rc0 : cmax;
            const int i1 = rc1 <= cmax ? rc1 : cmax;
            const int rlo = compact ? g_idx[i0] : rc0;
            const int rhi = compact ? g_idx[i1] : rc1;
#pragma unroll
            for (int ni = 0; ni < 4; ni++) {
                const size_t coff = (size_t)col0 + wn * 32 + ni * 8 + cc;
                *(__half2*)(Ch + (size_t)rlo * DMODEL + coff) =
                    __floats2half2_rn(acc[mi][ni][0] * scale, acc[mi][ni][1] * scale);
                *(__half2*)(Ch + (size_t)rhi * DMODEL + coff) =
                    __floats2half2_rn(acc[mi][ni][2] * scale, acc[mi][ni][3] * scale);
            }
        }
    } else {
#pragma unroll
        for (int mi = 0; mi < 4; mi++) {
            const int rc0 = m0 + wm * 64 + mi * 16 + g;
            const int rc1 = rc0 + 8;
            const int i0 = rc0 <= cmax ? rc0 : cmax;
            const int i1 = rc1 <= cmax ? rc1 : cmax;
            const int rlo = g_idx[i0];
            const int rhi = g_idx[i1];
#pragma unroll
            for (int ni = 0; ni < 4; ni++) {
                const size_t coff = (size_t)n0 + wn * 32 + ni * 8 + cc;
                *(__half2*)(O + (size_t)rlo * DMODEL + coff) =
                    __floats2half2_rn(acc[mi][ni][0], acc[mi][ni][1]);
                *(__half2*)(O + (size_t)rhi * DMODEL + coff) =
                    __floats2half2_rn(acc[mi][ni][2], acc[mi][ni][3]);
            }
        }
    }
}

// ---------------------------------------------------------------------------
// Attention on mma.sync: one CTA per (b,h), 128 threads (4 warps).
// Q pre-scaled by ATT_SCALE. Inactive Q rows are zero -> uniform softmax ->
// finite output, discarded by the residual gate.
// ---------------------------------------------------------------------------
#define ATT_SMEM (3 * 8192)

__global__ __launch_bounds__(128) void attn_mma(const __half* __restrict__ Qf,
                                                const __half* __restrict__ Kf,
                                                const __half* __restrict__ Vf,
                                                __half* __restrict__ AOf) {
    const int h = blockIdx.x;
    const int b = blockIdx.y;
    const int t = threadIdx.x;
    const int w = t >> 5;
    const int lane = t & 31;

    __shared__ __align__(128) char sm[ATT_SMEM];
    const uint32_t sQ = smem_u32(sm);
    const uint32_t sK = sQ + 8192;
    const uint32_t sV = sQ + 16384;

    const size_t gbase = (size_t)b * SEQLEN * DMODEL + h * DHEAD;

    for (int idx = t; idx < 512; idx += 128) {
        const int r = idx >> 3, c = idx & 7;
        const uint32_t sw = (uint32_t)r * 128 + (uint32_t)((c ^ (r & 7)) << 4);
        const size_t go = gbase + (size_t)r * DMODEL + c * 8;
        CP_ASYNC16(sQ + sw, Qf + go);
        CP_ASYNC16(sK + sw, Kf + go);
        CP_ASYNC16(sV + sw, Vf + go);
    }
    CP_COMMIT();
    CP_WAIT(0);
    __syncthreads();

    float s[8][4];
#pragma unroll
    for (int j = 0; j < 8; j++)
#pragma unroll
        for (int q = 0; q < 4; q++) s[j][q] = 0.0f;

    const int a_row = w * 16 + (lane & 15);
    const int a_half = lane >> 4;
    const int b_row_in16 = (lane & 7) + ((lane >> 4) << 3);
    const int b_half = (lane >> 3) & 1;

#pragma unroll
    for (int g = 0; g < 4; g++) {
        uint32_t aq[4];
        {
            const int ch = 2 * g + a_half;
            const uint32_t addr = (uint32_t)a_row * 128 + (uint32_t)((ch ^ (a_row & 7)) << 4);
            LDSM4(aq[0], aq[1], aq[2], aq[3], sQ + addr);
        }
#pragma unroll
        for (int p = 0; p < 4; p++) {
            uint32_t bk[2][2];
            const int row = p * 16 + b_row_in16;
            const int ch  = 2 * g + b_half;
            const uint32_t addr = (uint32_t)row * 128 + (uint32_t)((ch ^ (row & 7)) << 4);
            LDSM4(bk[0][0], bk[0][1], bk[1][0], bk[1][1], sK + addr);
            MMA_F16(s[2 * p],     aq, bk[0]);
            MMA_F16(s[2 * p + 1], aq, bk[1]);
        }
    }

    float mx0 = -1e30f, mx1 = -1e30f;
#pragma unroll
    for (int j = 0; j < 8; j++) {
        mx0 = fmaxf(mx0, fmaxf(s[j][0], s[j][1]));
        mx1 = fmaxf(mx1, fmaxf(s[j][2], s[j][3]));
    }
#pragma unroll
    for (int d = 1; d <= 2; d <<= 1) {
        mx0 = fmaxf(mx0, __shfl_xor_sync(0xFFFFFFFFu, mx0, d));
        mx1 = fmaxf(mx1, __shfl_xor_sync(0xFFFFFFFFu, mx1, d));
    }
    float sm0 = 0.0f, sm1 = 0.0f;
#pragma unroll
    for (int j = 0; j < 8; j++) {
        s[j][0] = __expf(s[j][0] - mx0); sm0 += s[j][0];
        s[j][1] = __expf(s[j][1] - mx0); sm0 += s[j][1];
        s[j][2] = __expf(s[j][2] - mx1); sm1 += s[j][2];
        s[j][3] = __expf(s[j][3] - mx1); sm1 += s[j][3];
    }
#pragma unroll
    for (int d = 1; d <= 2; d <<= 1) {
        sm0 += __shfl_xor_sync(0xFFFFFFFFu, sm0, d);
        sm1 += __shfl_xor_sync(0xFFFFFFFFu, sm1, d);
    }
    const float inv0 = 1.0f / sm0;
    const float inv1 = 1.0f / sm1;

    uint32_t ph[8], pl[8];
#pragma unroll
    for (int j = 0; j < 8; j++) {
        ph[j] = h2u(__floats2half2_rn(s[j][0] * inv0, s[j][1] * inv0));
        pl[j] = h2u(__floats2half2_rn(s[j][2] * inv1, s[j][3] * inv1));
    }

    float o[8][4];
#pragma unroll
    for (int j = 0; j < 8; j++)
#pragma unroll
        for (int q = 0; q < 4; q++) o[j][q] = 0.0f;

    const int v_row_in16 = (lane & 7) + 8 * ((lane >> 3) & 1);
    const int v_col8     = 8 * (lane >> 4);

#pragma unroll
    for (int g = 0; g < 4; g++) {
        uint32_t ap[4] = { ph[2 * g], pl[2 * g], ph[2 * g + 1], pl[2 * g + 1] };
#pragma unroll
        for (int q = 0; q < 4; q++) {
            uint32_t bv[2][2];
            const int row = 16 * g + v_row_in16;
            const int col = 16 * q + v_col8;
            const uint32_t addr = (uint32_t)row * 128 +
                                  (uint32_t)(((col >> 3) ^ (row & 7)) << 4);
            LDSM4T(bv[0][0], bv[0][1], bv[1][0], bv[1][1], sV + addr);
            MMA_F16(o[2 * q],     ap, bv[0]);
            MMA_F16(o[2 * q + 1], ap, bv[1]);
        }
    }

    const int r0 = lane >> 2;
    const int cc = (lane & 3) * 2;
#pragma unroll
    for (int j = 0; j < 8; j++) {
        __half* p = AOf + gbase + (size_t)(w * 16 + r0) * DMODEL + j * 8 + cc;
        *(__half2*)p = __floats2half2_rn(o[j][0], o[j][1]);
        *(__half2*)(p + 8 * DMODEL) = __floats2half2_rn(o[j][2], o[j][3]);
    }
}

// ---------------------------------------------------------------------------
// Gated residual + LayerNorm (proj fp16; inactive proj rows stay zero)
// ---------------------------------------------------------------------------
__global__ __launch_bounds__(256) void resid_ln(const float* __restrict__ hidden,
                                                const __half* __restrict__ proj,
                                                const unsigned* __restrict__ mask,
                                                const float* __restrict__ gamma,
                                                const float* __restrict__ beta,
                                                float* __restrict__ out) {
    const int r = blockIdx.x;
    const int t = threadIdx.x;
    const size_t base = (size_t)r * DMODEL + t * 4;

    const float act = (mask[r] != 0u) ? 1.0f : 0.0f;
    const float4 hv = *(const float4*)(hidden + base);
    const uint2 o2 = *(const uint2*)(proj + base);
    const __half2 oh0 = *reinterpret_cast<const __half2*>(&o2.x);
    const __half2 oh1 = *reinterpret_cast<const __half2*>(&o2.y);
    const float2 of0 = __half22float2(oh0);
    const float2 of1 = __half22float2(oh1);

    float4 f;
    f.x = hv.x + act * of0.x;
    f.y = hv.y + act * of0.y;
    f.z = hv.z + act * of1.x;
    f.w = hv.w + act * of1.y;

    float s  = f.x + f.y + f.z + f.w;
    float s2 = f.x * f.x + f.y * f.y + f.z * f.z + f.w * f.w;

#pragma unroll
    for (int d = 16; d; d >>= 1) {
        s  += __shfl_xor_sync(0xFFFFFFFFu, s,  d);
        s2 += __shfl_xor_sync(0xFFFFFFFFu, s2, d);
    }

    __shared__ float ws[8], ws2[8];
    const int warp = t >> 5, lane = t & 31;
    if (lane == 0) { ws[warp] = s; ws2[warp] = s2; }
    __syncthreads();

    float ts = 0.0f, ts2 = 0.0f;
#pragma unroll
    for (int i = 0; i < 8; i++) { ts += ws[i]; ts2 += ws2[i]; }

    const float mu  = ts * (1.0f / DMODEL);
    const float var = ts2 * (1.0f / DMODEL) - mu * mu;
    const float rs  = rsqrtf(var + LN_EPS);

    const float4 gv = *(const float4*)(gamma + t * 4);
    const float4 bv = *(const float4*)(beta  + t * 4);

    float4 r4;
    r4.x = (f.x - mu) * rs * gv.x + bv.x;
    r4.y = (f.y - mu) * rs * gv.y + bv.y;
    r4.z = (f.z - mu) * rs * gv.z + bv.z;
    r4.w = (f.w - mu) * rs * gv.w + bv.w;
    *(float4*)(out + base) = r4;
}

// ---------------------------------------------------------------------------
// Launch
// ---------------------------------------------------------------------------
extern "C" void kernel_launch(void* const* d_in, const int* in_sizes, int n_in,
                              void* d_out, int out_size) {
    const float*    hidden = (const float*)d_in[0];
    const unsigned* mask   = (const unsigned*)d_in[1];
    const float*    W[4]   = {(const float*)d_in[2], (const float*)d_in[3],
                              (const float*)d_in[4], (const float*)d_in[5]};
    const float*    gamma  = (const float*)d_in[6];
    const float*    beta   = (const float*)d_in[7];
    float*          out    = (float*)d_out;

    __half *Qf, *Kf, *Vf, *Of, *hf, *aof, *wf;
    cudaGetSymbolAddress((void**)&Qf,  g_Qf);
    cudaGetSymbolAddress((void**)&Kf,  g_Kf);
    cudaGetSymbolAddress((void**)&Vf,  g_Vf);
    cudaGetSymbolAddress((void**)&Of,  g_Of);
    cudaGetSymbolAddress((void**)&hf,  g_hf);
    cudaGetSymbolAddress((void**)&aof, g_aof);
    cudaGetSymbolAddress((void**)&wf,  g_wf);

    cudaFuncSetAttribute(gemm_mma<0>, cudaFuncAttributeMaxDynamicSharedMemorySize, GEMM_SMEM);
    cudaFuncSetAttribute(gemm_mma<1>, cudaFuncAttributeMaxDynamicSharedMemorySize, GEMM_SMEM);

    // Conversions + active-row compaction
    const int n4h = MTOT * DMODEL / 4;
    cvt_f16<<<n4h / 256, 256>>>((const float4*)hidden, (uint2*)hf, n4h);
    cvt_w4<<<4 * (DMODEL * DMODEL / 4) / 256, 256>>>(
        (const float4*)W[0], (const float4*)W[1],
        (const float4*)W[2], (const float4*)W[3], (uint2*)wf);
    build_idx<<<1, 1024>>>(mask);

    // Fused QKV projection (N = 3072; Q region compacted)
    gemm_mma<1><<<dim3(3 * DMODEL / BN, MTOT / BM), GTHREADS, GEMM_SMEM>>>(
        hf, wf, nullptr, Qf, Kf, Vf);

    attn_mma<<<dim3(NHEAD, BATCH), 128>>>(Qf, Kf, Vf, aof);

    // O projection (compacted) -> fp16
    gemm_mma<0><<<dim3(DMODEL / BN, MTOT / BM), GTHREADS, GEMM_SMEM>>>(
        aof, wf + 3 * (size_t)DMODEL * DMODEL, Of, nullptr, nullptr, nullptr);

    resid_ln<<<MTOT, 256>>>(hidden, Of, mask, gamma, beta, out);
}

// round 15
// speedup vs baseline: 9.6281x; 1.0229x over previous
#include <cuda_runtime.h>
#include <cuda_fp16.h>
#include <cstdint>

// ---------------------------------------------------------------------------
// Problem constants
// ---------------------------------------------------------------------------
#define MTOT   16384      // B*K
#define DMODEL 1024
#define NHEAD  16
#define DHEAD  64
#define BATCH  256
#define SEQLEN 64
#define ATT_SCALE 0.125f
#define LN_EPS 1e-5f

// ---------------------------------------------------------------------------
// Scratch (device globals: the allowed no-alloc workaround)
// ---------------------------------------------------------------------------
__device__ __half g_Qf [MTOT * DMODEL];          // Q (pre-scaled) fp16
__device__ __half g_Kf [MTOT * DMODEL];          // K fp16
__device__ __half g_Vf [MTOT * DMODEL];          // V fp16
__device__ __half g_Of [MTOT * DMODEL];          // O projection fp16
__device__ __half g_hf [MTOT * DMODEL];          // hidden fp16
__device__ __half g_aof[MTOT * DMODEL];          // attn out fp16
__device__ __half g_wf [4][DMODEL * DMODEL];     // Wq,Wk,Wv,Wo fp16 (contiguous)
__device__ int    g_cnt;                         // # active rows
__device__ int    g_idx[MTOT];                   // sorted active-row indices

// ---------------------------------------------------------------------------
// Baseline-PTX helpers (harness compiles via compute_103: no tcgen05)
// ---------------------------------------------------------------------------
__device__ __forceinline__ uint32_t smem_u32(const void* p) {
    uint32_t a;
    asm("{ .reg .u64 t; cvta.to.shared.u64 t, %1; cvt.u32.u64 %0, t; }"
        : "=r"(a) : "l"(p));
    return a;
}

#define CP_ASYNC16(dst, src) \
    asm volatile("cp.async.cg.shared.global [%0], [%1], 16;" :: "r"(dst), "l"(src))
#define CP_COMMIT() asm volatile("cp.async.commit_group;" ::: "memory")
#define CP_WAIT(n)  asm volatile("cp.async.wait_group %0;" :: "n"(n) : "memory")

#define LDSM4(r0, r1, r2, r3, addr) \
    asm volatile("ldmatrix.sync.aligned.m8n8.x4.shared.b16 {%0,%1,%2,%3}, [%4];" \
                 : "=r"(r0), "=r"(r1), "=r"(r2), "=r"(r3) : "r"(addr))

#define LDSM4T(r0, r1, r2, r3, addr) \
    asm volatile("ldmatrix.sync.aligned.m8n8.x4.trans.shared.b16 {%0,%1,%2,%3}, [%4];" \
                 : "=r"(r0), "=r"(r1), "=r"(r2), "=r"(r3) : "r"(addr))

#define MMA_F16(d, a, b) \
    asm volatile("mma.sync.aligned.m16n8k16.row.col.f32.f16.f16.f32 " \
                 "{%0,%1,%2,%3},{%4,%5,%6,%7},{%8,%9},{%0,%1,%2,%3};" \
                 : "+f"((d)[0]), "+f"((d)[1]), "+f"((d)[2]), "+f"((d)[3]) \
                 : "r"((a)[0]), "r"((a)[1]), "r"((a)[2]), "r"((a)[3]), \
                   "r"((b)[0]), "r"((b)[1]))

__device__ __forceinline__ uint32_t h2u(__half2 h) {
    return *reinterpret_cast<uint32_t*>(&h);
}

// ---------------------------------------------------------------------------
// fp32 -> fp16 conversions
// ---------------------------------------------------------------------------
__global__ __launch_bounds__(256) void cvt_f16(const float4* __restrict__ in,
                                               uint2* __restrict__ out16, int n4) {
    int i = blockIdx.x * 256 + threadIdx.x;
    if (i >= n4) return;
    float4 v = in[i];
    __half2 p0 = __floats2half2_rn(v.x, v.y);
    __half2 p1 = __floats2half2_rn(v.z, v.w);
    out16[i] = make_uint2(h2u(p0), h2u(p1));
}

__global__ __launch_bounds__(256) void cvt_w4(const float4* __restrict__ w0,
                                              const float4* __restrict__ w1,
                                              const float4* __restrict__ w2,
                                              const float4* __restrict__ w3,
                                              uint2* __restrict__ out16) {
    const int i = blockIdx.x * 256 + threadIdx.x;   // 0 .. 4*262144-1
    const int w = i >> 18;
    const int j = i & 262143;
    const float4* src = (w == 0) ? w0 : (w == 1) ? w1 : (w == 2) ? w2 : w3;
    float4 v = src[j];
    __half2 p0 = __floats2half2_rn(v.x, v.y);
    __half2 p1 = __floats2half2_rn(v.z, v.w);
    out16[i] = make_uint2(h2u(p0), h2u(p1));
}

// ---------------------------------------------------------------------------
// Deterministic sorted compaction of active rows (single CTA, 1024 threads).
// ---------------------------------------------------------------------------
__global__ __launch_bounds__(1024) void build_idx(const unsigned* __restrict__ mask) {
    const int t = threadIdx.x;
    const int lane = t & 31, warp = t >> 5;

    int loc = 0;
    int c = 0;
#pragma unroll
    for (int i = 0; i < 16; i++) {
        const int r = t * 16 + i;
        const int a = (mask[r] != 0u) ? 1 : 0;
        loc |= a << i;
        c += a;
    }
    int pre = c;
#pragma unroll
    for (int d = 1; d < 32; d <<= 1) {
        int v = __shfl_up_sync(0xFFFFFFFFu, pre, d);
        if (lane >= d) pre += v;
    }
    __shared__ int wsum[32];
    if (lane == 31) wsum[warp] = pre;
    __syncthreads();
    if (warp == 0) {
        int v = wsum[lane];
        int p = v;
#pragma unroll
        for (int d = 1; d < 32; d <<= 1) {
            int x = __shfl_up_sync(0xFFFFFFFFu, p, d);
            if (lane >= d) p += x;
        }
        wsum[lane] = p - v;
    }
    __syncthreads();

    int base = wsum[warp] + (pre - c);
#pragma unroll
    for (int i = 0; i < 16; i++) {
        if ((loc >> i) & 1) g_idx[base++] = t * 16 + i;
    }
    if (t == 1023) g_cnt = base;
}

// ---------------------------------------------------------------------------
// mma.sync fp16 GEMM (NT): C[m,n] = sum_k A[m,k] * B[n,k], fp32 accum.
// BM=128, BN=128, BK=64, cp.async 3-stage pipeline (96KB), 8-chunk XOR
// swizzle. 128 threads = 4 warps = 2(M) x 2(N), warp tile 64x64:
// per kk only 8 LDSM.x4 feed 32 MMAs (minimal smem operand traffic).
// __launch_bounds__(128,2): TWO CTAs per SM to cover barrier/epilogue bubbles.
// MODE 1: fused QKV (N=3072). Q n-region compacted via g_idx; K/V full.
// MODE 0: O projection, fully compacted, fp16 out.
// ---------------------------------------------------------------------------
#define BM 128
#define BN 128
#define BKC 64
#define NC (DMODEL / BKC)        // 16 k-chunks
#define A_BYTES (128 * 128)      // 16384
#define B_BYTES (128 * 128)      // 16384
#define OFF_A 0
#define OFF_B A_BYTES
#define STAGE_BYTES (A_BYTES + B_BYTES)   // 32768
#define NSTAGE 3
#define GEMM_SMEM (NSTAGE * STAGE_BYTES)  // 98304
#define GTHREADS 128

template <int MODE>
__global__ __launch_bounds__(GTHREADS, 2) void gemm_mma(
    const __half* __restrict__ A, const __half* __restrict__ B,
    __half* __restrict__ O,
    __half* __restrict__ Q, __half* __restrict__ Kk, __half* __restrict__ V)
{
    const int m0   = blockIdx.y * BM;
    const int n0   = blockIdx.x * BN;
    const int widx = (MODE == 1) ? (n0 >> 10) : 0;   // 0=Q,1=K,2=V
    const bool compact = (MODE == 0) || (widx == 0);
    const int cnt = compact ? g_cnt : MTOT;
    if (compact && m0 >= cnt) return;
    const int cmax = cnt - 1;

    extern __shared__ char smem[];
    const uint32_t sb = smem_u32(smem);

    const int tid  = threadIdx.x;
    const int wid  = tid >> 5;
    const int lane = tid & 31;
    const int wm   = wid & 1;        // M offset wm*64
    const int wn   = wid >> 1;       // N offset wn*64

    // Per-thread A source rows (indirected per tile row when compacted)
    int arow[8];
#pragma unroll
    for (int i = 0; i < 8; i++) {
        const int r = (tid + i * GTHREADS) >> 3;
        const int gm = m0 + r;
        const int gc = gm <= cmax ? gm : cmax;
        arow[i] = compact ? g_idx[gc] : gm;
    }

    auto load_stage = [&](int kt, int stg) {
        const uint32_t base = sb + stg * STAGE_BYTES;
#pragma unroll
        for (int i = 0; i < 8; i++) {          // A: 1024 16B-chunks
            const int idx = tid + i * GTHREADS;
            const int r = idx >> 3, c = idx & 7;
            const uint32_t sw = (uint32_t)r * 128 + (uint32_t)((c ^ (r & 7)) << 4);
            CP_ASYNC16(base + OFF_A + sw,
                       A + (size_t)arow[i] * DMODEL + kt * BKC + c * 8);
        }
#pragma unroll
        for (int i = 0; i < 8; i++) {          // B: 1024 16B-chunks
            const int idx = tid + i * GTHREADS;
            const int r = idx >> 3, c = idx & 7;
            const uint32_t sw = (uint32_t)r * 128 + (uint32_t)((c ^ (r & 7)) << 4);
            CP_ASYNC16(base + OFF_B + sw,
                       B + (size_t)(n0 + r) * DMODEL + kt * BKC + c * 8);
        }
        CP_COMMIT();
    };

    float acc[4][8][4];
#pragma unroll
    for (int mi = 0; mi < 4; mi++)
#pragma unroll
        for (int ni = 0; ni < 8; ni++)
#pragma unroll
            for (int q = 0; q < 4; q++) acc[mi][ni][q] = 0.0f;

    const int a_row_in16 = lane & 15;
    const int a_half     = lane >> 4;
    const int b_row_in16 = (lane & 7) + ((lane >> 4) << 3);
    const int b_half     = (lane >> 3) & 1;

    load_stage(0, 0);
    load_stage(1, 1);

    for (int kt = 0; kt < NC; kt++) {
        if (kt < NC - 1) { CP_WAIT(1); } else { CP_WAIT(0); }
        __syncthreads();

        if (kt + 2 < NC) load_stage(kt + 2, (kt + 2) % NSTAGE);

        const uint32_t base = sb + (kt % NSTAGE) * STAGE_BYTES;

#pragma unroll
        for (int kk = 0; kk < 4; kk++) {
            uint32_t ah[4][4];
#pragma unroll
            for (int mi = 0; mi < 4; mi++) {
                const int row = wm * 64 + mi * 16 + a_row_in16;
                const int ch  = kk * 2 + a_half;
                const uint32_t addr = (uint32_t)row * 128 + (uint32_t)((ch ^ (row & 7)) << 4);
                LDSM4(ah[mi][0], ah[mi][1], ah[mi][2], ah[mi][3], base + OFF_A + addr);
            }
#pragma unroll
            for (int p = 0; p < 4; p++) {
                uint32_t bf[2][2];
                const int row = wn * 64 + p * 16 + b_row_in16;
                const int ch  = kk * 2 + b_half;
                const uint32_t addr = (uint32_t)row * 128 + (uint32_t)((ch ^ (row & 7)) << 4);
                LDSM4(bf[0][0], bf[0][1], bf[1][0], bf[1][1], base + OFF_B + addr);
#pragma unroll
                for (int mi = 0; mi < 4; mi++)
#pragma unroll
                    for (int q = 0; q < 2; q++)
                        MMA_F16(acc[mi][2 * p + q], ah[mi], bf[q]);
            }
        }
    }

    const int g  = lane >> 2;
    const int cc = (lane & 3) * 2;
    if (MODE == 1) {
        const int col0 = n0 & 1023;
        __half* Ch = (widx == 0) ? Q : (widx == 1) ? Kk : V;
        const float scale = (widx == 0) ? ATT_SCALE : 1.0f;
#pragma unroll
        for (int mi = 0; mi < 4; mi++) {
            const int rc0 = m0 + wm * 64 + mi * 16 + g;
            const int rc1 = rc0 + 8;
            const int i0 = rc0 <= cmax ? rc0 : cmax;
            const int i1 = rc1 <= cmax ? rc1 : cmax;
            const int rlo = compact ? g_idx[i0] : rc0;
            const int rhi = compact ? g_idx[i1] : rc1;
#pragma unroll
            for (int ni = 0; ni < 8; ni++) {
                const size_t coff = (size_t)col0 + wn * 64 + ni * 8 + cc;
                *(__half2*)(Ch + (size_t)rlo * DMODEL + coff) =
                    __floats2half2_rn(acc[mi][ni][0] * scale, acc[mi][ni][1] * scale);
                *(__half2*)(Ch + (size_t)rhi * DMODEL + coff) =
                    __floats2half2_rn(acc[mi][ni][2] * scale, acc[mi][ni][3] * scale);
            }
        }
    } else {
#pragma unroll
        for (int mi = 0; mi < 4; mi++) {
            const int rc0 = m0 + wm * 64 + mi * 16 + g;
            const int rc1 = rc0 + 8;
            const int i0 = rc0 <= cmax ? rc0 : cmax;
            const int i1 = rc1 <= cmax ? rc1 : cmax;
            const int rlo = g_idx[i0];
            const int rhi = g_idx[i1];
#pragma unroll
            for (int ni = 0; ni < 8; ni++) {
                const size_t coff = (size_t)n0 + wn * 64 + ni * 8 + cc;
                *(__half2*)(O + (size_t)rlo * DMODEL + coff) =
                    __floats2half2_rn(acc[mi][ni][0], acc[mi][ni][1]);
                *(__half2*)(O + (size_t)rhi * DMODEL + coff) =
                    __floats2half2_rn(acc[mi][ni][2], acc[mi][ni][3]);
            }
        }
    }
}

// ---------------------------------------------------------------------------
// Attention on mma.sync: one CTA per (b,h), 128 threads (4 warps).
// Q pre-scaled by ATT_SCALE. Inactive Q rows are zero -> uniform softmax ->
// finite output, discarded by the residual gate.
// ---------------------------------------------------------------------------
#define ATT_SMEM (3 * 8192)

__global__ __launch_bounds__(128) void attn_mma(const __half* __restrict__ Qf,
                                                const __half* __restrict__ Kf,
                                                const __half* __restrict__ Vf,
                                                __half* __restrict__ AOf) {
    const int h = blockIdx.x;
    const int b = blockIdx.y;
    const int t = threadIdx.x;
    const int w = t >> 5;
    const int lane = t & 31;

    __shared__ __align__(128) char sm[ATT_SMEM];
    const uint32_t sQ = smem_u32(sm);
    const uint32_t sK = sQ + 8192;
    const uint32_t sV = sQ + 16384;

    const size_t gbase = (size_t)b * SEQLEN * DMODEL + h * DHEAD;

    for (int idx = t; idx < 512; idx += 128) {
        const int r = idx >> 3, c = idx & 7;
        const uint32_t sw = (uint32_t)r * 128 + (uint32_t)((c ^ (r & 7)) << 4);
        const size_t go = gbase + (size_t)r * DMODEL + c * 8;
        CP_ASYNC16(sQ + sw, Qf + go);
        CP_ASYNC16(sK + sw, Kf + go);
        CP_ASYNC16(sV + sw, Vf + go);
    }
    CP_COMMIT();
    CP_WAIT(0);
    __syncthreads();

    float s[8][4];
#pragma unroll
    for (int j = 0; j < 8; j++)
#pragma unroll
        for (int q = 0; q < 4; q++) s[j][q] = 0.0f;

    const int a_row = w * 16 + (lane & 15);
    const int a_half = lane >> 4;
    const int b_row_in16 = (lane & 7) + ((lane >> 4) << 3);
    const int b_half = (lane >> 3) & 1;

#pragma unroll
    for (int g = 0; g < 4; g++) {
        uint32_t aq[4];
        {
            const int ch = 2 * g + a_half;
            const uint32_t addr = (uint32_t)a_row * 128 + (uint32_t)((ch ^ (a_row & 7)) << 4);
            LDSM4(aq[0], aq[1], aq[2], aq[3], sQ + addr);
        }
#pragma unroll
        for (int p = 0; p < 4; p++) {
            uint32_t bk[2][2];
            const int row = p * 16 + b_row_in16;
            const int ch  = 2 * g + b_half;
            const uint32_t addr = (uint32_t)row * 128 + (uint32_t)((ch ^ (row & 7)) << 4);
            LDSM4(bk[0][0], bk[0][1], bk[1][0], bk[1][1], sK + addr);
            MMA_F16(s[2 * p],     aq, bk[0]);
            MMA_F16(s[2 * p + 1], aq, bk[1]);
        }
    }

    float mx0 = -1e30f, mx1 = -1e30f;
#pragma unroll
    for (int j = 0; j < 8; j++) {
        mx0 = fmaxf(mx0, fmaxf(s[j][0], s[j][1]));
        mx1 = fmaxf(mx1, fmaxf(s[j][2], s[j][3]));
    }
#pragma unroll
    for (int d = 1; d <= 2; d <<= 1) {
        mx0 = fmaxf(mx0, __shfl_xor_sync(0xFFFFFFFFu, mx0, d));
        mx1 = fmaxf(mx1, __shfl_xor_sync(0xFFFFFFFFu, mx1, d));
    }
    float sm0 = 0.0f, sm1 = 0.0f;
#pragma unroll
    for (int j = 0; j < 8; j++) {
        s[j][0] = __expf(s[j][0] - mx0); sm0 += s[j][0];
        s[j][1] = __expf(s[j][1] - mx0); sm0 += s[j][1];
        s[j][2] = __expf(s[j][2] - mx1); sm1 += s[j][2];
        s[j][3] = __expf(s[j][3] - mx1); sm1 += s[j][3];
    }
#pragma unroll
    for (int d = 1; d <= 2; d <<= 1) {
        sm0 += __shfl_xor_sync(0xFFFFFFFFu, sm0, d);
        sm1 += __shfl_xor_sync(0xFFFFFFFFu, sm1, d);
    }
    const float inv0 = 1.0f / sm0;
    const float inv1 = 1.0f / sm1;

    uint32_t ph[8], pl[8];
#pragma unroll
    for (int j = 0; j < 8; j++) {
        ph[j] = h2u(__floats2half2_rn(s[j][0] * inv0, s[j][1] * inv0));
        pl[j] = h2u(__floats2half2_rn(s[j][2] * inv1, s[j][3] * inv1));
    }

    float o[8][4];
#pragma unroll
    for (int j = 0; j < 8; j++)
#pragma unroll
        for (int q = 0; q < 4; q++) o[j][q] = 0.0f;

    const int v_row_in16 = (lane & 7) + 8 * ((lane >> 3) & 1);
    const int v_col8     = 8 * (lane >> 4);

#pragma unroll
    for (int g = 0; g < 4; g++) {
        uint32_t ap[4] = { ph[2 * g], pl[2 * g], ph[2 * g + 1], pl[2 * g + 1] };
#pragma unroll
        for (int q = 0; q < 4; q++) {
            uint32_t bv[2][2];
            const int row = 16 * g + v_row_in16;
            const int col = 16 * q + v_col8;
            const uint32_t addr = (uint32_t)row * 128 +
                                  (uint32_t)(((col >> 3) ^ (row & 7)) << 4);
            LDSM4T(bv[0][0], bv[0][1], bv[1][0], bv[1][1], sV + addr);
            MMA_F16(o[2 * q],     ap, bv[0]);
            MMA_F16(o[2 * q + 1], ap, bv[1]);
        }
    }

    const int r0 = lane >> 2;
    const int cc = (lane & 3) * 2;
#pragma unroll
    for (int j = 0; j < 8; j++) {
        __half* p = AOf + gbase + (size_t)(w * 16 + r0) * DMODEL + j * 8 + cc;
        *(__half2*)p = __floats2half2_rn(o[j][0], o[j][1]);
        *(__half2*)(p + 8 * DMODEL) = __floats2half2_rn(o[j][2], o[j][3]);
    }
}

// ---------------------------------------------------------------------------
// Gated residual + LayerNorm (proj fp16; inactive proj rows stay zero)
// ---------------------------------------------------------------------------
__global__ __launch_bounds__(256) void resid_ln(const float* __restrict__ hidden,
                                                const __half* __restrict__ proj,
                                                const unsigned* __restrict__ mask,
                                                const float* __restrict__ gamma,
                                                const float* __restrict__ beta,
                                                float* __restrict__ out) {
    const int r = blockIdx.x;
    const int t = threadIdx.x;
    const size_t base = (size_t)r * DMODEL + t * 4;

    const float act = (mask[r] != 0u) ? 1.0f : 0.0f;
    const float4 hv = *(const float4*)(hidden + base);
    const uint2 o2 = *(const uint2*)(proj + base);
    const __half2 oh0 = *reinterpret_cast<const __half2*>(&o2.x);
    const __half2 oh1 = *reinterpret_cast<const __half2*>(&o2.y);
    const float2 of0 = __half22float2(oh0);
    const float2 of1 = __half22float2(oh1);

    float4 f;
    f.x = hv.x + act * of0.x;
    f.y = hv.y + act * of0.y;
    f.z = hv.z + act * of1.x;
    f.w = hv.w + act * of1.y;

    float s  = f.x + f.y + f.z + f.w;
    float s2 = f.x * f.x + f.y * f.y + f.z * f.z + f.w * f.w;

#pragma unroll
    for (int d = 16; d; d >>= 1) {
        s  += __shfl_xor_sync(0xFFFFFFFFu, s,  d);
        s2 += __shfl_xor_sync(0xFFFFFFFFu, s2, d);
    }

    __shared__ float ws[8], ws2[8];
    const int warp = t >> 5, lane = t & 31;
    if (lane == 0) { ws[warp] = s; ws2[warp] = s2; }
    __syncthreads();

    float ts = 0.0f, ts2 = 0.0f;
#pragma unroll
    for (int i = 0; i < 8; i++) { ts += ws[i]; ts2 += ws2[i]; }

    const float mu  = ts * (1.0f / DMODEL);
    const float var = ts2 * (1.0f / DMODEL) - mu * mu;
    const float rs  = rsqrtf(var + LN_EPS);

    const float4 gv = *(const float4*)(gamma + t * 4);
    const float4 bv = *(const float4*)(beta  + t * 4);

    float4 r4;
    r4.x = (f.x - mu) * rs * gv.x + bv.x;
    r4.y = (f.y - mu) * rs * gv.y + bv.y;
    r4.z = (f.z - mu) * rs * gv.z + bv.z;
    r4.w = (f.w - mu) * rs * gv.w + bv.w;
    *(float4*)(out + base) = r4;
}

// ---------------------------------------------------------------------------
// Launch
// ---------------------------------------------------------------------------
extern "C" void kernel_launch(void* const* d_in, const int* in_sizes, int n_in,
                              void* d_out, int out_size) {
    const float*    hidden = (const float*)d_in[0];
    const unsigned* mask   = (const unsigned*)d_in[1];
    const float*    W[4]   = {(const float*)d_in[2], (const float*)d_in[3],
                              (const float*)d_in[4], (const float*)d_in[5]};
    const float*    gamma  = (const float*)d_in[6];
    const float*    beta   = (const float*)d_in[7];
    float*          out    = (float*)d_out;

    __half *Qf, *Kf, *Vf, *Of, *hf, *aof, *wf;
    cudaGetSymbolAddress((void**)&Qf,  g_Qf);
    cudaGetSymbolAddress((void**)&Kf,  g_Kf);
    cudaGetSymbolAddress((void**)&Vf,  g_Vf);
    cudaGetSymbolAddress((void**)&Of,  g_Of);
    cudaGetSymbolAddress((void**)&hf,  g_hf);
    cudaGetSymbolAddress((void**)&aof, g_aof);
    cudaGetSymbolAddress((void**)&wf,  g_wf);

    cudaFuncSetAttribute(gemm_mma<0>, cudaFuncAttributeMaxDynamicSharedMemorySize, GEMM_SMEM);
    cudaFuncSetAttribute(gemm_mma<1>, cudaFuncAttributeMaxDynamicSharedMemorySize, GEMM_SMEM);

    // Conversions + active-row compaction
    const int n4h = MTOT * DMODEL / 4;
    cvt_f16<<<n4h / 256, 256>>>((const float4*)hidden, (uint2*)hf, n4h);
    cvt_w4<<<4 * (DMODEL * DMODEL / 4) / 256, 256>>>(
        (const float4*)W[0], (const float4*)W[1],
        (const float4*)W[2], (const float4*)W[3], (uint2*)wf);
    build_idx<<<1, 1024>>>(mask);

    // Fused QKV projection (N = 3072; Q region compacted)
    gemm_mma<1><<<dim3(3 * DMODEL / BN, MTOT / BM), GTHREADS, GEMM_SMEM>>>(
        hf, wf, nullptr, Qf, Kf, Vf);

    attn_mma<<<dim3(NHEAD, BATCH), 128>>>(Qf, Kf, Vf, aof);

    // O projection (compacted) -> fp16
    gemm_mma<0><<<dim3(DMODEL / BN, MTOT / BM), GTHREADS, GEMM_SMEM>>>(
        aof, wf + 3 * (size_t)DMODEL * DMODEL, Of, nullptr, nullptr, nullptr);

    resid_ln<<<MTOT, 256>>>(hidden, Of, mask, gamma, beta, out);
}